// round 1
// baseline (speedup 1.0000x reference)
#include <cuda_runtime.h>
#include <math.h>

// ---------------- problem constants ----------------
#define TOK    8192          // 4 * 2048 tokens
#define DMODEL 1024
#define NHEAD  16
#define HDIM   64
#define FDIM   4096
#define SEQ    2048
#define BATCH  4
#define EPS    1e-5f

// ---------------- scratch (device globals; no runtime alloc allowed) ------
__device__ float g_h   [(size_t)TOK * DMODEL];
__device__ float g_q   [(size_t)TOK * DMODEL];
__device__ float g_k   [(size_t)TOK * DMODEL];
__device__ float g_v   [(size_t)TOK * DMODEL];
__device__ float g_attn[(size_t)TOK * DMODEL];
__device__ float g_x2  [(size_t)TOK * DMODEL];
__device__ float g_h2  [(size_t)TOK * DMODEL];
__device__ float g_ffn [(size_t)TOK * FDIM];

// ====================================================================
// RMSNorm over D=1024: one block per row, one float4 per thread.
// ====================================================================
__global__ __launch_bounds__(256) void rmsnorm_k(const float* __restrict__ x,
                                                 const float* __restrict__ scale,
                                                 float* __restrict__ y)
{
    const int row = blockIdx.x;
    const int t   = threadIdx.x;
    const float4* xr = (const float4*)(x + (size_t)row * DMODEL);
    float4 v = xr[t];
    float ss = v.x*v.x + v.y*v.y + v.z*v.z + v.w*v.w;
    #pragma unroll
    for (int off = 16; off; off >>= 1) ss += __shfl_xor_sync(0xffffffffu, ss, off);
    __shared__ float red[8];
    if ((t & 31) == 0) red[t >> 5] = ss;
    __syncthreads();
    float tot = 0.f;
    #pragma unroll
    for (int w = 0; w < 8; w++) tot += red[w];
    const float r = rsqrtf(tot * (1.0f / DMODEL) + EPS);
    const float4 s4 = ((const float4*)scale)[t];
    float4 o;
    o.x = v.x * r * s4.x; o.y = v.y * r * s4.y;
    o.z = v.z * r * s4.z; o.w = v.w * r * s4.w;
    ((float4*)(y + (size_t)row * DMODEL))[t] = o;
}

// ====================================================================
// Per-head LayerNorm over HD=64, in place. One warp per row (2 elems/lane).
// ====================================================================
__global__ __launch_bounds__(256) void headln_k(float* __restrict__ q,
                                                const float* __restrict__ scale,
                                                const float* __restrict__ bias)
{
    const int row  = blockIdx.x * 8 + (threadIdx.x >> 5);
    const int lane = threadIdx.x & 31;
    float* p = q + (size_t)row * HDIM;
    float a = p[lane];
    float b = p[lane + 32];
    float mu = a + b;
    #pragma unroll
    for (int off = 16; off; off >>= 1) mu += __shfl_xor_sync(0xffffffffu, mu, off);
    mu *= (1.0f / 64.0f);
    float da = a - mu, db = b - mu;
    float var = da*da + db*db;
    #pragma unroll
    for (int off = 16; off; off >>= 1) var += __shfl_xor_sync(0xffffffffu, var, off);
    var *= (1.0f / 64.0f);
    const float r = rsqrtf(var + EPS);
    p[lane]      = da * r * scale[lane]      + bias[lane];
    p[lane + 32] = db * r * scale[lane + 32] + bias[lane + 32];
}

// ====================================================================
// fp32 SGEMM: C[M,N] = A[M,K] @ B[K,N] + bias, optional epilogue.
// 128x128 block, BK=8, 8x8 per thread, 256 threads.
// epi: 0 = bias, 1 = bias+exact GELU, 2 = bias+residual
// ====================================================================
#define EPI_NONE 0
#define EPI_GELU 1
#define EPI_RES  2

__global__ __launch_bounds__(256) void sgemm_k(const float* __restrict__ A,
                                               const float* __restrict__ B,
                                               const float* __restrict__ bias,
                                               const float* __restrict__ res,
                                               float* __restrict__ C,
                                               int M, int N, int K, int epi)
{
    __shared__ float As[8][132];   // transposed A tile, padded vs bank conflicts
    __shared__ float Bs[8][128];

    const int tid  = threadIdx.x;
    const int bm   = blockIdx.y * 128;
    const int bn   = blockIdx.x * 128;
    const int arow = tid >> 1;            // 0..127
    const int acol = (tid & 1) * 4;       // 0 or 4
    const int brow = tid >> 5;            // 0..7
    const int bcol = (tid & 31) * 4;      // 0..124
    const int ty   = tid >> 4;            // row group 0..15
    const int tx   = tid & 15;            // col group 0..15

    const float* Aptr = A + (size_t)(bm + arow) * K + acol;
    const float* Bptr = B + (size_t)brow * N + bn + bcol;

    float acc[8][8];
    #pragma unroll
    for (int i = 0; i < 8; i++)
        #pragma unroll
        for (int j = 0; j < 8; j++) acc[i][j] = 0.f;

    for (int k0 = 0; k0 < K; k0 += 8) {
        float4 av = *(const float4*)(Aptr + k0);
        As[acol + 0][arow] = av.x;
        As[acol + 1][arow] = av.y;
        As[acol + 2][arow] = av.z;
        As[acol + 3][arow] = av.w;
        *(float4*)&Bs[brow][bcol] = *(const float4*)(Bptr + (size_t)k0 * N);
        __syncthreads();
        #pragma unroll
        for (int kk = 0; kk < 8; kk++) {
            float ar[8], br[8];
            *(float4*)(ar)     = *(const float4*)&As[kk][ty * 8];
            *(float4*)(ar + 4) = *(const float4*)&As[kk][ty * 8 + 4];
            *(float4*)(br)     = *(const float4*)&Bs[kk][tx * 8];
            *(float4*)(br + 4) = *(const float4*)&Bs[kk][tx * 8 + 4];
            #pragma unroll
            for (int i = 0; i < 8; i++)
                #pragma unroll
                for (int j = 0; j < 8; j++)
                    acc[i][j] = fmaf(ar[i], br[j], acc[i][j]);
        }
        __syncthreads();
    }

    // epilogue
    #pragma unroll
    for (int i = 0; i < 8; i++) {
        const size_t row = (size_t)(bm + ty * 8 + i);
        float*       crow = C + row * N + bn;
        const float* rrow = res ? (res + row * N + bn) : nullptr;
        #pragma unroll
        for (int jj = 0; jj < 8; jj += 4) {
            float4 o;
            float vals[4];
            #pragma unroll
            for (int j = 0; j < 4; j++) {
                int col = tx * 8 + jj + j;
                float val = acc[i][jj + j] + bias[bn + col];
                if (epi == EPI_GELU)
                    val = 0.5f * val * (1.0f + erff(val * 0.70710678118654752f));
                else if (epi == EPI_RES)
                    val += rrow[col];
                vals[j] = val;
            }
            o.x = vals[0]; o.y = vals[1]; o.z = vals[2]; o.w = vals[3];
            *(float4*)(crow + tx * 8 + jj) = o;
        }
    }
}

// ====================================================================
// fp32 flash attention. HD=64. 64-query CTA, 64-key tiles, online softmax.
// Layout of q/k/v: [B*S, D] with head h in columns [h*64, h*64+64).
// Dynamic smem: Qt[64][68] (dim-major) + KV[64][68] + Ps[64][68] = 52224 B.
// Thread map: ty=tid/16 owns 4 query rows, tx=tid%16 owns 4 cols.
// ====================================================================
#define FA_PITCH 68
#define FA_SMEM  (3 * 64 * FA_PITCH * 4)

__global__ __launch_bounds__(256) void flash_k(const float* __restrict__ Q,
                                               const float* __restrict__ K,
                                               const float* __restrict__ V,
                                               float* __restrict__ O)
{
    extern __shared__ float sm[];
    float* Qt = sm;                       // Qt[d][q]   (dim-major)
    float* KV = sm + 64 * FA_PITCH;       // Kt[d][k] then Vs[k][d]
    float* Ps = sm + 2 * 64 * FA_PITCH;   // Ps[q][k]

    const int tid = threadIdx.x;
    const int ty  = tid >> 4;
    const int tx  = tid & 15;
    const int q0  = blockIdx.x * 64;
    const size_t hoff = (size_t)blockIdx.y * HDIM;
    const size_t boff = (size_t)blockIdx.z * SEQ * DMODEL;
    const float* Qb = Q + boff + hoff;
    const float* Kb = K + boff + hoff;
    const float* Vb = V + boff + hoff;

    // Load Q tile transposed (64 queries x 64 dims)
    #pragma unroll
    for (int t = 0; t < 4; t++) {
        int idx = tid + t * 256;
        int qi  = idx >> 4;
        int dg  = (idx & 15) << 2;
        float4 v = *(const float4*)(Qb + (size_t)(q0 + qi) * DMODEL + dg);
        Qt[(dg + 0) * FA_PITCH + qi] = v.x;
        Qt[(dg + 1) * FA_PITCH + qi] = v.y;
        Qt[(dg + 2) * FA_PITCH + qi] = v.z;
        Qt[(dg + 3) * FA_PITCH + qi] = v.w;
    }

    float m[4], l[4], o[4][4];
    #pragma unroll
    for (int i = 0; i < 4; i++) {
        m[i] = -INFINITY; l[i] = 0.f;
        #pragma unroll
        for (int j = 0; j < 4; j++) o[i][j] = 0.f;
    }

    for (int kb = 0; kb < SEQ; kb += 64) {
        __syncthreads();   // prev-iter PV done reading KV (and Q load on iter 0)
        // Load K tile transposed
        #pragma unroll
        for (int t = 0; t < 4; t++) {
            int idx = tid + t * 256;
            int ki  = idx >> 4;
            int dg  = (idx & 15) << 2;
            float4 v = *(const float4*)(Kb + (size_t)(kb + ki) * DMODEL + dg);
            KV[(dg + 0) * FA_PITCH + ki] = v.x;
            KV[(dg + 1) * FA_PITCH + ki] = v.y;
            KV[(dg + 2) * FA_PITCH + ki] = v.z;
            KV[(dg + 3) * FA_PITCH + ki] = v.w;
        }
        __syncthreads();

        // S = Q @ K^T  (4x4 per thread), conflict-free row reads
        float s[4][4];
        #pragma unroll
        for (int i = 0; i < 4; i++)
            #pragma unroll
            for (int j = 0; j < 4; j++) s[i][j] = 0.f;
        #pragma unroll 8
        for (int kk = 0; kk < 64; kk++) {
            float4 aqv = *(const float4*)&Qt[kk * FA_PITCH + ty * 4];
            float4 akv = *(const float4*)&KV[kk * FA_PITCH + tx * 4];
            float aq[4] = {aqv.x, aqv.y, aqv.z, aqv.w};
            float ak[4] = {akv.x, akv.y, akv.z, akv.w};
            #pragma unroll
            for (int i = 0; i < 4; i++)
                #pragma unroll
                for (int j = 0; j < 4; j++)
                    s[i][j] = fmaf(aq[i], ak[j], s[i][j]);
        }

        // online softmax update per query row
        #pragma unroll
        for (int i = 0; i < 4; i++) {
            #pragma unroll
            for (int j = 0; j < 4; j++) s[i][j] *= 0.125f;  // HD^-0.5
            float rmax = fmaxf(fmaxf(s[i][0], s[i][1]), fmaxf(s[i][2], s[i][3]));
            #pragma unroll
            for (int off = 1; off < 16; off <<= 1)
                rmax = fmaxf(rmax, __shfl_xor_sync(0xffffffffu, rmax, off));
            float mn    = fmaxf(m[i], rmax);
            float alpha = expf(m[i] - mn);
            float rs    = 0.f;
            #pragma unroll
            for (int j = 0; j < 4; j++) {
                float p = expf(s[i][j] - mn);
                s[i][j] = p;
                rs += p;
            }
            #pragma unroll
            for (int off = 1; off < 16; off <<= 1)
                rs += __shfl_xor_sync(0xffffffffu, rs, off);
            l[i] = l[i] * alpha + rs;
            m[i] = mn;
            #pragma unroll
            for (int j = 0; j < 4; j++) o[i][j] *= alpha;
            *(float4*)&Ps[(ty * 4 + i) * FA_PITCH + tx * 4] =
                make_float4(s[i][0], s[i][1], s[i][2], s[i][3]);
        }
        __syncthreads();   // Kt reads done; Ps visible

        // Load V tile (natural layout Vs[k][d])
        #pragma unroll
        for (int t = 0; t < 4; t++) {
            int idx = tid + t * 256;
            int ki  = idx >> 4;
            int dg  = (idx & 15) << 2;
            *(float4*)&KV[ki * FA_PITCH + dg] =
                *(const float4*)(Vb + (size_t)(kb + ki) * DMODEL + dg);
        }
        __syncthreads();

        // O += P @ V
        #pragma unroll 4
        for (int kk = 0; kk < 64; kk++) {
            float pr[4];
            #pragma unroll
            for (int i = 0; i < 4; i++) pr[i] = Ps[(ty * 4 + i) * FA_PITCH + kk];
            float4 vv = *(const float4*)&KV[kk * FA_PITCH + tx * 4];
            float vb[4] = {vv.x, vv.y, vv.z, vv.w};
            #pragma unroll
            for (int i = 0; i < 4; i++)
                #pragma unroll
                for (int j = 0; j < 4; j++)
                    o[i][j] = fmaf(pr[i], vb[j], o[i][j]);
        }
    }

    // finalize: divide by l, write out
    float* Ob = O + boff + hoff;
    #pragma unroll
    for (int i = 0; i < 4; i++) {
        const float inv = 1.0f / l[i];
        float4 ov = make_float4(o[i][0] * inv, o[i][1] * inv,
                                o[i][2] * inv, o[i][3] * inv);
        *(float4*)(Ob + (size_t)(q0 + ty * 4 + i) * DMODEL + tx * 4) = ov;
    }
}

// ====================================================================
// kernel_launch
// ====================================================================
extern "C" void kernel_launch(void* const* d_in, const int* in_sizes, int n_in,
                              void* d_out, int out_size)
{
    const float* x        = (const float*)d_in[0];
    const float* Wq       = (const float*)d_in[1];
    const float* bq       = (const float*)d_in[2];
    const float* Wk       = (const float*)d_in[3];
    const float* bk       = (const float*)d_in[4];
    const float* Wv       = (const float*)d_in[5];
    const float* bv       = (const float*)d_in[6];
    const float* Wo       = (const float*)d_in[7];
    const float* bo       = (const float*)d_in[8];
    const float* qn_scale = (const float*)d_in[9];
    const float* qn_bias  = (const float*)d_in[10];
    const float* kn_scale = (const float*)d_in[11];
    const float* kn_bias  = (const float*)d_in[12];
    const float* W1       = (const float*)d_in[13];
    const float* b1       = (const float*)d_in[14];
    const float* W2       = (const float*)d_in[15];
    const float* b2       = (const float*)d_in[16];
    const float* n1_scale = (const float*)d_in[17];
    const float* n2_scale = (const float*)d_in[18];
    float* out = (float*)d_out;

    float *h, *q, *k, *v, *attn, *x2, *h2, *ffn;
    cudaGetSymbolAddress((void**)&h,    g_h);
    cudaGetSymbolAddress((void**)&q,    g_q);
    cudaGetSymbolAddress((void**)&k,    g_k);
    cudaGetSymbolAddress((void**)&v,    g_v);
    cudaGetSymbolAddress((void**)&attn, g_attn);
    cudaGetSymbolAddress((void**)&x2,   g_x2);
    cudaGetSymbolAddress((void**)&h2,   g_h2);
    cudaGetSymbolAddress((void**)&ffn,  g_ffn);

    cudaFuncSetAttribute(flash_k, cudaFuncAttributeMaxDynamicSharedMemorySize, FA_SMEM);

    const dim3 gD(DMODEL / 128, TOK / 128);   // 8 x 64
    const dim3 gF(FDIM   / 128, TOK / 128);   // 32 x 64

    // 1. h = rms(x) * n1_scale
    rmsnorm_k<<<TOK, 256>>>(x, n1_scale, h);

    // 2. q/k/v = h @ W{q,k,v} + b
    sgemm_k<<<gD, 256>>>(h, Wq, bq, nullptr, q, TOK, DMODEL, DMODEL, EPI_NONE);
    sgemm_k<<<gD, 256>>>(h, Wk, bk, nullptr, k, TOK, DMODEL, DMODEL, EPI_NONE);
    sgemm_k<<<gD, 256>>>(h, Wv, bv, nullptr, v, TOK, DMODEL, DMODEL, EPI_NONE);

    // 3. per-head LayerNorm on q and k (in place)
    headln_k<<<TOK * NHEAD / 8, 256>>>(q, qn_scale, qn_bias);
    headln_k<<<TOK * NHEAD / 8, 256>>>(k, kn_scale, kn_bias);

    // 4. attention
    flash_k<<<dim3(SEQ / 64, NHEAD, BATCH), 256, FA_SMEM>>>(q, k, v, attn);

    // 5. x2 = x + attn @ Wo + bo
    sgemm_k<<<gD, 256>>>(attn, Wo, bo, x, x2, TOK, DMODEL, DMODEL, EPI_RES);

    // 6. h2 = rms(x2) * n2_scale
    rmsnorm_k<<<TOK, 256>>>(x2, n2_scale, h2);

    // 7. ffn = gelu(h2 @ W1 + b1)
    sgemm_k<<<gF, 256>>>(h2, W1, b1, nullptr, ffn, TOK, FDIM, DMODEL, EPI_GELU);

    // 8. out = x2 + ffn @ W2 + b2
    sgemm_k<<<gD, 256>>>(ffn, W2, b2, x2, out, TOK, DMODEL, FDIM, EPI_RES);
}

// round 3
// speedup vs baseline: 1.6848x; 1.6848x over previous
#include <cuda_runtime.h>
#include <cuda_bf16.h>
#include <math.h>
#include <stdint.h>

// ---------------- problem constants ----------------
#define TOK    8192          // 4 * 2048 tokens
#define DMODEL 1024
#define NHEAD  16
#define HDIM   64
#define FDIM   4096
#define SEQ    2048
#define BATCH  4
#define EPS    1e-5f

// ---------------- scratch (device globals; no runtime alloc) --------------
__device__ __align__(256) __nv_bfloat16 g_hH  [(size_t)TOK * DMODEL];
__device__ __align__(256) __nv_bfloat16 g_hL  [(size_t)TOK * DMODEL];
__device__ __align__(256) float         g_q   [(size_t)TOK * DMODEL];
__device__ __align__(256) float         g_k   [(size_t)TOK * DMODEL];
__device__ __align__(256) float         g_v   [(size_t)TOK * DMODEL];
__device__ __align__(256) __nv_bfloat16 g_atH [(size_t)TOK * DMODEL];
__device__ __align__(256) __nv_bfloat16 g_atL [(size_t)TOK * DMODEL];
__device__ __align__(256) float         g_x2  [(size_t)TOK * DMODEL];
__device__ __align__(256) __nv_bfloat16 g_h2H [(size_t)TOK * DMODEL];
__device__ __align__(256) __nv_bfloat16 g_h2L [(size_t)TOK * DMODEL];
__device__ __align__(256) __nv_bfloat16 g_fH  [(size_t)TOK * FDIM];
__device__ __align__(256) __nv_bfloat16 g_fL  [(size_t)TOK * FDIM];
// transposed+split weights: Wt[N,K]
__device__ __align__(256) __nv_bfloat16 g_WqH [(size_t)DMODEL * DMODEL];
__device__ __align__(256) __nv_bfloat16 g_WqL [(size_t)DMODEL * DMODEL];
__device__ __align__(256) __nv_bfloat16 g_WkH [(size_t)DMODEL * DMODEL];
__device__ __align__(256) __nv_bfloat16 g_WkL [(size_t)DMODEL * DMODEL];
__device__ __align__(256) __nv_bfloat16 g_WvH [(size_t)DMODEL * DMODEL];
__device__ __align__(256) __nv_bfloat16 g_WvL [(size_t)DMODEL * DMODEL];
__device__ __align__(256) __nv_bfloat16 g_WoH [(size_t)DMODEL * DMODEL];
__device__ __align__(256) __nv_bfloat16 g_WoL [(size_t)DMODEL * DMODEL];
__device__ __align__(256) __nv_bfloat16 g_W1H [(size_t)FDIM * DMODEL];
__device__ __align__(256) __nv_bfloat16 g_W1L [(size_t)FDIM * DMODEL];
__device__ __align__(256) __nv_bfloat16 g_W2H [(size_t)DMODEL * FDIM];
__device__ __align__(256) __nv_bfloat16 g_W2L [(size_t)DMODEL * FDIM];

// =================== PTX helpers (sm_80-compatible only) ===================
__device__ __forceinline__ uint32_t smem_u32(const void* p) {
    uint32_t a;
    asm("{ .reg .u64 t; cvta.to.shared.u64 t, %1; cvt.u32.u64 %0, t; }"
        : "=r"(a) : "l"(p));
    return a;
}
__device__ __forceinline__ void cp16(uint32_t dst, const void* src) {
    asm volatile("cp.async.cg.shared.global [%0], [%1], 16;"
                 :: "r"(dst), "l"(src));
}
#define CP_COMMIT() asm volatile("cp.async.commit_group;" ::: "memory")
#define CP_WAIT1()  asm volatile("cp.async.wait_group 1;" ::: "memory")
#define CP_WAIT0()  asm volatile("cp.async.wait_group 0;" ::: "memory")

__device__ __forceinline__ void ldmx4(uint32_t* r, uint32_t addr) {
    asm volatile("ldmatrix.sync.aligned.m8n8.x4.shared.b16 {%0,%1,%2,%3}, [%4];"
                 : "=r"(r[0]), "=r"(r[1]), "=r"(r[2]), "=r"(r[3]) : "r"(addr));
}
__device__ __forceinline__ void ldmx2(uint32_t* r, uint32_t addr) {
    asm volatile("ldmatrix.sync.aligned.m8n8.x2.shared.b16 {%0,%1}, [%2];"
                 : "=r"(r[0]), "=r"(r[1]) : "r"(addr));
}
__device__ __forceinline__ void mma16816(float* c, const uint32_t* a,
                                         const uint32_t* b) {
    asm volatile(
        "mma.sync.aligned.m16n8k16.row.col.f32.bf16.bf16.f32 "
        "{%0,%1,%2,%3}, {%4,%5,%6,%7}, {%8,%9}, {%0,%1,%2,%3};"
        : "+f"(c[0]), "+f"(c[1]), "+f"(c[2]), "+f"(c[3])
        : "r"(a[0]), "r"(a[1]), "r"(a[2]), "r"(a[3]), "r"(b[0]), "r"(b[1]));
}

// =================== split helpers ===================
__device__ __forceinline__ void split2(float a, float b,
                                       __nv_bfloat162& hi, __nv_bfloat162& lo) {
    __nv_bfloat16 ha = __float2bfloat16(a), hb = __float2bfloat16(b);
    __nv_bfloat16 la = __float2bfloat16(a - __bfloat162float(ha));
    __nv_bfloat16 lb = __float2bfloat16(b - __bfloat162float(hb));
    hi = __halves2bfloat162(ha, hb);
    lo = __halves2bfloat162(la, lb);
}

// ====================================================================
// Weight transpose + split:  W[K,N] fp32  ->  Th/Tl[N,K] bf16
// ====================================================================
__global__ __launch_bounds__(256) void wsplit_t(const float* __restrict__ W,
                                                __nv_bfloat16* __restrict__ Th,
                                                __nv_bfloat16* __restrict__ Tl,
                                                int K, int N)
{
    __shared__ float t[32][33];
    const int k0 = blockIdx.y * 32, n0 = blockIdx.x * 32;
    const int tx = threadIdx.x, ty = threadIdx.y;   // (32, 8)
    #pragma unroll
    for (int j = 0; j < 4; j++) {
        int r = ty + j * 8;
        t[r][tx] = W[(size_t)(k0 + r) * N + n0 + tx];
    }
    __syncthreads();
    #pragma unroll
    for (int j = 0; j < 4; j++) {
        int r = ty + j * 8;
        float v = t[tx][r];
        __nv_bfloat16 h = __float2bfloat16(v);
        __nv_bfloat16 l = __float2bfloat16(v - __bfloat162float(h));
        size_t o = (size_t)(n0 + r) * K + k0 + tx;
        Th[o] = h; Tl[o] = l;
    }
}

// ====================================================================
// RMSNorm over D=1024 -> split bf16 outputs
// ====================================================================
__global__ __launch_bounds__(256) void rmsnorm_split_k(const float* __restrict__ x,
                                                       const float* __restrict__ scale,
                                                       __nv_bfloat16* __restrict__ yH,
                                                       __nv_bfloat16* __restrict__ yL)
{
    const int row = blockIdx.x;
    const int t   = threadIdx.x;
    const float4 v = ((const float4*)(x + (size_t)row * DMODEL))[t];
    float ss = v.x*v.x + v.y*v.y + v.z*v.z + v.w*v.w;
    #pragma unroll
    for (int off = 16; off; off >>= 1) ss += __shfl_xor_sync(0xffffffffu, ss, off);
    __shared__ float red[8];
    if ((t & 31) == 0) red[t >> 5] = ss;
    __syncthreads();
    float tot = 0.f;
    #pragma unroll
    for (int w = 0; w < 8; w++) tot += red[w];
    const float r = rsqrtf(tot * (1.0f / DMODEL) + EPS);
    const float4 s4 = ((const float4*)scale)[t];
    float o0 = v.x*r*s4.x, o1 = v.y*r*s4.y, o2 = v.z*r*s4.z, o3 = v.w*r*s4.w;
    __nv_bfloat162 h0, l0, h1, l1;
    split2(o0, o1, h0, l0);
    split2(o2, o3, h1, l1);
    const size_t base = (size_t)row * DMODEL + t * 4;
    *(__nv_bfloat162*)(yH + base)     = h0;
    *(__nv_bfloat162*)(yH + base + 2) = h1;
    *(__nv_bfloat162*)(yL + base)     = l0;
    *(__nv_bfloat162*)(yL + base + 2) = l1;
}

// ====================================================================
// Per-head LayerNorm over HD=64 (in place, fp32)
// ====================================================================
__global__ __launch_bounds__(256) void headln_k(float* __restrict__ q,
                                                const float* __restrict__ scale,
                                                const float* __restrict__ bias)
{
    const int row  = blockIdx.x * 8 + (threadIdx.x >> 5);
    const int lane = threadIdx.x & 31;
    float* p = q + (size_t)row * HDIM;
    float a = p[lane];
    float b = p[lane + 32];
    float mu = a + b;
    #pragma unroll
    for (int off = 16; off; off >>= 1) mu += __shfl_xor_sync(0xffffffffu, mu, off);
    mu *= (1.0f / 64.0f);
    float da = a - mu, db = b - mu;
    float var = da*da + db*db;
    #pragma unroll
    for (int off = 16; off; off >>= 1) var += __shfl_xor_sync(0xffffffffu, var, off);
    var *= (1.0f / 64.0f);
    const float r = rsqrtf(var + EPS);
    p[lane]      = da * r * scale[lane]      + bias[lane];
    p[lane + 32] = db * r * scale[lane + 32] + bias[lane + 32];
}

// ====================================================================
// split-bf16 mma.sync GEMM: D[M,N] = A[M,K] @ Wt[N,K]^T + bias (+epi)
// A, Wt given as hi/lo bf16 pairs. CTA 128x128, BK=32, 8 warps (2x4),
// warp tile 64x32 = 4x4 m16n8k16 tiles, 3 HMMA passes (hh, hl, lh).
// epi: 0 -> fp32 out, 1 -> GELU + split bf16 out, 2 -> residual + fp32 out
// ====================================================================
#define EPI_NONE 0
#define EPI_GELU 1
#define EPI_RES  2

#define GPITCH 40                     // halves per smem row (32 + 8 pad)
#define GARR   (128 * GPITCH)         // halves per tile array
#define GSTAGE (4 * GARR)             // Ah, Al, Bh, Bl
#define GSMEM  (2 * GSTAGE * 2)       // bytes (double-buffered)

__global__ __launch_bounds__(256, 1) void mma_gemm(
    const __nv_bfloat16* __restrict__ Ah, const __nv_bfloat16* __restrict__ Al,
    const __nv_bfloat16* __restrict__ Bh, const __nv_bfloat16* __restrict__ Bl,
    const float* __restrict__ bias, const float* __restrict__ res,
    float* __restrict__ outF,
    __nv_bfloat16* __restrict__ outH, __nv_bfloat16* __restrict__ outL,
    int M, int N, int K, int epi)
{
    extern __shared__ __nv_bfloat16 smh[];
    const uint32_t sb = smem_u32(smh);
    const int tid  = threadIdx.x;
    const int wid  = tid >> 5;
    const int lane = tid & 31;
    const int wm   = wid >> 2;           // 0..1 -> 64 rows each
    const int wn   = wid & 3;            // 0..3 -> 32 cols each
    const int bm   = blockIdx.y * 128;
    const int bn   = blockIdx.x * 128;

    auto load_chunk = [&](int c, int s) {
        const int k0 = c << 5;
        const uint32_t base = sb + (uint32_t)s * GSTAGE * 2;
        const __nv_bfloat16* srcs[4] = { Ah, Al, Bh, Bl };
        #pragma unroll
        for (int j = 0; j < 8; j++) {
            int idx = tid + j * 256;       // 2048 x 16B
            int arr = idx >> 9;            // 0..3
            int a   = idx & 511;
            int row = a >> 2, ch = a & 3;
            int gr  = ((arr < 2) ? bm : bn) + row;
            cp16(base + (uint32_t)arr * GARR * 2 + (uint32_t)(row * GPITCH + ch * 8) * 2,
                 srcs[arr] + (size_t)gr * K + k0 + ch * 8);
        }
        CP_COMMIT();
    };

    float acc[4][4][4];
    #pragma unroll
    for (int m = 0; m < 4; m++)
        #pragma unroll
        for (int n = 0; n < 4; n++)
            #pragma unroll
            for (int e = 0; e < 4; e++) acc[m][n][e] = 0.f;

    const int nch = K >> 5;
    load_chunk(0, 0);
    load_chunk(1, 1);

    const int l16 = lane & 15;
    const int a_r = l16;                 // A fragment source row
    const int a_c = (lane >> 4) * 8;     // A fragment source col (halves)
    const int b_r = l16 & 7;             // B fragment source row
    const int b_c = (l16 >> 3) * 8;      // B fragment source col (halves)

    for (int i = 0; i < nch; i++) {
        const int s = i & 1;
        if (i + 1 < nch) { CP_WAIT1(); } else { CP_WAIT0(); }
        __syncthreads();
        const uint32_t ab = sb + (uint32_t)s * GSTAGE * 2;

        #pragma unroll
        for (int kk = 0; kk < 2; kk++) {
            const int kh = kk * 16;
            uint32_t ah[4][4], al[4][4], bh[4][2], bl[4][2];
            #pragma unroll
            for (int m = 0; m < 4; m++) {
                uint32_t addr = ab +
                    (uint32_t)((wm * 64 + m * 16 + a_r) * GPITCH + kh + a_c) * 2;
                ldmx4(ah[m], addr);
                ldmx4(al[m], addr + GARR * 2);
            }
            #pragma unroll
            for (int n = 0; n < 4; n++) {
                uint32_t addr = ab + 2 * GARR * 2 +
                    (uint32_t)((wn * 32 + n * 8 + b_r) * GPITCH + kh + b_c) * 2;
                ldmx2(bh[n], addr);
                ldmx2(bl[n], addr + GARR * 2);
            }
            #pragma unroll
            for (int m = 0; m < 4; m++)
                #pragma unroll
                for (int n = 0; n < 4; n++) {
                    mma16816(acc[m][n], ah[m], bh[n]);
                    mma16816(acc[m][n], ah[m], bl[n]);
                    mma16816(acc[m][n], al[m], bh[n]);
                }
        }
        __syncthreads();
        if (i + 2 < nch) load_chunk(i + 2, s);
    }

    // -------- epilogue: registers -> gmem with fused bias/gelu/residual ----
    const int g  = lane >> 2;
    const int t4 = lane & 3;
    #pragma unroll
    for (int n = 0; n < 4; n++) {
        const int col = bn + wn * 32 + n * 8 + t4 * 2;
        const float b0 = __ldg(&bias[col]);
        const float b1 = __ldg(&bias[col + 1]);
        #pragma unroll
        for (int m = 0; m < 4; m++) {
            const int row0 = bm + wm * 64 + m * 16 + g;
            float v[4] = { acc[m][n][0] + b0, acc[m][n][1] + b1,
                           acc[m][n][2] + b0, acc[m][n][3] + b1 };
            if (epi == EPI_GELU) {
                #pragma unroll
                for (int e = 0; e < 4; e++) {
                    float u = v[e];
                    v[e] = 0.5f * u * (1.0f + erff(u * 0.70710678118654752f));
                }
                __nv_bfloat162 h2, l2;
                split2(v[0], v[1], h2, l2);
                *(__nv_bfloat162*)(outH + (size_t)row0 * N + col) = h2;
                *(__nv_bfloat162*)(outL + (size_t)row0 * N + col) = l2;
                split2(v[2], v[3], h2, l2);
                *(__nv_bfloat162*)(outH + (size_t)(row0 + 8) * N + col) = h2;
                *(__nv_bfloat162*)(outL + (size_t)(row0 + 8) * N + col) = l2;
            } else {
                if (epi == EPI_RES) {
                    float2 r0 = *(const float2*)(res + (size_t)row0 * N + col);
                    float2 r1 = *(const float2*)(res + (size_t)(row0 + 8) * N + col);
                    v[0] += r0.x; v[1] += r0.y; v[2] += r1.x; v[3] += r1.y;
                }
                *(float2*)(outF + (size_t)row0 * N + col)       = make_float2(v[0], v[1]);
                *(float2*)(outF + (size_t)(row0 + 8) * N + col) = make_float2(v[2], v[3]);
            }
        }
    }
}

// ====================================================================
// fp32 flash attention — emits split-bf16 output for the Wo GEMM.
// ====================================================================
#define FA_PITCH 68
#define FA_SMEM  (3 * 64 * FA_PITCH * 4)

__global__ __launch_bounds__(256) void flash_k(const float* __restrict__ Q,
                                               const float* __restrict__ K,
                                               const float* __restrict__ V,
                                               __nv_bfloat16* __restrict__ OH,
                                               __nv_bfloat16* __restrict__ OL)
{
    extern __shared__ float sm[];
    float* Qt = sm;
    float* KV = sm + 64 * FA_PITCH;
    float* Ps = sm + 2 * 64 * FA_PITCH;

    const int tid = threadIdx.x;
    const int ty  = tid >> 4;
    const int tx  = tid & 15;
    const int q0  = blockIdx.x * 64;
    const size_t hoff = (size_t)blockIdx.y * HDIM;
    const size_t boff = (size_t)blockIdx.z * SEQ * DMODEL;
    const float* Qb = Q + boff + hoff;
    const float* Kb = K + boff + hoff;
    const float* Vb = V + boff + hoff;

    #pragma unroll
    for (int t = 0; t < 4; t++) {
        int idx = tid + t * 256;
        int qi  = idx >> 4;
        int dg  = (idx & 15) << 2;
        float4 v = *(const float4*)(Qb + (size_t)(q0 + qi) * DMODEL + dg);
        Qt[(dg + 0) * FA_PITCH + qi] = v.x;
        Qt[(dg + 1) * FA_PITCH + qi] = v.y;
        Qt[(dg + 2) * FA_PITCH + qi] = v.z;
        Qt[(dg + 3) * FA_PITCH + qi] = v.w;
    }

    float m[4], l[4], o[4][4];
    #pragma unroll
    for (int i = 0; i < 4; i++) {
        m[i] = -INFINITY; l[i] = 0.f;
        #pragma unroll
        for (int j = 0; j < 4; j++) o[i][j] = 0.f;
    }

    for (int kb = 0; kb < SEQ; kb += 64) {
        __syncthreads();
        #pragma unroll
        for (int t = 0; t < 4; t++) {
            int idx = tid + t * 256;
            int ki  = idx >> 4;
            int dg  = (idx & 15) << 2;
            float4 v = *(const float4*)(Kb + (size_t)(kb + ki) * DMODEL + dg);
            KV[(dg + 0) * FA_PITCH + ki] = v.x;
            KV[(dg + 1) * FA_PITCH + ki] = v.y;
            KV[(dg + 2) * FA_PITCH + ki] = v.z;
            KV[(dg + 3) * FA_PITCH + ki] = v.w;
        }
        __syncthreads();

        float s[4][4];
        #pragma unroll
        for (int i = 0; i < 4; i++)
            #pragma unroll
            for (int j = 0; j < 4; j++) s[i][j] = 0.f;
        #pragma unroll 8
        for (int kk = 0; kk < 64; kk++) {
            float4 aqv = *(const float4*)&Qt[kk * FA_PITCH + ty * 4];
            float4 akv = *(const float4*)&KV[kk * FA_PITCH + tx * 4];
            float aq[4] = {aqv.x, aqv.y, aqv.z, aqv.w};
            float ak[4] = {akv.x, akv.y, akv.z, akv.w};
            #pragma unroll
            for (int i = 0; i < 4; i++)
                #pragma unroll
                for (int j = 0; j < 4; j++)
                    s[i][j] = fmaf(aq[i], ak[j], s[i][j]);
        }

        #pragma unroll
        for (int i = 0; i < 4; i++) {
            #pragma unroll
            for (int j = 0; j < 4; j++) s[i][j] *= 0.125f;
            float rmax = fmaxf(fmaxf(s[i][0], s[i][1]), fmaxf(s[i][2], s[i][3]));
            #pragma unroll
            for (int off = 1; off < 16; off <<= 1)
                rmax = fmaxf(rmax, __shfl_xor_sync(0xffffffffu, rmax, off));
            float mn    = fmaxf(m[i], rmax);
            float alpha = expf(m[i] - mn);
            float rs    = 0.f;
            #pragma unroll
            for (int j = 0; j < 4; j++) {
                float p = expf(s[i][j] - mn);
                s[i][j] = p;
                rs += p;
            }
            #pragma unroll
            for (int off = 1; off < 16; off <<= 1)
                rs += __shfl_xor_sync(0xffffffffu, rs, off);
            l[i] = l[i] * alpha + rs;
            m[i] = mn;
            #pragma unroll
            for (int j = 0; j < 4; j++) o[i][j] *= alpha;
            *(float4*)&Ps[(ty * 4 + i) * FA_PITCH + tx * 4] =
                make_float4(s[i][0], s[i][1], s[i][2], s[i][3]);
        }
        __syncthreads();

        #pragma unroll
        for (int t = 0; t < 4; t++) {
            int idx = tid + t * 256;
            int ki  = idx >> 4;
            int dg  = (idx & 15) << 2;
            *(float4*)&KV[ki * FA_PITCH + dg] =
                *(const float4*)(Vb + (size_t)(kb + ki) * DMODEL + dg);
        }
        __syncthreads();

        #pragma unroll 4
        for (int kk = 0; kk < 64; kk++) {
            float pr[4];
            #pragma unroll
            for (int i = 0; i < 4; i++) pr[i] = Ps[(ty * 4 + i) * FA_PITCH + kk];
            float4 vv = *(const float4*)&KV[kk * FA_PITCH + tx * 4];
            float vb[4] = {vv.x, vv.y, vv.z, vv.w};
            #pragma unroll
            for (int i = 0; i < 4; i++)
                #pragma unroll
                for (int j = 0; j < 4; j++)
                    o[i][j] = fmaf(pr[i], vb[j], o[i][j]);
        }
    }

    __nv_bfloat16* OhB = OH + boff + hoff;
    __nv_bfloat16* OlB = OL + boff + hoff;
    #pragma unroll
    for (int i = 0; i < 4; i++) {
        const float inv = 1.0f / l[i];
        float v0 = o[i][0]*inv, v1 = o[i][1]*inv, v2 = o[i][2]*inv, v3 = o[i][3]*inv;
        __nv_bfloat162 h0, l0, h1, l1;
        split2(v0, v1, h0, l0);
        split2(v2, v3, h1, l1);
        const size_t off = (size_t)(q0 + ty * 4 + i) * DMODEL + tx * 4;
        *(__nv_bfloat162*)(OhB + off)     = h0;
        *(__nv_bfloat162*)(OhB + off + 2) = h1;
        *(__nv_bfloat162*)(OlB + off)     = l0;
        *(__nv_bfloat162*)(OlB + off + 2) = l1;
    }
}

// ====================================================================
// kernel_launch
// ====================================================================
extern "C" void kernel_launch(void* const* d_in, const int* in_sizes, int n_in,
                              void* d_out, int out_size)
{
    const float* x        = (const float*)d_in[0];
    const float* Wq       = (const float*)d_in[1];
    const float* bq       = (const float*)d_in[2];
    const float* Wk       = (const float*)d_in[3];
    const float* bk       = (const float*)d_in[4];
    const float* Wv       = (const float*)d_in[5];
    const float* bv       = (const float*)d_in[6];
    const float* Wo       = (const float*)d_in[7];
    const float* bo       = (const float*)d_in[8];
    const float* qn_scale = (const float*)d_in[9];
    const float* qn_bias  = (const float*)d_in[10];
    const float* kn_scale = (const float*)d_in[11];
    const float* kn_bias  = (const float*)d_in[12];
    const float* W1       = (const float*)d_in[13];
    const float* b1       = (const float*)d_in[14];
    const float* W2       = (const float*)d_in[15];
    const float* b2       = (const float*)d_in[16];
    const float* n1_scale = (const float*)d_in[17];
    const float* n2_scale = (const float*)d_in[18];
    float* out = (float*)d_out;

    __nv_bfloat16 *hH, *hL, *atH, *atL, *h2H, *h2L, *fH, *fL;
    __nv_bfloat16 *WqH, *WqL, *WkH, *WkL, *WvH, *WvL, *WoH, *WoL, *W1H, *W1L, *W2H, *W2L;
    float *q, *k, *v, *x2;
    cudaGetSymbolAddress((void**)&hH,  g_hH);  cudaGetSymbolAddress((void**)&hL,  g_hL);
    cudaGetSymbolAddress((void**)&q,   g_q);   cudaGetSymbolAddress((void**)&k,   g_k);
    cudaGetSymbolAddress((void**)&v,   g_v);
    cudaGetSymbolAddress((void**)&atH, g_atH); cudaGetSymbolAddress((void**)&atL, g_atL);
    cudaGetSymbolAddress((void**)&x2,  g_x2);
    cudaGetSymbolAddress((void**)&h2H, g_h2H); cudaGetSymbolAddress((void**)&h2L, g_h2L);
    cudaGetSymbolAddress((void**)&fH,  g_fH);  cudaGetSymbolAddress((void**)&fL,  g_fL);
    cudaGetSymbolAddress((void**)&WqH, g_WqH); cudaGetSymbolAddress((void**)&WqL, g_WqL);
    cudaGetSymbolAddress((void**)&WkH, g_WkH); cudaGetSymbolAddress((void**)&WkL, g_WkL);
    cudaGetSymbolAddress((void**)&WvH, g_WvH); cudaGetSymbolAddress((void**)&WvL, g_WvL);
    cudaGetSymbolAddress((void**)&WoH, g_WoH); cudaGetSymbolAddress((void**)&WoL, g_WoL);
    cudaGetSymbolAddress((void**)&W1H, g_W1H); cudaGetSymbolAddress((void**)&W1L, g_W1L);
    cudaGetSymbolAddress((void**)&W2H, g_W2H); cudaGetSymbolAddress((void**)&W2L, g_W2L);

    cudaFuncSetAttribute(mma_gemm, cudaFuncAttributeMaxDynamicSharedMemorySize, GSMEM);
    cudaFuncSetAttribute(flash_k,  cudaFuncAttributeMaxDynamicSharedMemorySize, FA_SMEM);

    const dim3 tb(32, 8);
    // weight transpose + split (Wt[N,K])
    wsplit_t<<<dim3(DMODEL/32, DMODEL/32), tb>>>(Wq, WqH, WqL, DMODEL, DMODEL);
    wsplit_t<<<dim3(DMODEL/32, DMODEL/32), tb>>>(Wk, WkH, WkL, DMODEL, DMODEL);
    wsplit_t<<<dim3(DMODEL/32, DMODEL/32), tb>>>(Wv, WvH, WvL, DMODEL, DMODEL);
    wsplit_t<<<dim3(DMODEL/32, DMODEL/32), tb>>>(Wo, WoH, WoL, DMODEL, DMODEL);
    wsplit_t<<<dim3(FDIM/32,   DMODEL/32), tb>>>(W1, W1H, W1L, DMODEL, FDIM);
    wsplit_t<<<dim3(DMODEL/32, FDIM/32),   tb>>>(W2, W2H, W2L, FDIM,   DMODEL);

    const dim3 gD(DMODEL / 128, TOK / 128);   // 8 x 64
    const dim3 gF(FDIM   / 128, TOK / 128);   // 32 x 64

    // 1. h = rms(x) * n1_scale  (split)
    rmsnorm_split_k<<<TOK, 256>>>(x, n1_scale, hH, hL);

    // 2. q/k/v = h @ W{q,k,v} + b  (fp32 out)
    mma_gemm<<<gD, 256, GSMEM>>>(hH, hL, WqH, WqL, bq, nullptr, q, nullptr, nullptr,
                                 TOK, DMODEL, DMODEL, EPI_NONE);
    mma_gemm<<<gD, 256, GSMEM>>>(hH, hL, WkH, WkL, bk, nullptr, k, nullptr, nullptr,
                                 TOK, DMODEL, DMODEL, EPI_NONE);
    mma_gemm<<<gD, 256, GSMEM>>>(hH, hL, WvH, WvL, bv, nullptr, v, nullptr, nullptr,
                                 TOK, DMODEL, DMODEL, EPI_NONE);

    // 3. per-head LayerNorm on q and k
    headln_k<<<TOK * NHEAD / 8, 256>>>(q, qn_scale, qn_bias);
    headln_k<<<TOK * NHEAD / 8, 256>>>(k, kn_scale, kn_bias);

    // 4. attention -> split bf16
    flash_k<<<dim3(SEQ / 64, NHEAD, BATCH), 256, FA_SMEM>>>(q, k, v, atH, atL);

    // 5. x2 = x + attn @ Wo + bo
    mma_gemm<<<gD, 256, GSMEM>>>(atH, atL, WoH, WoL, bo, x, x2, nullptr, nullptr,
                                 TOK, DMODEL, DMODEL, EPI_RES);

    // 6. h2 = rms(x2) * n2_scale  (split)
    rmsnorm_split_k<<<TOK, 256>>>(x2, n2_scale, h2H, h2L);

    // 7. ffn = gelu(h2 @ W1 + b1)  (split bf16 out)
    mma_gemm<<<gF, 256, GSMEM>>>(h2H, h2L, W1H, W1L, b1, nullptr, nullptr, fH, fL,
                                 TOK, FDIM, DMODEL, EPI_GELU);

    // 8. out = x2 + ffn @ W2 + b2
    mma_gemm<<<gD, 256, GSMEM>>>(fH, fL, W2H, W2L, b2, x2, out, nullptr, nullptr,
                                 TOK, DMODEL, FDIM, EPI_RES);
}

// round 4
// speedup vs baseline: 2.8226x; 1.6754x over previous
#include <cuda_runtime.h>
#include <cuda_bf16.h>
#include <math.h>
#include <stdint.h>

// ---------------- problem constants ----------------
#define TOK    8192          // 4 * 2048 tokens
#define DMODEL 1024
#define NHEAD  16
#define HDIM   64
#define FDIM   4096
#define SEQ    2048
#define BATCH  4
#define EPS    1e-5f

// ---------------- scratch (device globals; no runtime alloc) --------------
__device__ __align__(256) __nv_bfloat16 g_hH  [(size_t)TOK * DMODEL];
__device__ __align__(256) __nv_bfloat16 g_hL  [(size_t)TOK * DMODEL];
__device__ __align__(256) float         g_q   [(size_t)TOK * DMODEL];
__device__ __align__(256) float         g_k   [(size_t)TOK * DMODEL];
__device__ __align__(256) __nv_bfloat16 g_qb  [(size_t)TOK * DMODEL];
__device__ __align__(256) __nv_bfloat16 g_kb  [(size_t)TOK * DMODEL];
__device__ __align__(256) __nv_bfloat16 g_vb  [(size_t)TOK * DMODEL];
__device__ __align__(256) __nv_bfloat16 g_atH [(size_t)TOK * DMODEL];
__device__ __align__(256) __nv_bfloat16 g_atL [(size_t)TOK * DMODEL];
__device__ __align__(256) float         g_x2  [(size_t)TOK * DMODEL];
__device__ __align__(256) __nv_bfloat16 g_h2H [(size_t)TOK * DMODEL];
__device__ __align__(256) __nv_bfloat16 g_h2L [(size_t)TOK * DMODEL];
__device__ __align__(256) __nv_bfloat16 g_fH  [(size_t)TOK * FDIM];
__device__ __align__(256) __nv_bfloat16 g_fL  [(size_t)TOK * FDIM];
// transposed+split weights: Wt[N,K]
__device__ __align__(256) __nv_bfloat16 g_WqH [(size_t)DMODEL * DMODEL];
__device__ __align__(256) __nv_bfloat16 g_WqL [(size_t)DMODEL * DMODEL];
__device__ __align__(256) __nv_bfloat16 g_WkH [(size_t)DMODEL * DMODEL];
__device__ __align__(256) __nv_bfloat16 g_WkL [(size_t)DMODEL * DMODEL];
__device__ __align__(256) __nv_bfloat16 g_WvH [(size_t)DMODEL * DMODEL];
__device__ __align__(256) __nv_bfloat16 g_WvL [(size_t)DMODEL * DMODEL];
__device__ __align__(256) __nv_bfloat16 g_WoH [(size_t)DMODEL * DMODEL];
__device__ __align__(256) __nv_bfloat16 g_WoL [(size_t)DMODEL * DMODEL];
__device__ __align__(256) __nv_bfloat16 g_W1H [(size_t)FDIM * DMODEL];
__device__ __align__(256) __nv_bfloat16 g_W1L [(size_t)FDIM * DMODEL];
__device__ __align__(256) __nv_bfloat16 g_W2H [(size_t)DMODEL * FDIM];
__device__ __align__(256) __nv_bfloat16 g_W2L [(size_t)DMODEL * FDIM];

// =================== PTX helpers (sm_80-compatible only) ===================
__device__ __forceinline__ uint32_t smem_u32(const void* p) {
    uint32_t a;
    asm("{ .reg .u64 t; cvta.to.shared.u64 t, %1; cvt.u32.u64 %0, t; }"
        : "=r"(a) : "l"(p));
    return a;
}
__device__ __forceinline__ void cp16(uint32_t dst, const void* src) {
    asm volatile("cp.async.cg.shared.global [%0], [%1], 16;"
                 :: "r"(dst), "l"(src));
}
#define CP_COMMIT() asm volatile("cp.async.commit_group;" ::: "memory")
#define CP_WAIT1()  asm volatile("cp.async.wait_group 1;" ::: "memory")
#define CP_WAIT0()  asm volatile("cp.async.wait_group 0;" ::: "memory")

__device__ __forceinline__ void ldmx4(uint32_t* r, uint32_t addr) {
    asm volatile("ldmatrix.sync.aligned.m8n8.x4.shared.b16 {%0,%1,%2,%3}, [%4];"
                 : "=r"(r[0]), "=r"(r[1]), "=r"(r[2]), "=r"(r[3]) : "r"(addr));
}
__device__ __forceinline__ void ldmx4t(uint32_t* r, uint32_t addr) {
    asm volatile("ldmatrix.sync.aligned.m8n8.x4.trans.shared.b16 {%0,%1,%2,%3}, [%4];"
                 : "=r"(r[0]), "=r"(r[1]), "=r"(r[2]), "=r"(r[3]) : "r"(addr));
}
__device__ __forceinline__ void ldmx2(uint32_t* r, uint32_t addr) {
    asm volatile("ldmatrix.sync.aligned.m8n8.x2.shared.b16 {%0,%1}, [%2];"
                 : "=r"(r[0]), "=r"(r[1]) : "r"(addr));
}
__device__ __forceinline__ void mma16816(float* c, const uint32_t* a,
                                         const uint32_t* b) {
    asm volatile(
        "mma.sync.aligned.m16n8k16.row.col.f32.bf16.bf16.f32 "
        "{%0,%1,%2,%3}, {%4,%5,%6,%7}, {%8,%9}, {%0,%1,%2,%3};"
        : "+f"(c[0]), "+f"(c[1]), "+f"(c[2]), "+f"(c[3])
        : "r"(a[0]), "r"(a[1]), "r"(a[2]), "r"(a[3]), "r"(b[0]), "r"(b[1]));
}

// =================== split helpers ===================
__device__ __forceinline__ void split2(float a, float b,
                                       __nv_bfloat162& hi, __nv_bfloat162& lo) {
    __nv_bfloat16 ha = __float2bfloat16(a), hb = __float2bfloat16(b);
    __nv_bfloat16 la = __float2bfloat16(a - __bfloat162float(ha));
    __nv_bfloat16 lb = __float2bfloat16(b - __bfloat162float(hb));
    hi = __halves2bfloat162(ha, hb);
    lo = __halves2bfloat162(la, lb);
}
__device__ __forceinline__ uint32_t packbf2(float lo, float hi) {
    __nv_bfloat162 t = __halves2bfloat162(__float2bfloat16(lo), __float2bfloat16(hi));
    return *(uint32_t*)&t;
}

// ====================================================================
// Weight transpose + split:  W[K,N] fp32  ->  Th/Tl[N,K] bf16
// ====================================================================
__global__ __launch_bounds__(256) void wsplit_t(const float* __restrict__ W,
                                                __nv_bfloat16* __restrict__ Th,
                                                __nv_bfloat16* __restrict__ Tl,
                                                int K, int N)
{
    __shared__ float t[32][33];
    const int k0 = blockIdx.y * 32, n0 = blockIdx.x * 32;
    const int tx = threadIdx.x, ty = threadIdx.y;   // (32, 8)
    #pragma unroll
    for (int j = 0; j < 4; j++) {
        int r = ty + j * 8;
        t[r][tx] = W[(size_t)(k0 + r) * N + n0 + tx];
    }
    __syncthreads();
    #pragma unroll
    for (int j = 0; j < 4; j++) {
        int r = ty + j * 8;
        float v = t[tx][r];
        __nv_bfloat16 h = __float2bfloat16(v);
        __nv_bfloat16 l = __float2bfloat16(v - __bfloat162float(h));
        size_t o = (size_t)(n0 + r) * K + k0 + tx;
        Th[o] = h; Tl[o] = l;
    }
}

// ====================================================================
// RMSNorm over D=1024 -> split bf16 outputs
// ====================================================================
__global__ __launch_bounds__(256) void rmsnorm_split_k(const float* __restrict__ x,
                                                       const float* __restrict__ scale,
                                                       __nv_bfloat16* __restrict__ yH,
                                                       __nv_bfloat16* __restrict__ yL)
{
    const int row = blockIdx.x;
    const int t   = threadIdx.x;
    const float4 v = ((const float4*)(x + (size_t)row * DMODEL))[t];
    float ss = v.x*v.x + v.y*v.y + v.z*v.z + v.w*v.w;
    #pragma unroll
    for (int off = 16; off; off >>= 1) ss += __shfl_xor_sync(0xffffffffu, ss, off);
    __shared__ float red[8];
    if ((t & 31) == 0) red[t >> 5] = ss;
    __syncthreads();
    float tot = 0.f;
    #pragma unroll
    for (int w = 0; w < 8; w++) tot += red[w];
    const float r = rsqrtf(tot * (1.0f / DMODEL) + EPS);
    const float4 s4 = ((const float4*)scale)[t];
    float o0 = v.x*r*s4.x, o1 = v.y*r*s4.y, o2 = v.z*r*s4.z, o3 = v.w*r*s4.w;
    __nv_bfloat162 h0, l0, h1, l1;
    split2(o0, o1, h0, l0);
    split2(o2, o3, h1, l1);
    const size_t base = (size_t)row * DMODEL + t * 4;
    *(__nv_bfloat162*)(yH + base)     = h0;
    *(__nv_bfloat162*)(yH + base + 2) = h1;
    *(__nv_bfloat162*)(yL + base)     = l0;
    *(__nv_bfloat162*)(yL + base + 2) = l1;
}

// ====================================================================
// Per-head LayerNorm over HD=64, fp32 in -> bf16 out (optional scale mul)
// ====================================================================
__global__ __launch_bounds__(256) void headln_bf16(const float* __restrict__ src,
                                                   __nv_bfloat16* __restrict__ dst,
                                                   const float* __restrict__ scale,
                                                   const float* __restrict__ bias,
                                                   float mul)
{
    const int row  = blockIdx.x * 8 + (threadIdx.x >> 5);
    const int lane = threadIdx.x & 31;
    const float* p = src + (size_t)row * HDIM;
    float a = p[lane];
    float b = p[lane + 32];
    float mu = a + b;
    #pragma unroll
    for (int off = 16; off; off >>= 1) mu += __shfl_xor_sync(0xffffffffu, mu, off);
    mu *= (1.0f / 64.0f);
    float da = a - mu, db = b - mu;
    float var = da*da + db*db;
    #pragma unroll
    for (int off = 16; off; off >>= 1) var += __shfl_xor_sync(0xffffffffu, var, off);
    var *= (1.0f / 64.0f);
    const float r = rsqrtf(var + EPS);
    float ra = (da * r * scale[lane]      + bias[lane])      * mul;
    float rb = (db * r * scale[lane + 32] + bias[lane + 32]) * mul;
    dst[(size_t)row * HDIM + lane]      = __float2bfloat16(ra);
    dst[(size_t)row * HDIM + lane + 32] = __float2bfloat16(rb);
}

// ====================================================================
// split-bf16 mma.sync GEMM: D[M,N] = A[M,K] @ Wt[N,K]^T + bias (+epi)
// ====================================================================
#define EPI_NONE 0
#define EPI_GELU 1
#define EPI_RES  2
#define EPI_BF16 3

#define GPITCH 40                     // halves per smem row (32 + 8 pad)
#define GARR   (128 * GPITCH)         // halves per tile array
#define GSTAGE (4 * GARR)             // Ah, Al, Bh, Bl
#define GSMEM  (2 * GSTAGE * 2)       // bytes (double-buffered)

__global__ __launch_bounds__(256, 1) void mma_gemm(
    const __nv_bfloat16* __restrict__ Ah, const __nv_bfloat16* __restrict__ Al,
    const __nv_bfloat16* __restrict__ Bh, const __nv_bfloat16* __restrict__ Bl,
    const float* __restrict__ bias, const float* __restrict__ res,
    float* __restrict__ outF,
    __nv_bfloat16* __restrict__ outH, __nv_bfloat16* __restrict__ outL,
    int M, int N, int K, int epi)
{
    extern __shared__ __nv_bfloat16 smh[];
    const uint32_t sb = smem_u32(smh);
    const int tid  = threadIdx.x;
    const int wid  = tid >> 5;
    const int lane = tid & 31;
    const int wm   = wid >> 2;           // 0..1 -> 64 rows each
    const int wn   = wid & 3;            // 0..3 -> 32 cols each
    const int bm   = blockIdx.y * 128;
    const int bn   = blockIdx.x * 128;

    auto load_chunk = [&](int c, int s) {
        const int k0 = c << 5;
        const uint32_t base = sb + (uint32_t)s * GSTAGE * 2;
        const __nv_bfloat16* srcs[4] = { Ah, Al, Bh, Bl };
        #pragma unroll
        for (int j = 0; j < 8; j++) {
            int idx = tid + j * 256;       // 2048 x 16B
            int arr = idx >> 9;            // 0..3
            int a   = idx & 511;
            int row = a >> 2, ch = a & 3;
            int gr  = ((arr < 2) ? bm : bn) + row;
            cp16(base + (uint32_t)arr * GARR * 2 + (uint32_t)(row * GPITCH + ch * 8) * 2,
                 srcs[arr] + (size_t)gr * K + k0 + ch * 8);
        }
        CP_COMMIT();
    };

    float acc[4][4][4];
    #pragma unroll
    for (int m = 0; m < 4; m++)
        #pragma unroll
        for (int n = 0; n < 4; n++)
            #pragma unroll
            for (int e = 0; e < 4; e++) acc[m][n][e] = 0.f;

    const int nch = K >> 5;
    load_chunk(0, 0);
    load_chunk(1, 1);

    const int l16 = lane & 15;
    const int a_r = l16;
    const int a_c = (lane >> 4) * 8;
    const int b_r = l16 & 7;
    const int b_c = (l16 >> 3) * 8;

    for (int i = 0; i < nch; i++) {
        const int s = i & 1;
        if (i + 1 < nch) { CP_WAIT1(); } else { CP_WAIT0(); }
        __syncthreads();
        const uint32_t ab = sb + (uint32_t)s * GSTAGE * 2;

        #pragma unroll
        for (int kk = 0; kk < 2; kk++) {
            const int kh = kk * 16;
            uint32_t ah[4][4], al[4][4], bh[4][2], bl[4][2];
            #pragma unroll
            for (int m = 0; m < 4; m++) {
                uint32_t addr = ab +
                    (uint32_t)((wm * 64 + m * 16 + a_r) * GPITCH + kh + a_c) * 2;
                ldmx4(ah[m], addr);
                ldmx4(al[m], addr + GARR * 2);
            }
            #pragma unroll
            for (int n = 0; n < 4; n++) {
                uint32_t addr = ab + 2 * GARR * 2 +
                    (uint32_t)((wn * 32 + n * 8 + b_r) * GPITCH + kh + b_c) * 2;
                ldmx2(bh[n], addr);
                ldmx2(bl[n], addr + GARR * 2);
            }
            #pragma unroll
            for (int m = 0; m < 4; m++)
                #pragma unroll
                for (int n = 0; n < 4; n++) {
                    mma16816(acc[m][n], ah[m], bh[n]);
                    mma16816(acc[m][n], ah[m], bl[n]);
                    mma16816(acc[m][n], al[m], bh[n]);
                }
        }
        __syncthreads();
        if (i + 2 < nch) load_chunk(i + 2, s);
    }

    // -------- epilogue ----------
    const int g  = lane >> 2;
    const int t4 = lane & 3;
    #pragma unroll
    for (int n = 0; n < 4; n++) {
        const int col = bn + wn * 32 + n * 8 + t4 * 2;
        const float b0 = __ldg(&bias[col]);
        const float b1 = __ldg(&bias[col + 1]);
        #pragma unroll
        for (int m = 0; m < 4; m++) {
            const int row0 = bm + wm * 64 + m * 16 + g;
            float v[4] = { acc[m][n][0] + b0, acc[m][n][1] + b1,
                           acc[m][n][2] + b0, acc[m][n][3] + b1 };
            if (epi == EPI_GELU) {
                #pragma unroll
                for (int e = 0; e < 4; e++) {
                    float u = v[e];
                    v[e] = 0.5f * u * (1.0f + erff(u * 0.70710678118654752f));
                }
                __nv_bfloat162 h2, l2;
                split2(v[0], v[1], h2, l2);
                *(__nv_bfloat162*)(outH + (size_t)row0 * N + col) = h2;
                *(__nv_bfloat162*)(outL + (size_t)row0 * N + col) = l2;
                split2(v[2], v[3], h2, l2);
                *(__nv_bfloat162*)(outH + (size_t)(row0 + 8) * N + col) = h2;
                *(__nv_bfloat162*)(outL + (size_t)(row0 + 8) * N + col) = l2;
            } else if (epi == EPI_BF16) {
                *(uint32_t*)(outH + (size_t)row0 * N + col)       = packbf2(v[0], v[1]);
                *(uint32_t*)(outH + (size_t)(row0 + 8) * N + col) = packbf2(v[2], v[3]);
            } else {
                if (epi == EPI_RES) {
                    float2 r0 = *(const float2*)(res + (size_t)row0 * N + col);
                    float2 r1 = *(const float2*)(res + (size_t)(row0 + 8) * N + col);
                    v[0] += r0.x; v[1] += r0.y; v[2] += r1.x; v[3] += r1.y;
                }
                *(float2*)(outF + (size_t)row0 * N + col)       = make_float2(v[0], v[1]);
                *(float2*)(outF + (size_t)(row0 + 8) * N + col) = make_float2(v[2], v[3]);
            }
        }
    }
}

// ====================================================================
// Tensorized flash attention (mma.sync bf16, fp32 softmax).
// CTA: 64 queries x (head, batch). 4 warps x m16. 64-key iterations.
// Q/K/V bf16 [TOK, DMODEL]; q pre-scaled by 0.125 in headln.
// Output: split bf16 (atH, atL).
// ====================================================================
#define FP 72   // smem pitch in halves (64 + 8)

__global__ __launch_bounds__(128) void flash_mma(
    const __nv_bfloat16* __restrict__ Qb,
    const __nv_bfloat16* __restrict__ Kb,
    const __nv_bfloat16* __restrict__ Vb,
    __nv_bfloat16* __restrict__ OH,
    __nv_bfloat16* __restrict__ OL)
{
    __shared__ __nv_bfloat16 Qs[64 * FP];
    __shared__ __nv_bfloat16 KVs[2][2][64 * FP];   // [stage][K=0/V=1]

    const int tid  = threadIdx.x;
    const int wid  = tid >> 5;
    const int lane = tid & 31;
    const int q0   = blockIdx.x * 64;
    const size_t hoff = (size_t)blockIdx.y * HDIM;
    const size_t boff = (size_t)blockIdx.z * SEQ * DMODEL;
    const __nv_bfloat16* Qg = Qb + boff + hoff;
    const __nv_bfloat16* Kg = Kb + boff + hoff;
    const __nv_bfloat16* Vg = Vb + boff + hoff;

    // ---- load Q tile, build resident A-fragments ----
    #pragma unroll
    for (int t = 0; t < 4; t++) {
        int idx = tid + t * 128;
        int row = idx >> 3, c8 = idx & 7;
        *(uint4*)&Qs[row * FP + c8 * 8] =
            *(const uint4*)(Qg + (size_t)(q0 + row) * DMODEL + c8 * 8);
    }
    __syncthreads();

    const uint32_t qsb = smem_u32(Qs);
    uint32_t qa[4][4];
    {
        const int ar = wid * 16 + (lane & 15);
        const int ac = (lane >> 4) * 8;
        #pragma unroll
        for (int c = 0; c < 4; c++)
            ldmx4(qa[c], qsb + (uint32_t)(ar * FP + c * 16 + ac) * 2);
    }

    float o[8][4];
    #pragma unroll
    for (int d = 0; d < 8; d++)
        #pragma unroll
        for (int e = 0; e < 4; e++) o[d][e] = 0.f;
    float m0 = -INFINITY, m1 = -INFINITY, l0 = 0.f, l1 = 0.f;

    auto load_kv = [&](int it, int s) {
        const int kb = it * 64;
        #pragma unroll
        for (int t = 0; t < 8; t++) {
            int idx   = tid + t * 128;
            int which = idx >> 9;
            int a     = idx & 511;
            int row   = a >> 3, c8 = a & 7;
            const __nv_bfloat16* g =
                (which ? Vg : Kg) + (size_t)(kb + row) * DMODEL + c8 * 8;
            cp16(smem_u32(&KVs[s][which][row * FP + c8 * 8]), g);
        }
        CP_COMMIT();
    };

    load_kv(0, 0);

    // fragment address offsets
    const int krow = (lane & 7) + ((lane >> 4) << 3);       // K ldmx4 row
    const int kcol = ((lane >> 3) & 1) * 8;                 // K ldmx4 col
    const int vrow = (lane & 7) + (((lane >> 3) & 1) << 3); // V ldmx4t row
    const int vcol = (lane >> 4) << 3;                      // V ldmx4t col

    for (int it = 0; it < SEQ / 64; it++) {
        const int s = it & 1;
        if (it + 1 < SEQ / 64) { load_kv(it + 1, s ^ 1); CP_WAIT1(); }
        else                   { CP_WAIT0(); }
        __syncthreads();

        // ---- S = Q @ K^T ----
        float sc[8][4];
        #pragma unroll
        for (int j = 0; j < 8; j++)
            #pragma unroll
            for (int e = 0; e < 4; e++) sc[j][e] = 0.f;

        const uint32_t kbase = smem_u32(&KVs[s][0][0]);
        #pragma unroll
        for (int c = 0; c < 4; c++) {
            #pragma unroll
            for (int j2 = 0; j2 < 4; j2++) {
                uint32_t r[4];
                ldmx4(r, kbase + (uint32_t)((16 * j2 + krow) * FP + c * 16 + kcol) * 2);
                mma16816(sc[2 * j2],     qa[c], r);
                mma16816(sc[2 * j2 + 1], qa[c], r + 2);
            }
        }

        // ---- online softmax (fp32) ----
        float rx0 = -INFINITY, rx1 = -INFINITY;
        #pragma unroll
        for (int j = 0; j < 8; j++) {
            rx0 = fmaxf(rx0, fmaxf(sc[j][0], sc[j][1]));
            rx1 = fmaxf(rx1, fmaxf(sc[j][2], sc[j][3]));
        }
        #pragma unroll
        for (int off = 1; off < 4; off <<= 1) {
            rx0 = fmaxf(rx0, __shfl_xor_sync(0xffffffffu, rx0, off));
            rx1 = fmaxf(rx1, __shfl_xor_sync(0xffffffffu, rx1, off));
        }
        const float mn0 = fmaxf(m0, rx0), mn1 = fmaxf(m1, rx1);
        const float al0 = expf(m0 - mn0), al1 = expf(m1 - mn1);
        float rs0 = 0.f, rs1 = 0.f;
        #pragma unroll
        for (int j = 0; j < 8; j++) {
            sc[j][0] = expf(sc[j][0] - mn0);
            sc[j][1] = expf(sc[j][1] - mn0);
            sc[j][2] = expf(sc[j][2] - mn1);
            sc[j][3] = expf(sc[j][3] - mn1);
            rs0 += sc[j][0] + sc[j][1];
            rs1 += sc[j][2] + sc[j][3];
        }
        #pragma unroll
        for (int off = 1; off < 4; off <<= 1) {
            rs0 += __shfl_xor_sync(0xffffffffu, rs0, off);
            rs1 += __shfl_xor_sync(0xffffffffu, rs1, off);
        }
        l0 = l0 * al0 + rs0; m0 = mn0;
        l1 = l1 * al1 + rs1; m1 = mn1;
        #pragma unroll
        for (int d = 0; d < 8; d++) {
            o[d][0] *= al0; o[d][1] *= al0;
            o[d][2] *= al1; o[d][3] *= al1;
        }

        // ---- P fragments (in-register S -> bf16 A-frags) ----
        uint32_t pa[4][4];
        #pragma unroll
        for (int kc = 0; kc < 4; kc++) {
            pa[kc][0] = packbf2(sc[2 * kc][0],     sc[2 * kc][1]);
            pa[kc][1] = packbf2(sc[2 * kc][2],     sc[2 * kc][3]);
            pa[kc][2] = packbf2(sc[2 * kc + 1][0], sc[2 * kc + 1][1]);
            pa[kc][3] = packbf2(sc[2 * kc + 1][2], sc[2 * kc + 1][3]);
        }

        // ---- O += P @ V ----
        const uint32_t vbase = smem_u32(&KVs[s][1][0]);
        #pragma unroll
        for (int kc = 0; kc < 4; kc++) {
            #pragma unroll
            for (int d2 = 0; d2 < 4; d2++) {
                uint32_t r[4];
                ldmx4t(r, vbase + (uint32_t)((kc * 16 + vrow) * FP + d2 * 16 + vcol) * 2);
                mma16816(o[2 * d2],     pa[kc], r);
                mma16816(o[2 * d2 + 1], pa[kc], r + 2);
            }
        }
        __syncthreads();
    }

    // ---- finalize: /l, split bf16 store ----
    const float inv0 = 1.0f / l0, inv1 = 1.0f / l1;
    const int row0 = q0 + wid * 16 + (lane >> 2);
    const int coff = (lane & 3) * 2;
    __nv_bfloat16* OhB = OH + boff + hoff;
    __nv_bfloat16* OlB = OL + boff + hoff;
    #pragma unroll
    for (int d = 0; d < 8; d++) {
        __nv_bfloat162 h2, l2;
        split2(o[d][0] * inv0, o[d][1] * inv0, h2, l2);
        size_t off0 = (size_t)row0 * DMODEL + d * 8 + coff;
        *(__nv_bfloat162*)(OhB + off0) = h2;
        *(__nv_bfloat162*)(OlB + off0) = l2;
        split2(o[d][2] * inv1, o[d][3] * inv1, h2, l2);
        size_t off1 = (size_t)(row0 + 8) * DMODEL + d * 8 + coff;
        *(__nv_bfloat162*)(OhB + off1) = h2;
        *(__nv_bfloat162*)(OlB + off1) = l2;
    }
}

// ====================================================================
// kernel_launch
// ====================================================================
extern "C" void kernel_launch(void* const* d_in, const int* in_sizes, int n_in,
                              void* d_out, int out_size)
{
    const float* x        = (const float*)d_in[0];
    const float* Wq       = (const float*)d_in[1];
    const float* bq       = (const float*)d_in[2];
    const float* Wk       = (const float*)d_in[3];
    const float* bk       = (const float*)d_in[4];
    const float* Wv       = (const float*)d_in[5];
    const float* bv       = (const float*)d_in[6];
    const float* Wo       = (const float*)d_in[7];
    const float* bo       = (const float*)d_in[8];
    const float* qn_scale = (const float*)d_in[9];
    const float* qn_bias  = (const float*)d_in[10];
    const float* kn_scale = (const float*)d_in[11];
    const float* kn_bias  = (const float*)d_in[12];
    const float* W1       = (const float*)d_in[13];
    const float* b1       = (const float*)d_in[14];
    const float* W2       = (const float*)d_in[15];
    const float* b2       = (const float*)d_in[16];
    const float* n1_scale = (const float*)d_in[17];
    const float* n2_scale = (const float*)d_in[18];
    float* out = (float*)d_out;

    __nv_bfloat16 *hH, *hL, *atH, *atL, *h2H, *h2L, *fH, *fL, *qb, *kb, *vb;
    __nv_bfloat16 *WqH, *WqL, *WkH, *WkL, *WvH, *WvL, *WoH, *WoL, *W1H, *W1L, *W2H, *W2L;
    float *q, *k, *x2;
    cudaGetSymbolAddress((void**)&hH,  g_hH);  cudaGetSymbolAddress((void**)&hL,  g_hL);
    cudaGetSymbolAddress((void**)&q,   g_q);   cudaGetSymbolAddress((void**)&k,   g_k);
    cudaGetSymbolAddress((void**)&qb,  g_qb);  cudaGetSymbolAddress((void**)&kb,  g_kb);
    cudaGetSymbolAddress((void**)&vb,  g_vb);
    cudaGetSymbolAddress((void**)&atH, g_atH); cudaGetSymbolAddress((void**)&atL, g_atL);
    cudaGetSymbolAddress((void**)&x2,  g_x2);
    cudaGetSymbolAddress((void**)&h2H, g_h2H); cudaGetSymbolAddress((void**)&h2L, g_h2L);
    cudaGetSymbolAddress((void**)&fH,  g_fH);  cudaGetSymbolAddress((void**)&fL,  g_fL);
    cudaGetSymbolAddress((void**)&WqH, g_WqH); cudaGetSymbolAddress((void**)&WqL, g_WqL);
    cudaGetSymbolAddress((void**)&WkH, g_WkH); cudaGetSymbolAddress((void**)&WkL, g_WkL);
    cudaGetSymbolAddress((void**)&WvH, g_WvH); cudaGetSymbolAddress((void**)&WvL, g_WvL);
    cudaGetSymbolAddress((void**)&WoH, g_WoH); cudaGetSymbolAddress((void**)&WoL, g_WoL);
    cudaGetSymbolAddress((void**)&W1H, g_W1H); cudaGetSymbolAddress((void**)&W1L, g_W1L);
    cudaGetSymbolAddress((void**)&W2H, g_W2H); cudaGetSymbolAddress((void**)&W2L, g_W2L);

    cudaFuncSetAttribute(mma_gemm, cudaFuncAttributeMaxDynamicSharedMemorySize, GSMEM);

    const dim3 tb(32, 8);
    wsplit_t<<<dim3(DMODEL/32, DMODEL/32), tb>>>(Wq, WqH, WqL, DMODEL, DMODEL);
    wsplit_t<<<dim3(DMODEL/32, DMODEL/32), tb>>>(Wk, WkH, WkL, DMODEL, DMODEL);
    wsplit_t<<<dim3(DMODEL/32, DMODEL/32), tb>>>(Wv, WvH, WvL, DMODEL, DMODEL);
    wsplit_t<<<dim3(DMODEL/32, DMODEL/32), tb>>>(Wo, WoH, WoL, DMODEL, DMODEL);
    wsplit_t<<<dim3(FDIM/32,   DMODEL/32), tb>>>(W1, W1H, W1L, DMODEL, FDIM);
    wsplit_t<<<dim3(DMODEL/32, FDIM/32),   tb>>>(W2, W2H, W2L, FDIM,   DMODEL);

    const dim3 gD(DMODEL / 128, TOK / 128);   // 8 x 64
    const dim3 gF(FDIM   / 128, TOK / 128);   // 32 x 64

    // 1. h = rms(x) * n1_scale  (split)
    rmsnorm_split_k<<<TOK, 256>>>(x, n1_scale, hH, hL);

    // 2. q/k (fp32 out), v (bf16 out)
    mma_gemm<<<gD, 256, GSMEM>>>(hH, hL, WqH, WqL, bq, nullptr, q, nullptr, nullptr,
                                 TOK, DMODEL, DMODEL, EPI_NONE);
    mma_gemm<<<gD, 256, GSMEM>>>(hH, hL, WkH, WkL, bk, nullptr, k, nullptr, nullptr,
                                 TOK, DMODEL, DMODEL, EPI_NONE);
    mma_gemm<<<gD, 256, GSMEM>>>(hH, hL, WvH, WvL, bv, nullptr, nullptr, vb, nullptr,
                                 TOK, DMODEL, DMODEL, EPI_BF16);

    // 3. per-head LayerNorm -> bf16 (q folded with softmax scale 1/8)
    headln_bf16<<<TOK * NHEAD / 8, 256>>>(q, qb, qn_scale, qn_bias, 0.125f);
    headln_bf16<<<TOK * NHEAD / 8, 256>>>(k, kb, kn_scale, kn_bias, 1.0f);

    // 4. tensorized attention -> split bf16
    flash_mma<<<dim3(SEQ / 64, NHEAD, BATCH), 128>>>(qb, kb, vb, atH, atL);

    // 5. x2 = x + attn @ Wo + bo
    mma_gemm<<<gD, 256, GSMEM>>>(atH, atL, WoH, WoL, bo, x, x2, nullptr, nullptr,
                                 TOK, DMODEL, DMODEL, EPI_RES);

    // 6. h2 = rms(x2) * n2_scale  (split)
    rmsnorm_split_k<<<TOK, 256>>>(x2, n2_scale, h2H, h2L);

    // 7. ffn = gelu(h2 @ W1 + b1)  (split bf16 out)
    mma_gemm<<<gF, 256, GSMEM>>>(h2H, h2L, W1H, W1L, b1, nullptr, nullptr, fH, fL,
                                 TOK, FDIM, DMODEL, EPI_GELU);

    // 8. out = x2 + ffn @ W2 + b2
    mma_gemm<<<gD, 256, GSMEM>>>(fH, fL, W2H, W2L, b2, x2, out, nullptr, nullptr,
                                 TOK, DMODEL, FDIM, EPI_RES);
}

// round 5
// speedup vs baseline: 3.0566x; 1.0829x over previous
#include <cuda_runtime.h>
#include <cuda_bf16.h>
#include <math.h>
#include <stdint.h>

// ---------------- problem constants ----------------
#define TOK    8192          // 4 * 2048 tokens
#define DMODEL 1024
#define NHEAD  16
#define HDIM   64
#define FDIM   4096
#define SEQ    2048
#define BATCH  4
#define EPS    1e-5f

// ---------------- scratch (device globals; no runtime alloc) --------------
__device__ __align__(256) __nv_bfloat16 g_hH  [(size_t)TOK * DMODEL];
__device__ __align__(256) __nv_bfloat16 g_hL  [(size_t)TOK * DMODEL];
__device__ __align__(256) float         g_q   [(size_t)TOK * DMODEL];
__device__ __align__(256) float         g_k   [(size_t)TOK * DMODEL];
__device__ __align__(256) __nv_bfloat16 g_qb  [(size_t)TOK * DMODEL];
__device__ __align__(256) __nv_bfloat16 g_kb  [(size_t)TOK * DMODEL];
__device__ __align__(256) __nv_bfloat16 g_vb  [(size_t)TOK * DMODEL];
__device__ __align__(256) __nv_bfloat16 g_atH [(size_t)TOK * DMODEL];
__device__ __align__(256) __nv_bfloat16 g_atL [(size_t)TOK * DMODEL];
__device__ __align__(256) float         g_x2  [(size_t)TOK * DMODEL];
__device__ __align__(256) __nv_bfloat16 g_h2H [(size_t)TOK * DMODEL];
__device__ __align__(256) __nv_bfloat16 g_h2L [(size_t)TOK * DMODEL];
__device__ __align__(256) __nv_bfloat16 g_fH  [(size_t)TOK * FDIM];
__device__ __align__(256) __nv_bfloat16 g_fL  [(size_t)TOK * FDIM];
// transposed+split weights: Wt[N,K]
__device__ __align__(256) __nv_bfloat16 g_WqH [(size_t)DMODEL * DMODEL];
__device__ __align__(256) __nv_bfloat16 g_WqL [(size_t)DMODEL * DMODEL];
__device__ __align__(256) __nv_bfloat16 g_WkH [(size_t)DMODEL * DMODEL];
__device__ __align__(256) __nv_bfloat16 g_WkL [(size_t)DMODEL * DMODEL];
__device__ __align__(256) __nv_bfloat16 g_WvH [(size_t)DMODEL * DMODEL];
__device__ __align__(256) __nv_bfloat16 g_WvL [(size_t)DMODEL * DMODEL];
__device__ __align__(256) __nv_bfloat16 g_WoH [(size_t)DMODEL * DMODEL];
__device__ __align__(256) __nv_bfloat16 g_WoL [(size_t)DMODEL * DMODEL];
__device__ __align__(256) __nv_bfloat16 g_W1H [(size_t)FDIM * DMODEL];
__device__ __align__(256) __nv_bfloat16 g_W1L [(size_t)FDIM * DMODEL];
__device__ __align__(256) __nv_bfloat16 g_W2H [(size_t)DMODEL * FDIM];
__device__ __align__(256) __nv_bfloat16 g_W2L [(size_t)DMODEL * FDIM];

// =================== PTX helpers (sm_80-compatible only) ===================
__device__ __forceinline__ uint32_t smem_u32(const void* p) {
    uint32_t a;
    asm("{ .reg .u64 t; cvta.to.shared.u64 t, %1; cvt.u32.u64 %0, t; }"
        : "=r"(a) : "l"(p));
    return a;
}
__device__ __forceinline__ void cp16(uint32_t dst, const void* src) {
    asm volatile("cp.async.cg.shared.global [%0], [%1], 16;"
                 :: "r"(dst), "l"(src));
}
#define CP_COMMIT() asm volatile("cp.async.commit_group;" ::: "memory")
#define CP_WAIT2()  asm volatile("cp.async.wait_group 2;" ::: "memory")
#define CP_WAIT1()  asm volatile("cp.async.wait_group 1;" ::: "memory")
#define CP_WAIT0()  asm volatile("cp.async.wait_group 0;" ::: "memory")

__device__ __forceinline__ void ldmx4(uint32_t* r, uint32_t addr) {
    asm volatile("ldmatrix.sync.aligned.m8n8.x4.shared.b16 {%0,%1,%2,%3}, [%4];"
                 : "=r"(r[0]), "=r"(r[1]), "=r"(r[2]), "=r"(r[3]) : "r"(addr));
}
__device__ __forceinline__ void ldmx4t(uint32_t* r, uint32_t addr) {
    asm volatile("ldmatrix.sync.aligned.m8n8.x4.trans.shared.b16 {%0,%1,%2,%3}, [%4];"
                 : "=r"(r[0]), "=r"(r[1]), "=r"(r[2]), "=r"(r[3]) : "r"(addr));
}
__device__ __forceinline__ void ldmx2(uint32_t* r, uint32_t addr) {
    asm volatile("ldmatrix.sync.aligned.m8n8.x2.shared.b16 {%0,%1}, [%2];"
                 : "=r"(r[0]), "=r"(r[1]) : "r"(addr));
}
__device__ __forceinline__ void mma16816(float* c, const uint32_t* a,
                                         const uint32_t* b) {
    asm volatile(
        "mma.sync.aligned.m16n8k16.row.col.f32.bf16.bf16.f32 "
        "{%0,%1,%2,%3}, {%4,%5,%6,%7}, {%8,%9}, {%0,%1,%2,%3};"
        : "+f"(c[0]), "+f"(c[1]), "+f"(c[2]), "+f"(c[3])
        : "r"(a[0]), "r"(a[1]), "r"(a[2]), "r"(a[3]), "r"(b[0]), "r"(b[1]));
}

// =================== split helpers ===================
__device__ __forceinline__ void split2(float a, float b,
                                       __nv_bfloat162& hi, __nv_bfloat162& lo) {
    __nv_bfloat16 ha = __float2bfloat16(a), hb = __float2bfloat16(b);
    __nv_bfloat16 la = __float2bfloat16(a - __bfloat162float(ha));
    __nv_bfloat16 lb = __float2bfloat16(b - __bfloat162float(hb));
    hi = __halves2bfloat162(ha, hb);
    lo = __halves2bfloat162(la, lb);
}
__device__ __forceinline__ uint32_t packbf2(float lo, float hi) {
    __nv_bfloat162 t = __halves2bfloat162(__float2bfloat16(lo), __float2bfloat16(hi));
    return *(uint32_t*)&t;
}

// ====================================================================
// Weight transpose + split:  W[K,N] fp32  ->  Th/Tl[N,K] bf16
// ====================================================================
__global__ __launch_bounds__(256) void wsplit_t(const float* __restrict__ W,
                                                __nv_bfloat16* __restrict__ Th,
                                                __nv_bfloat16* __restrict__ Tl,
                                                int K, int N)
{
    __shared__ float t[32][33];
    const int k0 = blockIdx.y * 32, n0 = blockIdx.x * 32;
    const int tx = threadIdx.x, ty = threadIdx.y;   // (32, 8)
    #pragma unroll
    for (int j = 0; j < 4; j++) {
        int r = ty + j * 8;
        t[r][tx] = W[(size_t)(k0 + r) * N + n0 + tx];
    }
    __syncthreads();
    #pragma unroll
    for (int j = 0; j < 4; j++) {
        int r = ty + j * 8;
        float v = t[tx][r];
        __nv_bfloat16 h = __float2bfloat16(v);
        __nv_bfloat16 l = __float2bfloat16(v - __bfloat162float(h));
        size_t o = (size_t)(n0 + r) * K + k0 + tx;
        Th[o] = h; Tl[o] = l;
    }
}

// ====================================================================
// RMSNorm over D=1024 -> split bf16 outputs
// ====================================================================
__global__ __launch_bounds__(256) void rmsnorm_split_k(const float* __restrict__ x,
                                                       const float* __restrict__ scale,
                                                       __nv_bfloat16* __restrict__ yH,
                                                       __nv_bfloat16* __restrict__ yL)
{
    const int row = blockIdx.x;
    const int t   = threadIdx.x;
    const float4 v = ((const float4*)(x + (size_t)row * DMODEL))[t];
    float ss = v.x*v.x + v.y*v.y + v.z*v.z + v.w*v.w;
    #pragma unroll
    for (int off = 16; off; off >>= 1) ss += __shfl_xor_sync(0xffffffffu, ss, off);
    __shared__ float red[8];
    if ((t & 31) == 0) red[t >> 5] = ss;
    __syncthreads();
    float tot = 0.f;
    #pragma unroll
    for (int w = 0; w < 8; w++) tot += red[w];
    const float r = rsqrtf(tot * (1.0f / DMODEL) + EPS);
    const float4 s4 = ((const float4*)scale)[t];
    float o0 = v.x*r*s4.x, o1 = v.y*r*s4.y, o2 = v.z*r*s4.z, o3 = v.w*r*s4.w;
    __nv_bfloat162 h0, l0, h1, l1;
    split2(o0, o1, h0, l0);
    split2(o2, o3, h1, l1);
    const size_t base = (size_t)row * DMODEL + t * 4;
    *(__nv_bfloat162*)(yH + base)     = h0;
    *(__nv_bfloat162*)(yH + base + 2) = h1;
    *(__nv_bfloat162*)(yL + base)     = l0;
    *(__nv_bfloat162*)(yL + base + 2) = l1;
}

// ====================================================================
// Per-head LayerNorm over HD=64, fp32 in -> bf16 out (optional scale mul)
// ====================================================================
__global__ __launch_bounds__(256) void headln_bf16(const float* __restrict__ src,
                                                   __nv_bfloat16* __restrict__ dst,
                                                   const float* __restrict__ scale,
                                                   const float* __restrict__ bias,
                                                   float mul)
{
    const int row  = blockIdx.x * 8 + (threadIdx.x >> 5);
    const int lane = threadIdx.x & 31;
    const float* p = src + (size_t)row * HDIM;
    float a = p[lane];
    float b = p[lane + 32];
    float mu = a + b;
    #pragma unroll
    for (int off = 16; off; off >>= 1) mu += __shfl_xor_sync(0xffffffffu, mu, off);
    mu *= (1.0f / 64.0f);
    float da = a - mu, db = b - mu;
    float var = da*da + db*db;
    #pragma unroll
    for (int off = 16; off; off >>= 1) var += __shfl_xor_sync(0xffffffffu, var, off);
    var *= (1.0f / 64.0f);
    const float r = rsqrtf(var + EPS);
    float ra = (da * r * scale[lane]      + bias[lane])      * mul;
    float rb = (db * r * scale[lane + 32] + bias[lane + 32]) * mul;
    dst[(size_t)row * HDIM + lane]      = __float2bfloat16(ra);
    dst[(size_t)row * HDIM + lane + 32] = __float2bfloat16(rb);
}

// ====================================================================
// split-bf16 mma.sync GEMM: D[M,N] = A[M,K] @ Wt[N,K]^T + bias (+epi)
// CTA 128x256, BK=32, 8 warps (2x4), warp tile 64x64, 3-stage cp.async.
// 3 HMMA passes (hh, hl, lh) into fp32 accumulators.
// ====================================================================
#define EPI_NONE 0
#define EPI_GELU 1
#define EPI_RES  2
#define EPI_BF16 3

#define BM 128
#define BN 256
#define GPITCH 40                       // halves per smem row (32 + 8 pad)
#define A_ARR  (BM * GPITCH)            // halves
#define B_ARR  (BN * GPITCH)            // halves
#define STG_H  (2 * A_ARR + 2 * B_ARR)  // halves per stage
#define GSMEM  (3 * STG_H * 2)          // bytes, 3 stages = 184320

__global__ __launch_bounds__(256, 1) void mma_gemm(
    const __nv_bfloat16* __restrict__ Ah, const __nv_bfloat16* __restrict__ Al,
    const __nv_bfloat16* __restrict__ Bh, const __nv_bfloat16* __restrict__ Bl,
    const float* __restrict__ bias, const float* __restrict__ res,
    float* __restrict__ outF,
    __nv_bfloat16* __restrict__ outH, __nv_bfloat16* __restrict__ outL,
    int M, int N, int K, int epi)
{
    extern __shared__ __nv_bfloat16 smh[];
    const uint32_t sb = smem_u32(smh);
    const int tid  = threadIdx.x;
    const int wid  = tid >> 5;
    const int lane = tid & 31;
    const int wm   = wid >> 2;           // 0..1 -> 64 rows each
    const int wn   = wid & 3;            // 0..3 -> 64 cols each
    const int bm   = blockIdx.y * BM;
    const int bn   = blockIdx.x * BN;

    auto load_chunk = [&](int c, int s) {
        const int k0 = c << 5;
        const uint32_t base = sb + (uint32_t)s * STG_H * 2;
        #pragma unroll
        for (int j = 0; j < 12; j++) {
            int idx = tid + j * 256;     // 0..3071 16B-chunks
            const __nv_bfloat16* g;
            uint32_t dst;
            if (idx < 1024) {            // A: 2 arrays x 128 rows x 4 chunks
                int arr = idx >> 9;
                int a   = idx & 511;
                int row = a >> 2, ch = a & 3;
                g   = (arr ? Al : Ah) + (size_t)(bm + row) * K + k0 + ch * 8;
                dst = base + ((uint32_t)arr * A_ARR + row * GPITCH + ch * 8) * 2;
            } else {                     // B: 2 arrays x 256 rows x 4 chunks
                int idx2 = idx - 1024;
                int arr  = idx2 >> 10;
                int a    = idx2 & 1023;
                int row  = a >> 2, ch = a & 3;
                g   = (arr ? Bl : Bh) + (size_t)(bn + row) * K + k0 + ch * 8;
                dst = base + (2 * A_ARR + (uint32_t)arr * B_ARR
                              + row * GPITCH + ch * 8) * 2;
            }
            cp16(dst, g);
        }
        CP_COMMIT();
    };

    float acc[4][8][4];
    #pragma unroll
    for (int m = 0; m < 4; m++)
        #pragma unroll
        for (int n = 0; n < 8; n++)
            #pragma unroll
            for (int e = 0; e < 4; e++) acc[m][n][e] = 0.f;

    const int nch = K >> 5;
    load_chunk(0, 0);
    load_chunk(1, 1);
    load_chunk(2, 2);

    const int l16 = lane & 15;
    const int a_r = l16;
    const int a_c = (lane >> 4) * 8;
    const int b_r = l16 & 7;
    const int b_c = (l16 >> 3) * 8;

    int s = 0;
    for (int i = 0; i < nch; i++) {
        if (i + 3 <= nch - 1)      { CP_WAIT2(); }
        else if (i + 2 <= nch - 1) { CP_WAIT1(); }
        else                       { CP_WAIT0(); }
        __syncthreads();
        const uint32_t ab = sb + (uint32_t)s * STG_H * 2;
        const uint32_t bb = ab + 2 * A_ARR * 2;

        #pragma unroll
        for (int kk = 0; kk < 2; kk++) {
            const int kh = kk * 16;
            uint32_t ah[4][4], al[4][4];
            #pragma unroll
            for (int m = 0; m < 4; m++) {
                uint32_t addr = ab +
                    (uint32_t)((wm * 64 + m * 16 + a_r) * GPITCH + kh + a_c) * 2;
                ldmx4(ah[m], addr);
                ldmx4(al[m], addr + A_ARR * 2);
            }
            #pragma unroll
            for (int half = 0; half < 2; half++) {
                uint32_t bh[4][2], bl[4][2];
                #pragma unroll
                for (int n4 = 0; n4 < 4; n4++) {
                    int n = half * 4 + n4;
                    uint32_t addr = bb +
                        (uint32_t)((wn * 64 + n * 8 + b_r) * GPITCH + kh + b_c) * 2;
                    ldmx2(bh[n4], addr);
                    ldmx2(bl[n4], addr + B_ARR * 2);
                }
                #pragma unroll
                for (int m = 0; m < 4; m++)
                    #pragma unroll
                    for (int n4 = 0; n4 < 4; n4++) {
                        float* a4 = acc[m][half * 4 + n4];
                        mma16816(a4, ah[m], bh[n4]);
                        mma16816(a4, ah[m], bl[n4]);
                        mma16816(a4, al[m], bh[n4]);
                    }
            }
        }
        __syncthreads();
        if (i + 3 < nch) load_chunk(i + 3, s);
        s = (s == 2) ? 0 : s + 1;
    }

    // -------- epilogue ----------
    const int g  = lane >> 2;
    const int t4 = lane & 3;
    #pragma unroll
    for (int n = 0; n < 8; n++) {
        const int col = bn + wn * 64 + n * 8 + t4 * 2;
        const float b0 = __ldg(&bias[col]);
        const float b1 = __ldg(&bias[col + 1]);
        #pragma unroll
        for (int m = 0; m < 4; m++) {
            const int row0 = bm + wm * 64 + m * 16 + g;
            float v[4] = { acc[m][n][0] + b0, acc[m][n][1] + b1,
                           acc[m][n][2] + b0, acc[m][n][3] + b1 };
            if (epi == EPI_GELU) {
                #pragma unroll
                for (int e = 0; e < 4; e++) {
                    float u = v[e];
                    v[e] = 0.5f * u * (1.0f + erff(u * 0.70710678118654752f));
                }
                __nv_bfloat162 h2, l2;
                split2(v[0], v[1], h2, l2);
                *(__nv_bfloat162*)(outH + (size_t)row0 * N + col) = h2;
                *(__nv_bfloat162*)(outL + (size_t)row0 * N + col) = l2;
                split2(v[2], v[3], h2, l2);
                *(__nv_bfloat162*)(outH + (size_t)(row0 + 8) * N + col) = h2;
                *(__nv_bfloat162*)(outL + (size_t)(row0 + 8) * N + col) = l2;
            } else if (epi == EPI_BF16) {
                *(uint32_t*)(outH + (size_t)row0 * N + col)       = packbf2(v[0], v[1]);
                *(uint32_t*)(outH + (size_t)(row0 + 8) * N + col) = packbf2(v[2], v[3]);
            } else {
                if (epi == EPI_RES) {
                    float2 r0 = *(const float2*)(res + (size_t)row0 * N + col);
                    float2 r1 = *(const float2*)(res + (size_t)(row0 + 8) * N + col);
                    v[0] += r0.x; v[1] += r0.y; v[2] += r1.x; v[3] += r1.y;
                }
                *(float2*)(outF + (size_t)row0 * N + col)       = make_float2(v[0], v[1]);
                *(float2*)(outF + (size_t)(row0 + 8) * N + col) = make_float2(v[2], v[3]);
            }
        }
    }
}

// ====================================================================
// Tensorized flash attention (mma.sync bf16, fp32 softmax).
// ====================================================================
#define FP 72   // smem pitch in halves (64 + 8)

__global__ __launch_bounds__(128) void flash_mma(
    const __nv_bfloat16* __restrict__ Qb,
    const __nv_bfloat16* __restrict__ Kb,
    const __nv_bfloat16* __restrict__ Vb,
    __nv_bfloat16* __restrict__ OH,
    __nv_bfloat16* __restrict__ OL)
{
    __shared__ __nv_bfloat16 Qs[64 * FP];
    __shared__ __nv_bfloat16 KVs[2][2][64 * FP];   // [stage][K=0/V=1]

    const int tid  = threadIdx.x;
    const int wid  = tid >> 5;
    const int lane = tid & 31;
    const int q0   = blockIdx.x * 64;
    const size_t hoff = (size_t)blockIdx.y * HDIM;
    const size_t boff = (size_t)blockIdx.z * SEQ * DMODEL;
    const __nv_bfloat16* Qg = Qb + boff + hoff;
    const __nv_bfloat16* Kg = Kb + boff + hoff;
    const __nv_bfloat16* Vg = Vb + boff + hoff;

    #pragma unroll
    for (int t = 0; t < 4; t++) {
        int idx = tid + t * 128;
        int row = idx >> 3, c8 = idx & 7;
        *(uint4*)&Qs[row * FP + c8 * 8] =
            *(const uint4*)(Qg + (size_t)(q0 + row) * DMODEL + c8 * 8);
    }
    __syncthreads();

    const uint32_t qsb = smem_u32(Qs);
    uint32_t qa[4][4];
    {
        const int ar = wid * 16 + (lane & 15);
        const int ac = (lane >> 4) * 8;
        #pragma unroll
        for (int c = 0; c < 4; c++)
            ldmx4(qa[c], qsb + (uint32_t)(ar * FP + c * 16 + ac) * 2);
    }

    float o[8][4];
    #pragma unroll
    for (int d = 0; d < 8; d++)
        #pragma unroll
        for (int e = 0; e < 4; e++) o[d][e] = 0.f;
    float m0 = -INFINITY, m1 = -INFINITY, l0 = 0.f, l1 = 0.f;

    auto load_kv = [&](int it, int s) {
        const int kb = it * 64;
        #pragma unroll
        for (int t = 0; t < 8; t++) {
            int idx   = tid + t * 128;
            int which = idx >> 9;
            int a     = idx & 511;
            int row   = a >> 3, c8 = a & 7;
            const __nv_bfloat16* g =
                (which ? Vg : Kg) + (size_t)(kb + row) * DMODEL + c8 * 8;
            cp16(smem_u32(&KVs[s][which][row * FP + c8 * 8]), g);
        }
        CP_COMMIT();
    };

    load_kv(0, 0);

    const int krow = (lane & 7) + ((lane >> 4) << 3);
    const int kcol = ((lane >> 3) & 1) * 8;
    const int vrow = (lane & 7) + (((lane >> 3) & 1) << 3);
    const int vcol = (lane >> 4) << 3;

    for (int it = 0; it < SEQ / 64; it++) {
        const int s = it & 1;
        if (it + 1 < SEQ / 64) { load_kv(it + 1, s ^ 1); CP_WAIT1(); }
        else                   { CP_WAIT0(); }
        __syncthreads();

        float sc[8][4];
        #pragma unroll
        for (int j = 0; j < 8; j++)
            #pragma unroll
            for (int e = 0; e < 4; e++) sc[j][e] = 0.f;

        const uint32_t kbase = smem_u32(&KVs[s][0][0]);
        #pragma unroll
        for (int c = 0; c < 4; c++) {
            #pragma unroll
            for (int j2 = 0; j2 < 4; j2++) {
                uint32_t r[4];
                ldmx4(r, kbase + (uint32_t)((16 * j2 + krow) * FP + c * 16 + kcol) * 2);
                mma16816(sc[2 * j2],     qa[c], r);
                mma16816(sc[2 * j2 + 1], qa[c], r + 2);
            }
        }

        float rx0 = -INFINITY, rx1 = -INFINITY;
        #pragma unroll
        for (int j = 0; j < 8; j++) {
            rx0 = fmaxf(rx0, fmaxf(sc[j][0], sc[j][1]));
            rx1 = fmaxf(rx1, fmaxf(sc[j][2], sc[j][3]));
        }
        #pragma unroll
        for (int off = 1; off < 4; off <<= 1) {
            rx0 = fmaxf(rx0, __shfl_xor_sync(0xffffffffu, rx0, off));
            rx1 = fmaxf(rx1, __shfl_xor_sync(0xffffffffu, rx1, off));
        }
        const float mn0 = fmaxf(m0, rx0), mn1 = fmaxf(m1, rx1);
        const float al0 = expf(m0 - mn0), al1 = expf(m1 - mn1);
        float rs0 = 0.f, rs1 = 0.f;
        #pragma unroll
        for (int j = 0; j < 8; j++) {
            sc[j][0] = expf(sc[j][0] - mn0);
            sc[j][1] = expf(sc[j][1] - mn0);
            sc[j][2] = expf(sc[j][2] - mn1);
            sc[j][3] = expf(sc[j][3] - mn1);
            rs0 += sc[j][0] + sc[j][1];
            rs1 += sc[j][2] + sc[j][3];
        }
        #pragma unroll
        for (int off = 1; off < 4; off <<= 1) {
            rs0 += __shfl_xor_sync(0xffffffffu, rs0, off);
            rs1 += __shfl_xor_sync(0xffffffffu, rs1, off);
        }
        l0 = l0 * al0 + rs0; m0 = mn0;
        l1 = l1 * al1 + rs1; m1 = mn1;
        #pragma unroll
        for (int d = 0; d < 8; d++) {
            o[d][0] *= al0; o[d][1] *= al0;
            o[d][2] *= al1; o[d][3] *= al1;
        }

        uint32_t pa[4][4];
        #pragma unroll
        for (int kc = 0; kc < 4; kc++) {
            pa[kc][0] = packbf2(sc[2 * kc][0],     sc[2 * kc][1]);
            pa[kc][1] = packbf2(sc[2 * kc][2],     sc[2 * kc][3]);
            pa[kc][2] = packbf2(sc[2 * kc + 1][0], sc[2 * kc + 1][1]);
            pa[kc][3] = packbf2(sc[2 * kc + 1][2], sc[2 * kc + 1][3]);
        }

        const uint32_t vbase = smem_u32(&KVs[s][1][0]);
        #pragma unroll
        for (int kc = 0; kc < 4; kc++) {
            #pragma unroll
            for (int d2 = 0; d2 < 4; d2++) {
                uint32_t r[4];
                ldmx4t(r, vbase + (uint32_t)((kc * 16 + vrow) * FP + d2 * 16 + vcol) * 2);
                mma16816(o[2 * d2],     pa[kc], r);
                mma16816(o[2 * d2 + 1], pa[kc], r + 2);
            }
        }
        __syncthreads();
    }

    const float inv0 = 1.0f / l0, inv1 = 1.0f / l1;
    const int row0 = q0 + wid * 16 + (lane >> 2);
    const int coff = (lane & 3) * 2;
    __nv_bfloat16* OhB = OH + boff + hoff;
    __nv_bfloat16* OlB = OL + boff + hoff;
    #pragma unroll
    for (int d = 0; d < 8; d++) {
        __nv_bfloat162 h2, l2;
        split2(o[d][0] * inv0, o[d][1] * inv0, h2, l2);
        size_t off0 = (size_t)row0 * DMODEL + d * 8 + coff;
        *(__nv_bfloat162*)(OhB + off0) = h2;
        *(__nv_bfloat162*)(OlB + off0) = l2;
        split2(o[d][2] * inv1, o[d][3] * inv1, h2, l2);
        size_t off1 = (size_t)(row0 + 8) * DMODEL + d * 8 + coff;
        *(__nv_bfloat162*)(OhB + off1) = h2;
        *(__nv_bfloat162*)(OlB + off1) = l2;
    }
}

// ====================================================================
// kernel_launch
// ====================================================================
extern "C" void kernel_launch(void* const* d_in, const int* in_sizes, int n_in,
                              void* d_out, int out_size)
{
    const float* x        = (const float*)d_in[0];
    const float* Wq       = (const float*)d_in[1];
    const float* bq       = (const float*)d_in[2];
    const float* Wk       = (const float*)d_in[3];
    const float* bk       = (const float*)d_in[4];
    const float* Wv       = (const float*)d_in[5];
    const float* bv       = (const float*)d_in[6];
    const float* Wo       = (const float*)d_in[7];
    const float* bo       = (const float*)d_in[8];
    const float* qn_scale = (const float*)d_in[9];
    const float* qn_bias  = (const float*)d_in[10];
    const float* kn_scale = (const float*)d_in[11];
    const float* kn_bias  = (const float*)d_in[12];
    const float* W1       = (const float*)d_in[13];
    const float* b1       = (const float*)d_in[14];
    const float* W2       = (const float*)d_in[15];
    const float* b2       = (const float*)d_in[16];
    const float* n1_scale = (const float*)d_in[17];
    const float* n2_scale = (const float*)d_in[18];
    float* out = (float*)d_out;

    __nv_bfloat16 *hH, *hL, *atH, *atL, *h2H, *h2L, *fH, *fL, *qb, *kb, *vb;
    __nv_bfloat16 *WqH, *WqL, *WkH, *WkL, *WvH, *WvL, *WoH, *WoL, *W1H, *W1L, *W2H, *W2L;
    float *q, *k, *x2;
    cudaGetSymbolAddress((void**)&hH,  g_hH);  cudaGetSymbolAddress((void**)&hL,  g_hL);
    cudaGetSymbolAddress((void**)&q,   g_q);   cudaGetSymbolAddress((void**)&k,   g_k);
    cudaGetSymbolAddress((void**)&qb,  g_qb);  cudaGetSymbolAddress((void**)&kb,  g_kb);
    cudaGetSymbolAddress((void**)&vb,  g_vb);
    cudaGetSymbolAddress((void**)&atH, g_atH); cudaGetSymbolAddress((void**)&atL, g_atL);
    cudaGetSymbolAddress((void**)&x2,  g_x2);
    cudaGetSymbolAddress((void**)&h2H, g_h2H); cudaGetSymbolAddress((void**)&h2L, g_h2L);
    cudaGetSymbolAddress((void**)&fH,  g_fH);  cudaGetSymbolAddress((void**)&fL,  g_fL);
    cudaGetSymbolAddress((void**)&WqH, g_WqH); cudaGetSymbolAddress((void**)&WqL, g_WqL);
    cudaGetSymbolAddress((void**)&WkH, g_WkH); cudaGetSymbolAddress((void**)&WkL, g_WkL);
    cudaGetSymbolAddress((void**)&WvH, g_WvH); cudaGetSymbolAddress((void**)&WvL, g_WvL);
    cudaGetSymbolAddress((void**)&WoH, g_WoH); cudaGetSymbolAddress((void**)&WoL, g_WoL);
    cudaGetSymbolAddress((void**)&W1H, g_W1H); cudaGetSymbolAddress((void**)&W1L, g_W1L);
    cudaGetSymbolAddress((void**)&W2H, g_W2H); cudaGetSymbolAddress((void**)&W2L, g_W2L);

    cudaFuncSetAttribute(mma_gemm, cudaFuncAttributeMaxDynamicSharedMemorySize, GSMEM);

    const dim3 tb(32, 8);
    const dim3 gD(DMODEL / BN, TOK / BM);     // 4 x 64
    const dim3 gF(FDIM   / BN, TOK / BM);     // 16 x 64

    // Launch order arranged so the 6th launch (ncu -s 5 -c 1) is mma_gemm.
    wsplit_t<<<dim3(DMODEL/32, DMODEL/32), tb>>>(Wq, WqH, WqL, DMODEL, DMODEL); // 1
    rmsnorm_split_k<<<TOK, 256>>>(x, n1_scale, hH, hL);                         // 2
    wsplit_t<<<dim3(DMODEL/32, DMODEL/32), tb>>>(Wk, WkH, WkL, DMODEL, DMODEL); // 3
    wsplit_t<<<dim3(DMODEL/32, DMODEL/32), tb>>>(Wv, WvH, WvL, DMODEL, DMODEL); // 4
    wsplit_t<<<dim3(DMODEL/32, DMODEL/32), tb>>>(Wo, WoH, WoL, DMODEL, DMODEL); // 5
    mma_gemm<<<gD, 256, GSMEM>>>(hH, hL, WqH, WqL, bq, nullptr, q, nullptr,     // 6 (profiled)
                                 nullptr, TOK, DMODEL, DMODEL, EPI_NONE);
    wsplit_t<<<dim3(FDIM/32,   DMODEL/32), tb>>>(W1, W1H, W1L, DMODEL, FDIM);   // 7
    wsplit_t<<<dim3(DMODEL/32, FDIM/32),   tb>>>(W2, W2H, W2L, FDIM,   DMODEL); // 8
    mma_gemm<<<gD, 256, GSMEM>>>(hH, hL, WkH, WkL, bk, nullptr, k, nullptr, nullptr,
                                 TOK, DMODEL, DMODEL, EPI_NONE);
    mma_gemm<<<gD, 256, GSMEM>>>(hH, hL, WvH, WvL, bv, nullptr, nullptr, vb, nullptr,
                                 TOK, DMODEL, DMODEL, EPI_BF16);

    headln_bf16<<<TOK * NHEAD / 8, 256>>>(q, qb, qn_scale, qn_bias, 0.125f);
    headln_bf16<<<TOK * NHEAD / 8, 256>>>(k, kb, kn_scale, kn_bias, 1.0f);

    flash_mma<<<dim3(SEQ / 64, NHEAD, BATCH), 128>>>(qb, kb, vb, atH, atL);

    mma_gemm<<<gD, 256, GSMEM>>>(atH, atL, WoH, WoL, bo, x, x2, nullptr, nullptr,
                                 TOK, DMODEL, DMODEL, EPI_RES);

    rmsnorm_split_k<<<TOK, 256>>>(x2, n2_scale, h2H, h2L);

    mma_gemm<<<gF, 256, GSMEM>>>(h2H, h2L, W1H, W1L, b1, nullptr, nullptr, fH, fL,
                                 TOK, FDIM, DMODEL, EPI_GELU);

    mma_gemm<<<gD, 256, GSMEM>>>(fH, fL, W2H, W2L, b2, x2, out, nullptr, nullptr,
                                 TOK, DMODEL, FDIM, EPI_RES);
}

// round 6
// speedup vs baseline: 3.0603x; 1.0012x over previous
#include <cuda_runtime.h>
#include <cuda_bf16.h>
#include <math.h>
#include <stdint.h>

// ---------------- problem constants ----------------
#define TOK    8192          // 4 * 2048 tokens
#define DMODEL 1024
#define NHEAD  16
#define HDIM   64
#define FDIM   4096
#define SEQ    2048
#define BATCH  4
#define EPS    1e-5f

// ---------------- scratch (device globals; no runtime alloc) --------------
__device__ __align__(256) __nv_bfloat16 g_hH  [(size_t)TOK * DMODEL];
__device__ __align__(256) __nv_bfloat16 g_hL  [(size_t)TOK * DMODEL];
__device__ __align__(256) float         g_q   [(size_t)TOK * DMODEL];
__device__ __align__(256) float         g_k   [(size_t)TOK * DMODEL];
__device__ __align__(256) __nv_bfloat16 g_qb  [(size_t)TOK * DMODEL];
__device__ __align__(256) __nv_bfloat16 g_kb  [(size_t)TOK * DMODEL];
__device__ __align__(256) __nv_bfloat16 g_vb  [(size_t)TOK * DMODEL];
__device__ __align__(256) __nv_bfloat16 g_atH [(size_t)TOK * DMODEL];
__device__ __align__(256) __nv_bfloat16 g_atL [(size_t)TOK * DMODEL];
__device__ __align__(256) float         g_x2  [(size_t)TOK * DMODEL];
__device__ __align__(256) __nv_bfloat16 g_h2H [(size_t)TOK * DMODEL];
__device__ __align__(256) __nv_bfloat16 g_h2L [(size_t)TOK * DMODEL];
__device__ __align__(256) __nv_bfloat16 g_fH  [(size_t)TOK * FDIM];
__device__ __align__(256) __nv_bfloat16 g_fL  [(size_t)TOK * FDIM];
// transposed+split weights: Wt[N,K]
__device__ __align__(256) __nv_bfloat16 g_WqH [(size_t)DMODEL * DMODEL];
__device__ __align__(256) __nv_bfloat16 g_WqL [(size_t)DMODEL * DMODEL];
__device__ __align__(256) __nv_bfloat16 g_WkH [(size_t)DMODEL * DMODEL];
__device__ __align__(256) __nv_bfloat16 g_WkL [(size_t)DMODEL * DMODEL];
__device__ __align__(256) __nv_bfloat16 g_WvH [(size_t)DMODEL * DMODEL];
__device__ __align__(256) __nv_bfloat16 g_WvL [(size_t)DMODEL * DMODEL];
__device__ __align__(256) __nv_bfloat16 g_WoH [(size_t)DMODEL * DMODEL];
__device__ __align__(256) __nv_bfloat16 g_WoL [(size_t)DMODEL * DMODEL];
__device__ __align__(256) __nv_bfloat16 g_W1H [(size_t)FDIM * DMODEL];
__device__ __align__(256) __nv_bfloat16 g_W1L [(size_t)FDIM * DMODEL];
__device__ __align__(256) __nv_bfloat16 g_W2H [(size_t)DMODEL * FDIM];
__device__ __align__(256) __nv_bfloat16 g_W2L [(size_t)DMODEL * FDIM];

// =================== PTX helpers (sm_80-compatible only) ===================
__device__ __forceinline__ uint32_t smem_u32(const void* p) {
    uint32_t a;
    asm("{ .reg .u64 t; cvta.to.shared.u64 t, %1; cvt.u32.u64 %0, t; }"
        : "=r"(a) : "l"(p));
    return a;
}
__device__ __forceinline__ void cp16(uint32_t dst, const void* src) {
    asm volatile("cp.async.cg.shared.global [%0], [%1], 16;"
                 :: "r"(dst), "l"(src));
}
#define CP_COMMIT() asm volatile("cp.async.commit_group;" ::: "memory")
#define CP_WAIT2()  asm volatile("cp.async.wait_group 2;" ::: "memory")
#define CP_WAIT1()  asm volatile("cp.async.wait_group 1;" ::: "memory")
#define CP_WAIT0()  asm volatile("cp.async.wait_group 0;" ::: "memory")

__device__ __forceinline__ void ldmx4(uint32_t* r, uint32_t addr) {
    asm volatile("ldmatrix.sync.aligned.m8n8.x4.shared.b16 {%0,%1,%2,%3}, [%4];"
                 : "=r"(r[0]), "=r"(r[1]), "=r"(r[2]), "=r"(r[3]) : "r"(addr));
}
__device__ __forceinline__ void ldmx4t(uint32_t* r, uint32_t addr) {
    asm volatile("ldmatrix.sync.aligned.m8n8.x4.trans.shared.b16 {%0,%1,%2,%3}, [%4];"
                 : "=r"(r[0]), "=r"(r[1]), "=r"(r[2]), "=r"(r[3]) : "r"(addr));
}
__device__ __forceinline__ void ldmx2(uint32_t* r, uint32_t addr) {
    asm volatile("ldmatrix.sync.aligned.m8n8.x2.shared.b16 {%0,%1}, [%2];"
                 : "=r"(r[0]), "=r"(r[1]) : "r"(addr));
}
__device__ __forceinline__ void mma16816(float* c, const uint32_t* a,
                                         const uint32_t* b) {
    asm volatile(
        "mma.sync.aligned.m16n8k16.row.col.f32.bf16.bf16.f32 "
        "{%0,%1,%2,%3}, {%4,%5,%6,%7}, {%8,%9}, {%0,%1,%2,%3};"
        : "+f"(c[0]), "+f"(c[1]), "+f"(c[2]), "+f"(c[3])
        : "r"(a[0]), "r"(a[1]), "r"(a[2]), "r"(a[3]), "r"(b[0]), "r"(b[1]));
}

// =================== split helpers ===================
__device__ __forceinline__ void split2(float a, float b,
                                       __nv_bfloat162& hi, __nv_bfloat162& lo) {
    __nv_bfloat16 ha = __float2bfloat16(a), hb = __float2bfloat16(b);
    __nv_bfloat16 la = __float2bfloat16(a - __bfloat162float(ha));
    __nv_bfloat16 lb = __float2bfloat16(b - __bfloat162float(hb));
    hi = __halves2bfloat162(ha, hb);
    lo = __halves2bfloat162(la, lb);
}
__device__ __forceinline__ uint32_t packbf2(float lo, float hi) {
    __nv_bfloat162 t = __halves2bfloat162(__float2bfloat16(lo), __float2bfloat16(hi));
    return *(uint32_t*)&t;
}

// ====================================================================
// Weight transpose + split:  W[K,N] fp32  ->  Th/Tl[N,K] bf16
// ====================================================================
__global__ __launch_bounds__(256) void wsplit_t(const float* __restrict__ W,
                                                __nv_bfloat16* __restrict__ Th,
                                                __nv_bfloat16* __restrict__ Tl,
                                                int K, int N)
{
    __shared__ float t[32][33];
    const int k0 = blockIdx.y * 32, n0 = blockIdx.x * 32;
    const int tx = threadIdx.x, ty = threadIdx.y;   // (32, 8)
    #pragma unroll
    for (int j = 0; j < 4; j++) {
        int r = ty + j * 8;
        t[r][tx] = W[(size_t)(k0 + r) * N + n0 + tx];
    }
    __syncthreads();
    #pragma unroll
    for (int j = 0; j < 4; j++) {
        int r = ty + j * 8;
        float v = t[tx][r];
        __nv_bfloat16 h = __float2bfloat16(v);
        __nv_bfloat16 l = __float2bfloat16(v - __bfloat162float(h));
        size_t o = (size_t)(n0 + r) * K + k0 + tx;
        Th[o] = h; Tl[o] = l;
    }
}

// ====================================================================
// RMSNorm over D=1024 -> split bf16 outputs
// ====================================================================
__global__ __launch_bounds__(256) void rmsnorm_split_k(const float* __restrict__ x,
                                                       const float* __restrict__ scale,
                                                       __nv_bfloat16* __restrict__ yH,
                                                       __nv_bfloat16* __restrict__ yL)
{
    const int row = blockIdx.x;
    const int t   = threadIdx.x;
    const float4 v = ((const float4*)(x + (size_t)row * DMODEL))[t];
    float ss = v.x*v.x + v.y*v.y + v.z*v.z + v.w*v.w;
    #pragma unroll
    for (int off = 16; off; off >>= 1) ss += __shfl_xor_sync(0xffffffffu, ss, off);
    __shared__ float red[8];
    if ((t & 31) == 0) red[t >> 5] = ss;
    __syncthreads();
    float tot = 0.f;
    #pragma unroll
    for (int w = 0; w < 8; w++) tot += red[w];
    const float r = rsqrtf(tot * (1.0f / DMODEL) + EPS);
    const float4 s4 = ((const float4*)scale)[t];
    float o0 = v.x*r*s4.x, o1 = v.y*r*s4.y, o2 = v.z*r*s4.z, o3 = v.w*r*s4.w;
    __nv_bfloat162 h0, l0, h1, l1;
    split2(o0, o1, h0, l0);
    split2(o2, o3, h1, l1);
    const size_t base = (size_t)row * DMODEL + t * 4;
    *(__nv_bfloat162*)(yH + base)     = h0;
    *(__nv_bfloat162*)(yH + base + 2) = h1;
    *(__nv_bfloat162*)(yL + base)     = l0;
    *(__nv_bfloat162*)(yL + base + 2) = l1;
}

// ====================================================================
// Per-head LayerNorm over HD=64, fp32 in -> bf16 out (optional scale mul)
// ====================================================================
__global__ __launch_bounds__(256) void headln_bf16(const float* __restrict__ src,
                                                   __nv_bfloat16* __restrict__ dst,
                                                   const float* __restrict__ scale,
                                                   const float* __restrict__ bias,
                                                   float mul)
{
    const int row  = blockIdx.x * 8 + (threadIdx.x >> 5);
    const int lane = threadIdx.x & 31;
    const float* p = src + (size_t)row * HDIM;
    float a = p[lane];
    float b = p[lane + 32];
    float mu = a + b;
    #pragma unroll
    for (int off = 16; off; off >>= 1) mu += __shfl_xor_sync(0xffffffffu, mu, off);
    mu *= (1.0f / 64.0f);
    float da = a - mu, db = b - mu;
    float var = da*da + db*db;
    #pragma unroll
    for (int off = 16; off; off >>= 1) var += __shfl_xor_sync(0xffffffffu, var, off);
    var *= (1.0f / 64.0f);
    const float r = rsqrtf(var + EPS);
    float ra = (da * r * scale[lane]      + bias[lane])      * mul;
    float rb = (db * r * scale[lane + 32] + bias[lane + 32]) * mul;
    dst[(size_t)row * HDIM + lane]      = __float2bfloat16(ra);
    dst[(size_t)row * HDIM + lane + 32] = __float2bfloat16(rb);
}

// ====================================================================
// split-bf16 mma.sync GEMM: D[M,N] = A[M,K] @ Wt[N,K]^T + bias (+epi)
// CTA 128x256, BK=32, 8 warps (2x4), warp tile 64x64, 3-stage cp.async.
// Pass-major MMA schedule: 16 independent MMAs per pass (hh, hl, lh) so
// consecutive HMMAs never share an accumulator (RAW distance = 16).
// ====================================================================
#define EPI_NONE 0
#define EPI_GELU 1
#define EPI_RES  2
#define EPI_BF16 3

#define BM 128
#define BN 256
#define GPITCH 40                       // halves per smem row (32 + 8 pad)
#define A_ARR  (BM * GPITCH)            // halves
#define B_ARR  (BN * GPITCH)            // halves
#define STG_H  (2 * A_ARR + 2 * B_ARR)  // halves per stage
#define GSMEM  (3 * STG_H * 2)          // bytes, 3 stages = 184320

__global__ __launch_bounds__(256, 1) void mma_gemm(
    const __nv_bfloat16* __restrict__ Ah, const __nv_bfloat16* __restrict__ Al,
    const __nv_bfloat16* __restrict__ Bh, const __nv_bfloat16* __restrict__ Bl,
    const float* __restrict__ bias, const float* __restrict__ res,
    float* __restrict__ outF,
    __nv_bfloat16* __restrict__ outH, __nv_bfloat16* __restrict__ outL,
    int M, int N, int K, int epi)
{
    extern __shared__ __nv_bfloat16 smh[];
    const uint32_t sb = smem_u32(smh);
    const int tid  = threadIdx.x;
    const int wid  = tid >> 5;
    const int lane = tid & 31;
    const int wm   = wid >> 2;           // 0..1 -> 64 rows each
    const int wn   = wid & 3;            // 0..3 -> 64 cols each
    const int bm   = blockIdx.y * BM;
    const int bn   = blockIdx.x * BN;

    auto load_chunk = [&](int c, int s) {
        const int k0 = c << 5;
        const uint32_t base = sb + (uint32_t)s * STG_H * 2;
        #pragma unroll
        for (int j = 0; j < 12; j++) {
            int idx = tid + j * 256;     // 0..3071 16B-chunks
            const __nv_bfloat16* g;
            uint32_t dst;
            if (idx < 1024) {            // A: 2 arrays x 128 rows x 4 chunks
                int arr = idx >> 9;
                int a   = idx & 511;
                int row = a >> 2, ch = a & 3;
                g   = (arr ? Al : Ah) + (size_t)(bm + row) * K + k0 + ch * 8;
                dst = base + ((uint32_t)arr * A_ARR + row * GPITCH + ch * 8) * 2;
            } else {                     // B: 2 arrays x 256 rows x 4 chunks
                int idx2 = idx - 1024;
                int arr  = idx2 >> 10;
                int a    = idx2 & 1023;
                int row  = a >> 2, ch = a & 3;
                g   = (arr ? Bl : Bh) + (size_t)(bn + row) * K + k0 + ch * 8;
                dst = base + (2 * A_ARR + (uint32_t)arr * B_ARR
                              + row * GPITCH + ch * 8) * 2;
            }
            cp16(dst, g);
        }
        CP_COMMIT();
    };

    float acc[4][8][4];
    #pragma unroll
    for (int m = 0; m < 4; m++)
        #pragma unroll
        for (int n = 0; n < 8; n++)
            #pragma unroll
            for (int e = 0; e < 4; e++) acc[m][n][e] = 0.f;

    const int nch = K >> 5;
    load_chunk(0, 0);
    load_chunk(1, 1);
    load_chunk(2, 2);

    const int l16 = lane & 15;
    const int a_r = l16;
    const int a_c = (lane >> 4) * 8;
    const int b_r = l16 & 7;
    const int b_c = (l16 >> 3) * 8;

    int s = 0;
    for (int i = 0; i < nch; i++) {
        if (i + 3 <= nch - 1)      { CP_WAIT2(); }
        else if (i + 2 <= nch - 1) { CP_WAIT1(); }
        else                       { CP_WAIT0(); }
        __syncthreads();
        const uint32_t ab = sb + (uint32_t)s * STG_H * 2;
        const uint32_t bb = ab + 2 * A_ARR * 2;

        #pragma unroll
        for (int kk = 0; kk < 2; kk++) {
            const int kh = kk * 16;
            uint32_t ah[4][4], al[4][4];
            #pragma unroll
            for (int m = 0; m < 4; m++) {
                uint32_t addr = ab +
                    (uint32_t)((wm * 64 + m * 16 + a_r) * GPITCH + kh + a_c) * 2;
                ldmx4(ah[m], addr);
                ldmx4(al[m], addr + A_ARR * 2);
            }
            #pragma unroll
            for (int half = 0; half < 2; half++) {
                uint32_t bh[4][2], bl[4][2];
                #pragma unroll
                for (int n4 = 0; n4 < 4; n4++) {
                    int n = half * 4 + n4;
                    uint32_t addr = bb +
                        (uint32_t)((wn * 64 + n * 8 + b_r) * GPITCH + kh + b_c) * 2;
                    ldmx2(bh[n4], addr);
                    ldmx2(bl[n4], addr + B_ARR * 2);
                }
                // pass-major: 16 independent MMAs per pass, RAW distance 16
                #pragma unroll
                for (int m = 0; m < 4; m++)
                    #pragma unroll
                    for (int n4 = 0; n4 < 4; n4++)
                        mma16816(acc[m][half * 4 + n4], ah[m], bh[n4]);
                #pragma unroll
                for (int m = 0; m < 4; m++)
                    #pragma unroll
                    for (int n4 = 0; n4 < 4; n4++)
                        mma16816(acc[m][half * 4 + n4], ah[m], bl[n4]);
                #pragma unroll
                for (int m = 0; m < 4; m++)
                    #pragma unroll
                    for (int n4 = 0; n4 < 4; n4++)
                        mma16816(acc[m][half * 4 + n4], al[m], bh[n4]);
            }
        }
        __syncthreads();
        if (i + 3 < nch) load_chunk(i + 3, s);
        s = (s == 2) ? 0 : s + 1;
    }

    // -------- epilogue ----------
    const int g  = lane >> 2;
    const int t4 = lane & 3;
    #pragma unroll
    for (int n = 0; n < 8; n++) {
        const int col = bn + wn * 64 + n * 8 + t4 * 2;
        const float b0 = __ldg(&bias[col]);
        const float b1 = __ldg(&bias[col + 1]);
        #pragma unroll
        for (int m = 0; m < 4; m++) {
            const int row0 = bm + wm * 64 + m * 16 + g;
            float v[4] = { acc[m][n][0] + b0, acc[m][n][1] + b1,
                           acc[m][n][2] + b0, acc[m][n][3] + b1 };
            if (epi == EPI_GELU) {
                #pragma unroll
                for (int e = 0; e < 4; e++) {
                    float u = v[e];
                    v[e] = 0.5f * u * (1.0f + erff(u * 0.70710678118654752f));
                }
                __nv_bfloat162 h2, l2;
                split2(v[0], v[1], h2, l2);
                *(__nv_bfloat162*)(outH + (size_t)row0 * N + col) = h2;
                *(__nv_bfloat162*)(outL + (size_t)row0 * N + col) = l2;
                split2(v[2], v[3], h2, l2);
                *(__nv_bfloat162*)(outH + (size_t)(row0 + 8) * N + col) = h2;
                *(__nv_bfloat162*)(outL + (size_t)(row0 + 8) * N + col) = l2;
            } else if (epi == EPI_BF16) {
                *(uint32_t*)(outH + (size_t)row0 * N + col)       = packbf2(v[0], v[1]);
                *(uint32_t*)(outH + (size_t)(row0 + 8) * N + col) = packbf2(v[2], v[3]);
            } else {
                if (epi == EPI_RES) {
                    float2 r0 = *(const float2*)(res + (size_t)row0 * N + col);
                    float2 r1 = *(const float2*)(res + (size_t)(row0 + 8) * N + col);
                    v[0] += r0.x; v[1] += r0.y; v[2] += r1.x; v[3] += r1.y;
                }
                *(float2*)(outF + (size_t)row0 * N + col)       = make_float2(v[0], v[1]);
                *(float2*)(outF + (size_t)(row0 + 8) * N + col) = make_float2(v[2], v[3]);
            }
        }
    }
}

// ====================================================================
// Tensorized flash attention (mma.sync bf16, fp32 softmax).
// ====================================================================
#define FP 72   // smem pitch in halves (64 + 8)

__global__ __launch_bounds__(128) void flash_mma(
    const __nv_bfloat16* __restrict__ Qb,
    const __nv_bfloat16* __restrict__ Kb,
    const __nv_bfloat16* __restrict__ Vb,
    __nv_bfloat16* __restrict__ OH,
    __nv_bfloat16* __restrict__ OL)
{
    __shared__ __nv_bfloat16 Qs[64 * FP];
    __shared__ __nv_bfloat16 KVs[2][2][64 * FP];   // [stage][K=0/V=1]

    const int tid  = threadIdx.x;
    const int wid  = tid >> 5;
    const int lane = tid & 31;
    const int q0   = blockIdx.x * 64;
    const size_t hoff = (size_t)blockIdx.y * HDIM;
    const size_t boff = (size_t)blockIdx.z * SEQ * DMODEL;
    const __nv_bfloat16* Qg = Qb + boff + hoff;
    const __nv_bfloat16* Kg = Kb + boff + hoff;
    const __nv_bfloat16* Vg = Vb + boff + hoff;

    #pragma unroll
    for (int t = 0; t < 4; t++) {
        int idx = tid + t * 128;
        int row = idx >> 3, c8 = idx & 7;
        *(uint4*)&Qs[row * FP + c8 * 8] =
            *(const uint4*)(Qg + (size_t)(q0 + row) * DMODEL + c8 * 8);
    }
    __syncthreads();

    const uint32_t qsb = smem_u32(Qs);
    uint32_t qa[4][4];
    {
        const int ar = wid * 16 + (lane & 15);
        const int ac = (lane >> 4) * 8;
        #pragma unroll
        for (int c = 0; c < 4; c++)
            ldmx4(qa[c], qsb + (uint32_t)(ar * FP + c * 16 + ac) * 2);
    }

    float o[8][4];
    #pragma unroll
    for (int d = 0; d < 8; d++)
        #pragma unroll
        for (int e = 0; e < 4; e++) o[d][e] = 0.f;
    float m0 = -INFINITY, m1 = -INFINITY, l0 = 0.f, l1 = 0.f;

    auto load_kv = [&](int it, int s) {
        const int kb = it * 64;
        #pragma unroll
        for (int t = 0; t < 8; t++) {
            int idx   = tid + t * 128;
            int which = idx >> 9;
            int a     = idx & 511;
            int row   = a >> 3, c8 = a & 7;
            const __nv_bfloat16* g =
                (which ? Vg : Kg) + (size_t)(kb + row) * DMODEL + c8 * 8;
            cp16(smem_u32(&KVs[s][which][row * FP + c8 * 8]), g);
        }
        CP_COMMIT();
    };

    load_kv(0, 0);

    const int krow = (lane & 7) + ((lane >> 4) << 3);
    const int kcol = ((lane >> 3) & 1) * 8;
    const int vrow = (lane & 7) + (((lane >> 3) & 1) << 3);
    const int vcol = (lane >> 4) << 3;

    for (int it = 0; it < SEQ / 64; it++) {
        const int s = it & 1;
        if (it + 1 < SEQ / 64) { load_kv(it + 1, s ^ 1); CP_WAIT1(); }
        else                   { CP_WAIT0(); }
        __syncthreads();

        float sc[8][4];
        #pragma unroll
        for (int j = 0; j < 8; j++)
            #pragma unroll
            for (int e = 0; e < 4; e++) sc[j][e] = 0.f;

        const uint32_t kbase = smem_u32(&KVs[s][0][0]);
        #pragma unroll
        for (int c = 0; c < 4; c++) {
            #pragma unroll
            for (int j2 = 0; j2 < 4; j2++) {
                uint32_t r[4];
                ldmx4(r, kbase + (uint32_t)((16 * j2 + krow) * FP + c * 16 + kcol) * 2);
                mma16816(sc[2 * j2],     qa[c], r);
                mma16816(sc[2 * j2 + 1], qa[c], r + 2);
            }
        }

        float rx0 = -INFINITY, rx1 = -INFINITY;
        #pragma unroll
        for (int j = 0; j < 8; j++) {
            rx0 = fmaxf(rx0, fmaxf(sc[j][0], sc[j][1]));
            rx1 = fmaxf(rx1, fmaxf(sc[j][2], sc[j][3]));
        }
        #pragma unroll
        for (int off = 1; off < 4; off <<= 1) {
            rx0 = fmaxf(rx0, __shfl_xor_sync(0xffffffffu, rx0, off));
            rx1 = fmaxf(rx1, __shfl_xor_sync(0xffffffffu, rx1, off));
        }
        const float mn0 = fmaxf(m0, rx0), mn1 = fmaxf(m1, rx1);
        const float al0 = expf(m0 - mn0), al1 = expf(m1 - mn1);
        float rs0 = 0.f, rs1 = 0.f;
        #pragma unroll
        for (int j = 0; j < 8; j++) {
            sc[j][0] = expf(sc[j][0] - mn0);
            sc[j][1] = expf(sc[j][1] - mn0);
            sc[j][2] = expf(sc[j][2] - mn1);
            sc[j][3] = expf(sc[j][3] - mn1);
            rs0 += sc[j][0] + sc[j][1];
            rs1 += sc[j][2] + sc[j][3];
        }
        #pragma unroll
        for (int off = 1; off < 4; off <<= 1) {
            rs0 += __shfl_xor_sync(0xffffffffu, rs0, off);
            rs1 += __shfl_xor_sync(0xffffffffu, rs1, off);
        }
        l0 = l0 * al0 + rs0; m0 = mn0;
        l1 = l1 * al1 + rs1; m1 = mn1;
        #pragma unroll
        for (int d = 0; d < 8; d++) {
            o[d][0] *= al0; o[d][1] *= al0;
            o[d][2] *= al1; o[d][3] *= al1;
        }

        uint32_t pa[4][4];
        #pragma unroll
        for (int kc = 0; kc < 4; kc++) {
            pa[kc][0] = packbf2(sc[2 * kc][0],     sc[2 * kc][1]);
            pa[kc][1] = packbf2(sc[2 * kc][2],     sc[2 * kc][3]);
            pa[kc][2] = packbf2(sc[2 * kc + 1][0], sc[2 * kc + 1][1]);
            pa[kc][3] = packbf2(sc[2 * kc + 1][2], sc[2 * kc + 1][3]);
        }

        const uint32_t vbase = smem_u32(&KVs[s][1][0]);
        #pragma unroll
        for (int kc = 0; kc < 4; kc++) {
            #pragma unroll
            for (int d2 = 0; d2 < 4; d2++) {
                uint32_t r[4];
                ldmx4t(r, vbase + (uint32_t)((kc * 16 + vrow) * FP + d2 * 16 + vcol) * 2);
                mma16816(o[2 * d2],     pa[kc], r);
                mma16816(o[2 * d2 + 1], pa[kc], r + 2);
            }
        }
        __syncthreads();
    }

    const float inv0 = 1.0f / l0, inv1 = 1.0f / l1;
    const int row0 = q0 + wid * 16 + (lane >> 2);
    const int coff = (lane & 3) * 2;
    __nv_bfloat16* OhB = OH + boff + hoff;
    __nv_bfloat16* OlB = OL + boff + hoff;
    #pragma unroll
    for (int d = 0; d < 8; d++) {
        __nv_bfloat162 h2, l2;
        split2(o[d][0] * inv0, o[d][1] * inv0, h2, l2);
        size_t off0 = (size_t)row0 * DMODEL + d * 8 + coff;
        *(__nv_bfloat162*)(OhB + off0) = h2;
        *(__nv_bfloat162*)(OlB + off0) = l2;
        split2(o[d][2] * inv1, o[d][3] * inv1, h2, l2);
        size_t off1 = (size_t)(row0 + 8) * DMODEL + d * 8 + coff;
        *(__nv_bfloat162*)(OhB + off1) = h2;
        *(__nv_bfloat162*)(OlB + off1) = l2;
    }
}

// ====================================================================
// kernel_launch
// ====================================================================
extern "C" void kernel_launch(void* const* d_in, const int* in_sizes, int n_in,
                              void* d_out, int out_size)
{
    const float* x        = (const float*)d_in[0];
    const float* Wq       = (const float*)d_in[1];
    const float* bq       = (const float*)d_in[2];
    const float* Wk       = (const float*)d_in[3];
    const float* bk       = (const float*)d_in[4];
    const float* Wv       = (const float*)d_in[5];
    const float* bv       = (const float*)d_in[6];
    const float* Wo       = (const float*)d_in[7];
    const float* bo       = (const float*)d_in[8];
    const float* qn_scale = (const float*)d_in[9];
    const float* qn_bias  = (const float*)d_in[10];
    const float* kn_scale = (const float*)d_in[11];
    const float* kn_bias  = (const float*)d_in[12];
    const float* W1       = (const float*)d_in[13];
    const float* b1       = (const float*)d_in[14];
    const float* W2       = (const float*)d_in[15];
    const float* b2       = (const float*)d_in[16];
    const float* n1_scale = (const float*)d_in[17];
    const float* n2_scale = (const float*)d_in[18];
    float* out = (float*)d_out;

    __nv_bfloat16 *hH, *hL, *atH, *atL, *h2H, *h2L, *fH, *fL, *qb, *kb, *vb;
    __nv_bfloat16 *WqH, *WqL, *WkH, *WkL, *WvH, *WvL, *WoH, *WoL, *W1H, *W1L, *W2H, *W2L;
    float *q, *k, *x2;
    cudaGetSymbolAddress((void**)&hH,  g_hH);  cudaGetSymbolAddress((void**)&hL,  g_hL);
    cudaGetSymbolAddress((void**)&q,   g_q);   cudaGetSymbolAddress((void**)&k,   g_k);
    cudaGetSymbolAddress((void**)&qb,  g_qb);  cudaGetSymbolAddress((void**)&kb,  g_kb);
    cudaGetSymbolAddress((void**)&vb,  g_vb);
    cudaGetSymbolAddress((void**)&atH, g_atH); cudaGetSymbolAddress((void**)&atL, g_atL);
    cudaGetSymbolAddress((void**)&x2,  g_x2);
    cudaGetSymbolAddress((void**)&h2H, g_h2H); cudaGetSymbolAddress((void**)&h2L, g_h2L);
    cudaGetSymbolAddress((void**)&fH,  g_fH);  cudaGetSymbolAddress((void**)&fL,  g_fL);
    cudaGetSymbolAddress((void**)&WqH, g_WqH); cudaGetSymbolAddress((void**)&WqL, g_WqL);
    cudaGetSymbolAddress((void**)&WkH, g_WkH); cudaGetSymbolAddress((void**)&WkL, g_WkL);
    cudaGetSymbolAddress((void**)&WvH, g_WvH); cudaGetSymbolAddress((void**)&WvL, g_WvL);
    cudaGetSymbolAddress((void**)&WoH, g_WoH); cudaGetSymbolAddress((void**)&WoL, g_WoL);
    cudaGetSymbolAddress((void**)&W1H, g_W1H); cudaGetSymbolAddress((void**)&W1L, g_W1L);
    cudaGetSymbolAddress((void**)&W2H, g_W2H); cudaGetSymbolAddress((void**)&W2L, g_W2L);

    cudaFuncSetAttribute(mma_gemm, cudaFuncAttributeMaxDynamicSharedMemorySize, GSMEM);

    const dim3 tb(32, 8);
    const dim3 gD(DMODEL / BN, TOK / BM);     // 4 x 64
    const dim3 gF(FDIM   / BN, TOK / BM);     // 16 x 64

    wsplit_t<<<dim3(DMODEL/32, DMODEL/32), tb>>>(Wq, WqH, WqL, DMODEL, DMODEL);
    rmsnorm_split_k<<<TOK, 256>>>(x, n1_scale, hH, hL);
    wsplit_t<<<dim3(DMODEL/32, DMODEL/32), tb>>>(Wk, WkH, WkL, DMODEL, DMODEL);
    wsplit_t<<<dim3(DMODEL/32, DMODEL/32), tb>>>(Wv, WvH, WvL, DMODEL, DMODEL);
    wsplit_t<<<dim3(DMODEL/32, DMODEL/32), tb>>>(Wo, WoH, WoL, DMODEL, DMODEL);
    mma_gemm<<<gD, 256, GSMEM>>>(hH, hL, WqH, WqL, bq, nullptr, q, nullptr,
                                 nullptr, TOK, DMODEL, DMODEL, EPI_NONE);
    wsplit_t<<<dim3(FDIM/32,   DMODEL/32), tb>>>(W1, W1H, W1L, DMODEL, FDIM);
    wsplit_t<<<dim3(DMODEL/32, FDIM/32),   tb>>>(W2, W2H, W2L, FDIM,   DMODEL);
    mma_gemm<<<gD, 256, GSMEM>>>(hH, hL, WkH, WkL, bk, nullptr, k, nullptr, nullptr,
                                 TOK, DMODEL, DMODEL, EPI_NONE);
    mma_gemm<<<gD, 256, GSMEM>>>(hH, hL, WvH, WvL, bv, nullptr, nullptr, vb, nullptr,
                                 TOK, DMODEL, DMODEL, EPI_BF16);

    headln_bf16<<<TOK * NHEAD / 8, 256>>>(q, qb, qn_scale, qn_bias, 0.125f);
    headln_bf16<<<TOK * NHEAD / 8, 256>>>(k, kb, kn_scale, kn_bias, 1.0f);

    flash_mma<<<dim3(SEQ / 64, NHEAD, BATCH), 128>>>(qb, kb, vb, atH, atL);

    mma_gemm<<<gD, 256, GSMEM>>>(atH, atL, WoH, WoL, bo, x, x2, nullptr, nullptr,
                                 TOK, DMODEL, DMODEL, EPI_RES);

    rmsnorm_split_k<<<TOK, 256>>>(x2, n2_scale, h2H, h2L);

    mma_gemm<<<gF, 256, GSMEM>>>(h2H, h2L, W1H, W1L, b1, nullptr, nullptr, fH, fL,
                                 TOK, FDIM, DMODEL, EPI_GELU);

    mma_gemm<<<gD, 256, GSMEM>>>(fH, fL, W2H, W2L, b2, x2, out, nullptr, nullptr,
                                 TOK, DMODEL, FDIM, EPI_RES);
}

// round 8
// speedup vs baseline: 4.1835x; 1.3670x over previous
#include <cuda_runtime.h>
#include <cuda_fp16.h>
#include <math.h>
#include <stdint.h>

// ---------------- problem constants ----------------
#define TOK    8192          // 4 * 2048 tokens
#define DMODEL 1024
#define NHEAD  16
#define HDIM   64
#define FDIM   4096
#define SEQ    2048
#define BATCH  4
#define EPS    1e-5f

// ---------------- scratch (device globals; no runtime alloc) --------------
__device__ __align__(256) __half g_hH [(size_t)TOK * DMODEL];
__device__ __align__(256) __half g_hL [(size_t)TOK * DMODEL];
__device__ __align__(256) __half g_qh [(size_t)TOK * DMODEL];
__device__ __align__(256) __half g_kh [(size_t)TOK * DMODEL];
__device__ __align__(256) __half g_vh [(size_t)TOK * DMODEL];
__device__ __align__(256) __half g_atH[(size_t)TOK * DMODEL];
__device__ __align__(256) __half g_atL[(size_t)TOK * DMODEL];
__device__ __align__(256) float  g_x2 [(size_t)TOK * DMODEL];
__device__ __align__(256) __half g_h2H[(size_t)TOK * DMODEL];
__device__ __align__(256) __half g_h2L[(size_t)TOK * DMODEL];
__device__ __align__(256) __half g_fH [(size_t)TOK * FDIM];
__device__ __align__(256) __half g_fL [(size_t)TOK * FDIM];
// transposed fp16 weights: Wt[N,K] (hi only — 2-pass scheme)
__device__ __align__(256) __half g_Wq [(size_t)DMODEL * DMODEL];
__device__ __align__(256) __half g_Wk [(size_t)DMODEL * DMODEL];
__device__ __align__(256) __half g_Wv [(size_t)DMODEL * DMODEL];
__device__ __align__(256) __half g_Wo [(size_t)DMODEL * DMODEL];
__device__ __align__(256) __half g_W1 [(size_t)FDIM * DMODEL];
__device__ __align__(256) __half g_W2 [(size_t)DMODEL * FDIM];

// =================== PTX helpers (sm_80-compatible only) ===================
__device__ __forceinline__ uint32_t smem_u32(const void* p) {
    uint32_t a;
    asm("{ .reg .u64 t; cvta.to.shared.u64 t, %1; cvt.u32.u64 %0, t; }"
        : "=r"(a) : "l"(p));
    return a;
}
__device__ __forceinline__ void cp16(uint32_t dst, const void* src) {
    asm volatile("cp.async.cg.shared.global [%0], [%1], 16;"
                 :: "r"(dst), "l"(src));
}
#define CP_COMMIT() asm volatile("cp.async.commit_group;" ::: "memory")
#define CP_WAIT2()  asm volatile("cp.async.wait_group 2;" ::: "memory")
#define CP_WAIT1()  asm volatile("cp.async.wait_group 1;" ::: "memory")
#define CP_WAIT0()  asm volatile("cp.async.wait_group 0;" ::: "memory")

__device__ __forceinline__ void ldmx4(uint32_t* r, uint32_t addr) {
    asm volatile("ldmatrix.sync.aligned.m8n8.x4.shared.b16 {%0,%1,%2,%3}, [%4];"
                 : "=r"(r[0]), "=r"(r[1]), "=r"(r[2]), "=r"(r[3]) : "r"(addr));
}
__device__ __forceinline__ void ldmx4t(uint32_t* r, uint32_t addr) {
    asm volatile("ldmatrix.sync.aligned.m8n8.x4.trans.shared.b16 {%0,%1,%2,%3}, [%4];"
                 : "=r"(r[0]), "=r"(r[1]), "=r"(r[2]), "=r"(r[3]) : "r"(addr));
}
__device__ __forceinline__ void ldmx2(uint32_t* r, uint32_t addr) {
    asm volatile("ldmatrix.sync.aligned.m8n8.x2.shared.b16 {%0,%1}, [%2];"
                 : "=r"(r[0]), "=r"(r[1]) : "r"(addr));
}
// fp16 inputs, fp32 accumulate
__device__ __forceinline__ void mma16816(float* c, const uint32_t* a,
                                         const uint32_t* b) {
    asm volatile(
        "mma.sync.aligned.m16n8k16.row.col.f32.f16.f16.f32 "
        "{%0,%1,%2,%3}, {%4,%5,%6,%7}, {%8,%9}, {%0,%1,%2,%3};"
        : "+f"(c[0]), "+f"(c[1]), "+f"(c[2]), "+f"(c[3])
        : "r"(a[0]), "r"(a[1]), "r"(a[2]), "r"(a[3]), "r"(b[0]), "r"(b[1]));
}

// =================== fp16 split helpers ===================
__device__ __forceinline__ void split2h(float a, float b,
                                        __half2& hi, __half2& lo) {
    __half ha = __float2half(a), hb = __float2half(b);
    __half la = __float2half(a - __half2float(ha));
    __half lb = __float2half(b - __half2float(hb));
    hi = __halves2half2(ha, hb);
    lo = __halves2half2(la, lb);
}
__device__ __forceinline__ uint32_t packh2(float lo, float hi) {
    __half2 t = __halves2half2(__float2half(lo), __float2half(hi));
    return *(uint32_t*)&t;
}

// ====================================================================
// Weight transpose + convert:  W[K,N] fp32  ->  Wt[N,K] fp16
// ====================================================================
__global__ __launch_bounds__(256) void wconv_t(const float* __restrict__ W,
                                               __half* __restrict__ T,
                                               int K, int N)
{
    __shared__ float t[32][33];
    const int k0 = blockIdx.y * 32, n0 = blockIdx.x * 32;
    const int tx = threadIdx.x, ty = threadIdx.y;   // (32, 8)
    #pragma unroll
    for (int j = 0; j < 4; j++) {
        int r = ty + j * 8;
        t[r][tx] = W[(size_t)(k0 + r) * N + n0 + tx];
    }
    __syncthreads();
    #pragma unroll
    for (int j = 0; j < 4; j++) {
        int r = ty + j * 8;
        T[(size_t)(n0 + r) * K + k0 + tx] = __float2half(t[tx][r]);
    }
}

// ====================================================================
// RMSNorm over D=1024 -> split fp16 outputs
// ====================================================================
__global__ __launch_bounds__(256) void rmsnorm_split_k(const float* __restrict__ x,
                                                       const float* __restrict__ scale,
                                                       __half* __restrict__ yH,
                                                       __half* __restrict__ yL)
{
    const int row = blockIdx.x;
    const int t   = threadIdx.x;
    const float4 v = ((const float4*)(x + (size_t)row * DMODEL))[t];
    float ss = v.x*v.x + v.y*v.y + v.z*v.z + v.w*v.w;
    #pragma unroll
    for (int off = 16; off; off >>= 1) ss += __shfl_xor_sync(0xffffffffu, ss, off);
    __shared__ float red[8];
    if ((t & 31) == 0) red[t >> 5] = ss;
    __syncthreads();
    float tot = 0.f;
    #pragma unroll
    for (int w = 0; w < 8; w++) tot += red[w];
    const float r = rsqrtf(tot * (1.0f / DMODEL) + EPS);
    const float4 s4 = ((const float4*)scale)[t];
    float o0 = v.x*r*s4.x, o1 = v.y*r*s4.y, o2 = v.z*r*s4.z, o3 = v.w*r*s4.w;
    __half2 h0, l0, h1, l1;
    split2h(o0, o1, h0, l0);
    split2h(o2, o3, h1, l1);
    const size_t base = (size_t)row * DMODEL + t * 4;
    *(__half2*)(yH + base)     = h0;
    *(__half2*)(yH + base + 2) = h1;
    *(__half2*)(yL + base)     = l0;
    *(__half2*)(yL + base + 2) = l1;
}

// ====================================================================
// 2-pass split-fp16 mma.sync GEMM: D[M,N] = (Ah+Al)[M,K] @ Wt[N,K]^T + bias
// CTA 128x256, BK=32, 8 warps (2x4), warp tile 64x64, 3-stage cp.async.
// epi: GELU -> split fp16; RES -> fp32 + residual; F16 -> fp16;
//      QLN/KLN -> fused per-head LayerNorm (warp's 64 cols = one head),
//                 fp16 out (QLN folds softmax scale 0.125).
// ====================================================================
#define EPI_GELU 1
#define EPI_RES  2
#define EPI_F16  3
#define EPI_QLN  4
#define EPI_KLN  5

#define BM 128
#define BN 256
#define GPITCH 40                       // halves per smem row (32 + 8 pad)
#define A_ARR  (BM * GPITCH)            // halves
#define B_ARR  (BN * GPITCH)            // halves
#define STG_H  (2 * A_ARR + B_ARR)      // halves per stage (Ah, Al, Bh)
#define GSMEM  (3 * STG_H * 2)          // bytes, 3 stages = 122880

__global__ __launch_bounds__(256, 1) void mma_gemm(
    const __half* __restrict__ Ah, const __half* __restrict__ Al,
    const __half* __restrict__ Bh,
    const float* __restrict__ bias, const float* __restrict__ res,
    const float* __restrict__ ln_s, const float* __restrict__ ln_b,
    float* __restrict__ outF,
    __half* __restrict__ outH, __half* __restrict__ outL,
    int M, int N, int K, int epi)
{
    extern __shared__ __half smh[];
    const uint32_t sb = smem_u32(smh);
    const int tid  = threadIdx.x;
    const int wid  = tid >> 5;
    const int lane = tid & 31;
    const int wm   = wid >> 2;           // 0..1 -> 64 rows each
    const int wn   = wid & 3;            // 0..3 -> 64 cols each
    const int bm   = blockIdx.y * BM;
    const int bn   = blockIdx.x * BN;

    auto load_chunk = [&](int c, int s) {
        const int k0 = c << 5;
        const uint32_t base = sb + (uint32_t)s * STG_H * 2;
        #pragma unroll
        for (int j = 0; j < 8; j++) {
            int idx = tid + j * 256;     // 0..2047 16B-chunks
            const __half* g;
            uint32_t dst;
            if (idx < 1024) {            // A: 2 arrays x 128 rows x 4 chunks
                int arr = idx >> 9;
                int a   = idx & 511;
                int row = a >> 2, ch = a & 3;
                g   = (arr ? Al : Ah) + (size_t)(bm + row) * K + k0 + ch * 8;
                dst = base + ((uint32_t)arr * A_ARR + row * GPITCH + ch * 8) * 2;
            } else {                     // B: 1 array x 256 rows x 4 chunks
                int a   = idx - 1024;
                int row = a >> 2, ch = a & 3;
                g   = Bh + (size_t)(bn + row) * K + k0 + ch * 8;
                dst = base + (2 * A_ARR + (uint32_t)row * GPITCH + ch * 8) * 2;
            }
            cp16(dst, g);
        }
        CP_COMMIT();
    };

    float acc[4][8][4];
    #pragma unroll
    for (int m = 0; m < 4; m++)
        #pragma unroll
        for (int n = 0; n < 8; n++)
            #pragma unroll
            for (int e = 0; e < 4; e++) acc[m][n][e] = 0.f;

    const int nch = K >> 5;
    load_chunk(0, 0);
    load_chunk(1, 1);
    load_chunk(2, 2);

    const int l16 = lane & 15;
    const int a_r = l16;
    const int a_c = (lane >> 4) * 8;
    const int b_r = l16 & 7;
    const int b_c = (l16 >> 3) * 8;

    int s = 0;
    for (int i = 0; i < nch; i++) {
        if (i + 3 <= nch - 1)      { CP_WAIT2(); }
        else if (i + 2 <= nch - 1) { CP_WAIT1(); }
        else                       { CP_WAIT0(); }
        __syncthreads();
        const uint32_t ab = sb + (uint32_t)s * STG_H * 2;
        const uint32_t bb = ab + 2 * A_ARR * 2;

        #pragma unroll
        for (int kk = 0; kk < 2; kk++) {
            const int kh = kk * 16;
            uint32_t ah[4][4], al[4][4];
            #pragma unroll
            for (int m = 0; m < 4; m++) {
                uint32_t addr = ab +
                    (uint32_t)((wm * 64 + m * 16 + a_r) * GPITCH + kh + a_c) * 2;
                ldmx4(ah[m], addr);
                ldmx4(al[m], addr + A_ARR * 2);
            }
            #pragma unroll
            for (int half = 0; half < 2; half++) {
                uint32_t bh[4][2];
                #pragma unroll
                for (int n4 = 0; n4 < 4; n4++) {
                    int n = half * 4 + n4;
                    uint32_t addr = bb +
                        (uint32_t)((wn * 64 + n * 8 + b_r) * GPITCH + kh + b_c) * 2;
                    ldmx2(bh[n4], addr);
                }
                #pragma unroll
                for (int m = 0; m < 4; m++)
                    #pragma unroll
                    for (int n4 = 0; n4 < 4; n4++)
                        mma16816(acc[m][half * 4 + n4], ah[m], bh[n4]);
                #pragma unroll
                for (int m = 0; m < 4; m++)
                    #pragma unroll
                    for (int n4 = 0; n4 < 4; n4++)
                        mma16816(acc[m][half * 4 + n4], al[m], bh[n4]);
            }
        }
        __syncthreads();
        if (i + 3 < nch) load_chunk(i + 3, s);
        s = (s == 2) ? 0 : s + 1;
    }

    // -------- epilogue ----------
    const int g  = lane >> 2;
    const int t4 = lane & 3;

    if (epi == EPI_QLN || epi == EPI_KLN) {
        // fused per-head LayerNorm: warp's 64 cols = one head.
        const float mul = (epi == EPI_QLN) ? 0.125f : 1.0f;
        #pragma unroll
        for (int m = 0; m < 4; m++) {
            float v[8][4];
            float s0 = 0.f, q0 = 0.f, s1 = 0.f, q1 = 0.f;
            #pragma unroll
            for (int n = 0; n < 8; n++) {
                const int col = bn + wn * 64 + n * 8 + t4 * 2;
                const float b0 = __ldg(&bias[col]);
                const float b1 = __ldg(&bias[col + 1]);
                v[n][0] = acc[m][n][0] + b0; v[n][1] = acc[m][n][1] + b1;
                v[n][2] = acc[m][n][2] + b0; v[n][3] = acc[m][n][3] + b1;
                s0 += v[n][0] + v[n][1];  q0 += v[n][0]*v[n][0] + v[n][1]*v[n][1];
                s1 += v[n][2] + v[n][3];  q1 += v[n][2]*v[n][2] + v[n][3]*v[n][3];
            }
            #pragma unroll
            for (int off = 1; off < 4; off <<= 1) {
                s0 += __shfl_xor_sync(0xffffffffu, s0, off);
                q0 += __shfl_xor_sync(0xffffffffu, q0, off);
                s1 += __shfl_xor_sync(0xffffffffu, s1, off);
                q1 += __shfl_xor_sync(0xffffffffu, q1, off);
            }
            const float mu0 = s0 * (1.0f/64.0f), mu1 = s1 * (1.0f/64.0f);
            const float r0  = rsqrtf(q0 * (1.0f/64.0f) - mu0*mu0 + EPS);
            const float r1  = rsqrtf(q1 * (1.0f/64.0f) - mu1*mu1 + EPS);
            const int row0 = bm + wm * 64 + m * 16 + g;
            #pragma unroll
            for (int n = 0; n < 8; n++) {
                const int col = bn + wn * 64 + n * 8 + t4 * 2;
                const int hc  = col & 63;
                const float sA = __ldg(&ln_s[hc]),     bA = __ldg(&ln_b[hc]);
                const float sB = __ldg(&ln_s[hc + 1]), bB = __ldg(&ln_b[hc + 1]);
                float o0 = ((v[n][0] - mu0) * r0 * sA + bA) * mul;
                float o1 = ((v[n][1] - mu0) * r0 * sB + bB) * mul;
                float o2 = ((v[n][2] - mu1) * r1 * sA + bA) * mul;
                float o3 = ((v[n][3] - mu1) * r1 * sB + bB) * mul;
                *(uint32_t*)(outH + (size_t)row0 * N + col)       = packh2(o0, o1);
                *(uint32_t*)(outH + (size_t)(row0 + 8) * N + col) = packh2(o2, o3);
            }
        }
        return;
    }

    #pragma unroll
    for (int n = 0; n < 8; n++) {
        const int col = bn + wn * 64 + n * 8 + t4 * 2;
        const float b0 = __ldg(&bias[col]);
        const float b1 = __ldg(&bias[col + 1]);
        #pragma unroll
        for (int m = 0; m < 4; m++) {
            const int row0 = bm + wm * 64 + m * 16 + g;
            float v[4] = { acc[m][n][0] + b0, acc[m][n][1] + b1,
                           acc[m][n][2] + b0, acc[m][n][3] + b1 };
            if (epi == EPI_GELU) {
                #pragma unroll
                for (int e = 0; e < 4; e++) {
                    float u = v[e];
                    v[e] = 0.5f * u * (1.0f + erff(u * 0.70710678118654752f));
                }
                __half2 h2, l2;
                split2h(v[0], v[1], h2, l2);
                *(__half2*)(outH + (size_t)row0 * N + col) = h2;
                *(__half2*)(outL + (size_t)row0 * N + col) = l2;
                split2h(v[2], v[3], h2, l2);
                *(__half2*)(outH + (size_t)(row0 + 8) * N + col) = h2;
                *(__half2*)(outL + (size_t)(row0 + 8) * N + col) = l2;
            } else if (epi == EPI_F16) {
                *(uint32_t*)(outH + (size_t)row0 * N + col)       = packh2(v[0], v[1]);
                *(uint32_t*)(outH + (size_t)(row0 + 8) * N + col) = packh2(v[2], v[3]);
            } else {  // EPI_RES
                float2 r0 = *(const float2*)(res + (size_t)row0 * N + col);
                float2 r1 = *(const float2*)(res + (size_t)(row0 + 8) * N + col);
                v[0] += r0.x; v[1] += r0.y; v[2] += r1.x; v[3] += r1.y;
                *(float2*)(outF + (size_t)row0 * N + col)       = make_float2(v[0], v[1]);
                *(float2*)(outF + (size_t)(row0 + 8) * N + col) = make_float2(v[2], v[3]);
            }
        }
    }
}

// ====================================================================
// Tensorized flash attention (mma.sync fp16, fp32 softmax).
// Output: split fp16 for the 2-pass Wo GEMM.
// ====================================================================
#define FP 72   // smem pitch in halves (64 + 8)

__global__ __launch_bounds__(128) void flash_mma(
    const __half* __restrict__ Qh,
    const __half* __restrict__ Kh,
    const __half* __restrict__ Vh,
    __half* __restrict__ OH,
    __half* __restrict__ OL)
{
    __shared__ __half Qs[64 * FP];
    __shared__ __half KVs[2][2][64 * FP];   // [stage][K=0/V=1]

    const int tid  = threadIdx.x;
    const int wid  = tid >> 5;
    const int lane = tid & 31;
    const int q0   = blockIdx.x * 64;
    const size_t hoff = (size_t)blockIdx.y * HDIM;
    const size_t boff = (size_t)blockIdx.z * SEQ * DMODEL;
    const __half* Qg = Qh + boff + hoff;
    const __half* Kg = Kh + boff + hoff;
    const __half* Vg = Vh + boff + hoff;

    #pragma unroll
    for (int t = 0; t < 4; t++) {
        int idx = tid + t * 128;
        int row = idx >> 3, c8 = idx & 7;
        *(uint4*)&Qs[row * FP + c8 * 8] =
            *(const uint4*)(Qg + (size_t)(q0 + row) * DMODEL + c8 * 8);
    }
    __syncthreads();

    const uint32_t qsb = smem_u32(Qs);
    uint32_t qa[4][4];
    {
        const int ar = wid * 16 + (lane & 15);
        const int ac = (lane >> 4) * 8;
        #pragma unroll
        for (int c = 0; c < 4; c++)
            ldmx4(qa[c], qsb + (uint32_t)(ar * FP + c * 16 + ac) * 2);
    }

    float o[8][4];
    #pragma unroll
    for (int d = 0; d < 8; d++)
        #pragma unroll
        for (int e = 0; e < 4; e++) o[d][e] = 0.f;
    float m0 = -INFINITY, m1 = -INFINITY, l0 = 0.f, l1 = 0.f;

    auto load_kv = [&](int it, int s) {
        const int kb = it * 64;
        #pragma unroll
        for (int t = 0; t < 8; t++) {
            int idx   = tid + t * 128;
            int which = idx >> 9;
            int a     = idx & 511;
            int row   = a >> 3, c8 = a & 7;
            const __half* g =
                (which ? Vg : Kg) + (size_t)(kb + row) * DMODEL + c8 * 8;
            cp16(smem_u32(&KVs[s][which][row * FP + c8 * 8]), g);
        }
        CP_COMMIT();
    };

    load_kv(0, 0);

    const int krow = (lane & 7) + ((lane >> 4) << 3);
    const int kcol = ((lane >> 3) & 1) * 8;
    const int vrow = (lane & 7) + (((lane >> 3) & 1) << 3);
    const int vcol = (lane >> 4) << 3;

    for (int it = 0; it < SEQ / 64; it++) {
        const int s = it & 1;
        if (it + 1 < SEQ / 64) { load_kv(it + 1, s ^ 1); CP_WAIT1(); }
        else                   { CP_WAIT0(); }
        __syncthreads();

        float sc[8][4];
        #pragma unroll
        for (int j = 0; j < 8; j++)
            #pragma unroll
            for (int e = 0; e < 4; e++) sc[j][e] = 0.f;

        const uint32_t kbase = smem_u32(&KVs[s][0][0]);
        #pragma unroll
        for (int c = 0; c < 4; c++) {
            #pragma unroll
            for (int j2 = 0; j2 < 4; j2++) {
                uint32_t r[4];
                ldmx4(r, kbase + (uint32_t)((16 * j2 + krow) * FP + c * 16 + kcol) * 2);
                mma16816(sc[2 * j2],     qa[c], r);
                mma16816(sc[2 * j2 + 1], qa[c], r + 2);
            }
        }

        float rx0 = -INFINITY, rx1 = -INFINITY;
        #pragma unroll
        for (int j = 0; j < 8; j++) {
            rx0 = fmaxf(rx0, fmaxf(sc[j][0], sc[j][1]));
            rx1 = fmaxf(rx1, fmaxf(sc[j][2], sc[j][3]));
        }
        #pragma unroll
        for (int off = 1; off < 4; off <<= 1) {
            rx0 = fmaxf(rx0, __shfl_xor_sync(0xffffffffu, rx0, off));
            rx1 = fmaxf(rx1, __shfl_xor_sync(0xffffffffu, rx1, off));
        }
        const float mn0 = fmaxf(m0, rx0), mn1 = fmaxf(m1, rx1);
        const float al0 = expf(m0 - mn0), al1 = expf(m1 - mn1);
        float rs0 = 0.f, rs1 = 0.f;
        #pragma unroll
        for (int j = 0; j < 8; j++) {
            sc[j][0] = expf(sc[j][0] - mn0);
            sc[j][1] = expf(sc[j][1] - mn0);
            sc[j][2] = expf(sc[j][2] - mn1);
            sc[j][3] = expf(sc[j][3] - mn1);
            rs0 += sc[j][0] + sc[j][1];
            rs1 += sc[j][2] + sc[j][3];
        }
        #pragma unroll
        for (int off = 1; off < 4; off <<= 1) {
            rs0 += __shfl_xor_sync(0xffffffffu, rs0, off);
            rs1 += __shfl_xor_sync(0xffffffffu, rs1, off);
        }
        l0 = l0 * al0 + rs0; m0 = mn0;
        l1 = l1 * al1 + rs1; m1 = mn1;
        #pragma unroll
        for (int d = 0; d < 8; d++) {
            o[d][0] *= al0; o[d][1] *= al0;
            o[d][2] *= al1; o[d][3] *= al1;
        }

        uint32_t pa[4][4];
        #pragma unroll
        for (int kc = 0; kc < 4; kc++) {
            pa[kc][0] = packh2(sc[2 * kc][0],     sc[2 * kc][1]);
            pa[kc][1] = packh2(sc[2 * kc][2],     sc[2 * kc][3]);
            pa[kc][2] = packh2(sc[2 * kc + 1][0], sc[2 * kc + 1][1]);
            pa[kc][3] = packh2(sc[2 * kc + 1][2], sc[2 * kc + 1][3]);
        }

        const uint32_t vbase = smem_u32(&KVs[s][1][0]);
        #pragma unroll
        for (int kc = 0; kc < 4; kc++) {
            #pragma unroll
            for (int d2 = 0; d2 < 4; d2++) {
                uint32_t r[4];
                ldmx4t(r, vbase + (uint32_t)((kc * 16 + vrow) * FP + d2 * 16 + vcol) * 2);
                mma16816(o[2 * d2],     pa[kc], r);
                mma16816(o[2 * d2 + 1], pa[kc], r + 2);
            }
        }
        __syncthreads();
    }

    const float inv0 = 1.0f / l0, inv1 = 1.0f / l1;
    const int row0 = q0 + wid * 16 + (lane >> 2);
    const int coff = (lane & 3) * 2;
    __half* OhB = OH + boff + hoff;
    __half* OlB = OL + boff + hoff;
    #pragma unroll
    for (int d = 0; d < 8; d++) {
        __half2 h2, l2;
        split2h(o[d][0] * inv0, o[d][1] * inv0, h2, l2);
        size_t off0 = (size_t)row0 * DMODEL + d * 8 + coff;
        *(__half2*)(OhB + off0) = h2;
        *(__half2*)(OlB + off0) = l2;
        split2h(o[d][2] * inv1, o[d][3] * inv1, h2, l2);
        size_t off1 = (size_t)(row0 + 8) * DMODEL + d * 8 + coff;
        *(__half2*)(OhB + off1) = h2;
        *(__half2*)(OlB + off1) = l2;
    }
}

// ====================================================================
// kernel_launch
// ====================================================================
extern "C" void kernel_launch(void* const* d_in, const int* in_sizes, int n_in,
                              void* d_out, int out_size)
{
    const float* x        = (const float*)d_in[0];
    const float* Wq       = (const float*)d_in[1];
    const float* bq       = (const float*)d_in[2];
    const float* Wk       = (const float*)d_in[3];
    const float* bk       = (const float*)d_in[4];
    const float* Wv       = (const float*)d_in[5];
    const float* bv       = (const float*)d_in[6];
    const float* Wo       = (const float*)d_in[7];
    const float* bo       = (const float*)d_in[8];
    const float* qn_scale = (const float*)d_in[9];
    const float* qn_bias  = (const float*)d_in[10];
    const float* kn_scale = (const float*)d_in[11];
    const float* kn_bias  = (const float*)d_in[12];
    const float* W1       = (const float*)d_in[13];
    const float* b1       = (const float*)d_in[14];
    const float* W2       = (const float*)d_in[15];
    const float* b2       = (const float*)d_in[16];
    const float* n1_scale = (const float*)d_in[17];
    const float* n2_scale = (const float*)d_in[18];
    float* out = (float*)d_out;

    __half *hH, *hL, *qh, *kh, *vh, *atH, *atL, *h2H, *h2L, *fH, *fL;
    __half *pWq, *pWk, *pWv, *pWo, *pW1, *pW2;
    float *x2;
    cudaGetSymbolAddress((void**)&hH,  g_hH);  cudaGetSymbolAddress((void**)&hL,  g_hL);
    cudaGetSymbolAddress((void**)&qh,  g_qh);  cudaGetSymbolAddress((void**)&kh,  g_kh);
    cudaGetSymbolAddress((void**)&vh,  g_vh);
    cudaGetSymbolAddress((void**)&atH, g_atH); cudaGetSymbolAddress((void**)&atL, g_atL);
    cudaGetSymbolAddress((void**)&x2,  g_x2);
    cudaGetSymbolAddress((void**)&h2H, g_h2H); cudaGetSymbolAddress((void**)&h2L, g_h2L);
    cudaGetSymbolAddress((void**)&fH,  g_fH);  cudaGetSymbolAddress((void**)&fL,  g_fL);
    cudaGetSymbolAddress((void**)&pWq, g_Wq);  cudaGetSymbolAddress((void**)&pWk, g_Wk);
    cudaGetSymbolAddress((void**)&pWv, g_Wv);  cudaGetSymbolAddress((void**)&pWo, g_Wo);
    cudaGetSymbolAddress((void**)&pW1, g_W1);  cudaGetSymbolAddress((void**)&pW2, g_W2);

    cudaFuncSetAttribute(mma_gemm, cudaFuncAttributeMaxDynamicSharedMemorySize, GSMEM);

    const dim3 tb(32, 8);
    const dim3 gD(DMODEL / BN, TOK / BM);     // 4 x 64
    const dim3 gF(FDIM   / BN, TOK / BM);     // 16 x 64

    // launches 6 and 7 are both mma_gemm so ncu (-s 5 -c 1) captures a GEMM
    wconv_t<<<dim3(DMODEL/32, DMODEL/32), tb>>>(Wq, pWq, DMODEL, DMODEL);   // 1
    wconv_t<<<dim3(DMODEL/32, DMODEL/32), tb>>>(Wk, pWk, DMODEL, DMODEL);   // 2
    wconv_t<<<dim3(DMODEL/32, DMODEL/32), tb>>>(Wv, pWv, DMODEL, DMODEL);   // 3
    rmsnorm_split_k<<<TOK, 256>>>(x, n1_scale, hH, hL);                     // 4
    wconv_t<<<dim3(DMODEL/32, DMODEL/32), tb>>>(Wo, pWo, DMODEL, DMODEL);   // 5
    // q = LN(h@Wq + bq) * 0.125  (fused head-LN epilogue)
    mma_gemm<<<gD, 256, GSMEM>>>(hH, hL, pWq, bq, nullptr, qn_scale, qn_bias,   // 6
                                 nullptr, qh, nullptr, TOK, DMODEL, DMODEL, EPI_QLN);
    // k = LN(h@Wk + bk)
    mma_gemm<<<gD, 256, GSMEM>>>(hH, hL, pWk, bk, nullptr, kn_scale, kn_bias,   // 7
                                 nullptr, kh, nullptr, TOK, DMODEL, DMODEL, EPI_KLN);
    wconv_t<<<dim3(FDIM/32,   DMODEL/32), tb>>>(W1, pW1, DMODEL, FDIM);     // 8
    wconv_t<<<dim3(DMODEL/32, FDIM/32),   tb>>>(W2, pW2, FDIM,   DMODEL);   // 9
    // v = h@Wv + bv  (fp16 out)
    mma_gemm<<<gD, 256, GSMEM>>>(hH, hL, pWv, bv, nullptr, nullptr, nullptr,
                                 nullptr, vh, nullptr, TOK, DMODEL, DMODEL, EPI_F16);

    flash_mma<<<dim3(SEQ / 64, NHEAD, BATCH), 128>>>(qh, kh, vh, atH, atL);

    // x2 = x + attn @ Wo + bo
    mma_gemm<<<gD, 256, GSMEM>>>(atH, atL, pWo, bo, x, nullptr, nullptr,
                                 x2, nullptr, nullptr, TOK, DMODEL, DMODEL, EPI_RES);

    rmsnorm_split_k<<<TOK, 256>>>(x2, n2_scale, h2H, h2L);

    // ffn = gelu(h2 @ W1 + b1)  (split fp16 out)
    mma_gemm<<<gF, 256, GSMEM>>>(h2H, h2L, pW1, b1, nullptr, nullptr, nullptr,
                                 nullptr, fH, fL, TOK, FDIM, DMODEL, EPI_GELU);

    // out = x2 + ffn @ W2 + b2
    mma_gemm<<<gD, 256, GSMEM>>>(fH, fL, pW2, b2, x2, nullptr, nullptr,
                                 out, nullptr, nullptr, TOK, DMODEL, FDIM, EPI_RES);
}

// round 9
// speedup vs baseline: 5.9809x; 1.4296x over previous
#include <cuda_runtime.h>
#include <cuda_fp16.h>
#include <math.h>
#include <stdint.h>

// ---------------- problem constants ----------------
#define TOK    8192          // 4 * 2048 tokens
#define DMODEL 1024
#define NHEAD  16
#define HDIM   64
#define FDIM   4096
#define SEQ    2048
#define BATCH  4
#define EPS    1e-5f

// ---------------- scratch (device globals; no runtime alloc) --------------
__device__ __align__(256) __half g_h  [(size_t)TOK * DMODEL];
__device__ __align__(256) __half g_qh [(size_t)TOK * DMODEL];
__device__ __align__(256) __half g_kh [(size_t)TOK * DMODEL];
__device__ __align__(256) __half g_vh [(size_t)TOK * DMODEL];
__device__ __align__(256) __half g_at [(size_t)TOK * DMODEL];
__device__ __align__(256) float  g_x2 [(size_t)TOK * DMODEL];
__device__ __align__(256) __half g_h2 [(size_t)TOK * DMODEL];
__device__ __align__(256) __half g_f  [(size_t)TOK * FDIM];
// transposed fp16 weights: Wt[N,K]
__device__ __align__(256) __half g_Wq [(size_t)DMODEL * DMODEL];
__device__ __align__(256) __half g_Wk [(size_t)DMODEL * DMODEL];
__device__ __align__(256) __half g_Wv [(size_t)DMODEL * DMODEL];
__device__ __align__(256) __half g_Wo [(size_t)DMODEL * DMODEL];
__device__ __align__(256) __half g_W1 [(size_t)FDIM * DMODEL];
__device__ __align__(256) __half g_W2 [(size_t)DMODEL * FDIM];

// =================== PTX helpers (sm_80-compatible only) ===================
__device__ __forceinline__ uint32_t smem_u32(const void* p) {
    uint32_t a;
    asm("{ .reg .u64 t; cvta.to.shared.u64 t, %1; cvt.u32.u64 %0, t; }"
        : "=r"(a) : "l"(p));
    return a;
}
__device__ __forceinline__ void cp16(uint32_t dst, const void* src) {
    asm volatile("cp.async.cg.shared.global [%0], [%1], 16;"
                 :: "r"(dst), "l"(src));
}
#define CP_COMMIT() asm volatile("cp.async.commit_group;" ::: "memory")
#define CP_WAIT2()  asm volatile("cp.async.wait_group 2;" ::: "memory")
#define CP_WAIT1()  asm volatile("cp.async.wait_group 1;" ::: "memory")
#define CP_WAIT0()  asm volatile("cp.async.wait_group 0;" ::: "memory")

__device__ __forceinline__ void ldmx4(uint32_t* r, uint32_t addr) {
    asm volatile("ldmatrix.sync.aligned.m8n8.x4.shared.b16 {%0,%1,%2,%3}, [%4];"
                 : "=r"(r[0]), "=r"(r[1]), "=r"(r[2]), "=r"(r[3]) : "r"(addr));
}
__device__ __forceinline__ void ldmx4t(uint32_t* r, uint32_t addr) {
    asm volatile("ldmatrix.sync.aligned.m8n8.x4.trans.shared.b16 {%0,%1,%2,%3}, [%4];"
                 : "=r"(r[0]), "=r"(r[1]), "=r"(r[2]), "=r"(r[3]) : "r"(addr));
}
__device__ __forceinline__ void ldmx2(uint32_t* r, uint32_t addr) {
    asm volatile("ldmatrix.sync.aligned.m8n8.x2.shared.b16 {%0,%1}, [%2];"
                 : "=r"(r[0]), "=r"(r[1]) : "r"(addr));
}
// fp16 inputs, fp32 accumulate
__device__ __forceinline__ void mma16816(float* c, const uint32_t* a,
                                         const uint32_t* b) {
    asm volatile(
        "mma.sync.aligned.m16n8k16.row.col.f32.f16.f16.f32 "
        "{%0,%1,%2,%3}, {%4,%5,%6,%7}, {%8,%9}, {%0,%1,%2,%3};"
        : "+f"(c[0]), "+f"(c[1]), "+f"(c[2]), "+f"(c[3])
        : "r"(a[0]), "r"(a[1]), "r"(a[2]), "r"(a[3]), "r"(b[0]), "r"(b[1]));
}

__device__ __forceinline__ uint32_t packh2(float lo, float hi) {
    __half2 t = __halves2half2(__float2half(lo), __float2half(hi));
    return *(uint32_t*)&t;
}

// ====================================================================
// Weight transpose + convert:  W[K,N] fp32  ->  Wt[N,K] fp16
// ====================================================================
__global__ __launch_bounds__(256) void wconv_t(const float* __restrict__ W,
                                               __half* __restrict__ T,
                                               int K, int N)
{
    __shared__ float t[32][33];
    const int k0 = blockIdx.y * 32, n0 = blockIdx.x * 32;
    const int tx = threadIdx.x, ty = threadIdx.y;   // (32, 8)
    #pragma unroll
    for (int j = 0; j < 4; j++) {
        int r = ty + j * 8;
        t[r][tx] = W[(size_t)(k0 + r) * N + n0 + tx];
    }
    __syncthreads();
    #pragma unroll
    for (int j = 0; j < 4; j++) {
        int r = ty + j * 8;
        T[(size_t)(n0 + r) * K + k0 + tx] = __float2half(t[tx][r]);
    }
}

// ====================================================================
// RMSNorm over D=1024 -> fp16 output
// ====================================================================
__global__ __launch_bounds__(256) void rmsnorm_h(const float* __restrict__ x,
                                                 const float* __restrict__ scale,
                                                 __half* __restrict__ y)
{
    const int row = blockIdx.x;
    const int t   = threadIdx.x;
    const float4 v = ((const float4*)(x + (size_t)row * DMODEL))[t];
    float ss = v.x*v.x + v.y*v.y + v.z*v.z + v.w*v.w;
    #pragma unroll
    for (int off = 16; off; off >>= 1) ss += __shfl_xor_sync(0xffffffffu, ss, off);
    __shared__ float red[8];
    if ((t & 31) == 0) red[t >> 5] = ss;
    __syncthreads();
    float tot = 0.f;
    #pragma unroll
    for (int w = 0; w < 8; w++) tot += red[w];
    const float r = rsqrtf(tot * (1.0f / DMODEL) + EPS);
    const float4 s4 = ((const float4*)scale)[t];
    const size_t base = (size_t)row * DMODEL + t * 4;
    *(uint32_t*)(y + base)     = packh2(v.x * r * s4.x, v.y * r * s4.y);
    *(uint32_t*)(y + base + 2) = packh2(v.z * r * s4.z, v.w * r * s4.w);
}

// ====================================================================
// 1-pass fp16 mma.sync GEMM: D[M,N] = A[M,K] @ Wt[N,K]^T + bias (+epi)
// CTA 128x256, BK=32, 8 warps (2x4), warp tile 64x64, 3-stage cp.async.
// epi: GELU/F16 -> fp16; RES -> fp32 + residual;
//      QLN/KLN -> fused per-head LayerNorm (warp's 64 cols = one head),
//                 fp16 out (QLN folds softmax scale 0.125).
// ====================================================================
#define EPI_GELU 1
#define EPI_RES  2
#define EPI_F16  3
#define EPI_QLN  4
#define EPI_KLN  5

#define BM 128
#define BN 256
#define GPITCH 40                       // halves per smem row (32 + 8 pad)
#define A_ARR  (BM * GPITCH)            // halves
#define B_ARR  (BN * GPITCH)            // halves
#define STG_H  (A_ARR + B_ARR)          // halves per stage
#define GSMEM  (3 * STG_H * 2)          // bytes, 3 stages = 92160

__global__ __launch_bounds__(256, 1) void mma_gemm(
    const __half* __restrict__ A,
    const __half* __restrict__ Bw,
    const float* __restrict__ bias, const float* __restrict__ res,
    const float* __restrict__ ln_s, const float* __restrict__ ln_b,
    float* __restrict__ outF, __half* __restrict__ outH,
    int M, int N, int K, int epi)
{
    extern __shared__ __half smh[];
    const uint32_t sb = smem_u32(smh);
    const int tid  = threadIdx.x;
    const int wid  = tid >> 5;
    const int lane = tid & 31;
    const int wm   = wid >> 2;           // 0..1 -> 64 rows each
    const int wn   = wid & 3;            // 0..3 -> 64 cols each
    const int bm   = blockIdx.y * BM;
    const int bn   = blockIdx.x * BN;

    auto load_chunk = [&](int c, int s) {
        const int k0 = c << 5;
        const uint32_t base = sb + (uint32_t)s * STG_H * 2;
        #pragma unroll
        for (int j = 0; j < 6; j++) {
            int idx = tid + j * 256;     // 0..1535 16B-chunks
            const __half* g;
            uint32_t dst;
            if (idx < 512) {             // A: 128 rows x 4 chunks
                int row = idx >> 2, ch = idx & 3;
                g   = A + (size_t)(bm + row) * K + k0 + ch * 8;
                dst = base + ((uint32_t)row * GPITCH + ch * 8) * 2;
            } else {                     // B: 256 rows x 4 chunks
                int a   = idx - 512;
                int row = a >> 2, ch = a & 3;
                g   = Bw + (size_t)(bn + row) * K + k0 + ch * 8;
                dst = base + (A_ARR + (uint32_t)row * GPITCH + ch * 8) * 2;
            }
            cp16(dst, g);
        }
        CP_COMMIT();
    };

    float acc[4][8][4];
    #pragma unroll
    for (int m = 0; m < 4; m++)
        #pragma unroll
        for (int n = 0; n < 8; n++)
            #pragma unroll
            for (int e = 0; e < 4; e++) acc[m][n][e] = 0.f;

    const int nch = K >> 5;
    load_chunk(0, 0);
    load_chunk(1, 1);
    load_chunk(2, 2);

    const int l16 = lane & 15;
    const int a_r = l16;
    const int a_c = (lane >> 4) * 8;
    const int b_r = l16 & 7;
    const int b_c = (l16 >> 3) * 8;

    int s = 0;
    for (int i = 0; i < nch; i++) {
        if (i + 3 <= nch - 1)      { CP_WAIT2(); }
        else if (i + 2 <= nch - 1) { CP_WAIT1(); }
        else                       { CP_WAIT0(); }
        __syncthreads();
        const uint32_t ab = sb + (uint32_t)s * STG_H * 2;
        const uint32_t bb = ab + A_ARR * 2;

        #pragma unroll
        for (int kk = 0; kk < 2; kk++) {
            const int kh = kk * 16;
            uint32_t ah[4][4];
            #pragma unroll
            for (int m = 0; m < 4; m++)
                ldmx4(ah[m], ab +
                    (uint32_t)((wm * 64 + m * 16 + a_r) * GPITCH + kh + a_c) * 2);
            #pragma unroll
            for (int half = 0; half < 2; half++) {
                uint32_t bh[4][2];
                #pragma unroll
                for (int n4 = 0; n4 < 4; n4++) {
                    int n = half * 4 + n4;
                    ldmx2(bh[n4], bb +
                        (uint32_t)((wn * 64 + n * 8 + b_r) * GPITCH + kh + b_c) * 2);
                }
                #pragma unroll
                for (int m = 0; m < 4; m++)
                    #pragma unroll
                    for (int n4 = 0; n4 < 4; n4++)
                        mma16816(acc[m][half * 4 + n4], ah[m], bh[n4]);
            }
        }
        __syncthreads();
        if (i + 3 < nch) load_chunk(i + 3, s);
        s = (s == 2) ? 0 : s + 1;
    }

    // -------- epilogue ----------
    const int g  = lane >> 2;
    const int t4 = lane & 3;

    if (epi == EPI_QLN || epi == EPI_KLN) {
        // fused per-head LayerNorm: warp's 64 cols = one head.
        const float mul = (epi == EPI_QLN) ? 0.125f : 1.0f;
        #pragma unroll
        for (int m = 0; m < 4; m++) {
            float v[8][4];
            float s0 = 0.f, q0 = 0.f, s1 = 0.f, q1 = 0.f;
            #pragma unroll
            for (int n = 0; n < 8; n++) {
                const int col = bn + wn * 64 + n * 8 + t4 * 2;
                const float b0 = __ldg(&bias[col]);
                const float b1 = __ldg(&bias[col + 1]);
                v[n][0] = acc[m][n][0] + b0; v[n][1] = acc[m][n][1] + b1;
                v[n][2] = acc[m][n][2] + b0; v[n][3] = acc[m][n][3] + b1;
                s0 += v[n][0] + v[n][1];  q0 += v[n][0]*v[n][0] + v[n][1]*v[n][1];
                s1 += v[n][2] + v[n][3];  q1 += v[n][2]*v[n][2] + v[n][3]*v[n][3];
            }
            #pragma unroll
            for (int off = 1; off < 4; off <<= 1) {
                s0 += __shfl_xor_sync(0xffffffffu, s0, off);
                q0 += __shfl_xor_sync(0xffffffffu, q0, off);
                s1 += __shfl_xor_sync(0xffffffffu, s1, off);
                q1 += __shfl_xor_sync(0xffffffffu, q1, off);
            }
            const float mu0 = s0 * (1.0f/64.0f), mu1 = s1 * (1.0f/64.0f);
            const float r0  = rsqrtf(q0 * (1.0f/64.0f) - mu0*mu0 + EPS);
            const float r1  = rsqrtf(q1 * (1.0f/64.0f) - mu1*mu1 + EPS);
            const int row0 = bm + wm * 64 + m * 16 + g;
            #pragma unroll
            for (int n = 0; n < 8; n++) {
                const int col = bn + wn * 64 + n * 8 + t4 * 2;
                const int hc  = col & 63;
                const float sA = __ldg(&ln_s[hc]),     bA = __ldg(&ln_b[hc]);
                const float sB = __ldg(&ln_s[hc + 1]), bB = __ldg(&ln_b[hc + 1]);
                float o0 = ((v[n][0] - mu0) * r0 * sA + bA) * mul;
                float o1 = ((v[n][1] - mu0) * r0 * sB + bB) * mul;
                float o2 = ((v[n][2] - mu1) * r1 * sA + bA) * mul;
                float o3 = ((v[n][3] - mu1) * r1 * sB + bB) * mul;
                *(uint32_t*)(outH + (size_t)row0 * N + col)       = packh2(o0, o1);
                *(uint32_t*)(outH + (size_t)(row0 + 8) * N + col) = packh2(o2, o3);
            }
        }
        return;
    }

    #pragma unroll
    for (int n = 0; n < 8; n++) {
        const int col = bn + wn * 64 + n * 8 + t4 * 2;
        const float b0 = __ldg(&bias[col]);
        const float b1 = __ldg(&bias[col + 1]);
        #pragma unroll
        for (int m = 0; m < 4; m++) {
            const int row0 = bm + wm * 64 + m * 16 + g;
            float v[4] = { acc[m][n][0] + b0, acc[m][n][1] + b1,
                           acc[m][n][2] + b0, acc[m][n][3] + b1 };
            if (epi == EPI_GELU) {
                #pragma unroll
                for (int e = 0; e < 4; e++) {
                    float u = v[e];
                    v[e] = 0.5f * u * (1.0f + erff(u * 0.70710678118654752f));
                }
                *(uint32_t*)(outH + (size_t)row0 * N + col)       = packh2(v[0], v[1]);
                *(uint32_t*)(outH + (size_t)(row0 + 8) * N + col) = packh2(v[2], v[3]);
            } else if (epi == EPI_F16) {
                *(uint32_t*)(outH + (size_t)row0 * N + col)       = packh2(v[0], v[1]);
                *(uint32_t*)(outH + (size_t)(row0 + 8) * N + col) = packh2(v[2], v[3]);
            } else {  // EPI_RES
                float2 r0 = *(const float2*)(res + (size_t)row0 * N + col);
                float2 r1 = *(const float2*)(res + (size_t)(row0 + 8) * N + col);
                v[0] += r0.x; v[1] += r0.y; v[2] += r1.x; v[3] += r1.y;
                *(float2*)(outF + (size_t)row0 * N + col)       = make_float2(v[0], v[1]);
                *(float2*)(outF + (size_t)(row0 + 8) * N + col) = make_float2(v[2], v[3]);
            }
        }
    }
}

// ====================================================================
// Tensorized flash attention (mma.sync fp16, fp32 softmax). fp16 out.
// ====================================================================
#define FP 72   // smem pitch in halves (64 + 8)

__global__ __launch_bounds__(128) void flash_mma(
    const __half* __restrict__ Qh,
    const __half* __restrict__ Kh,
    const __half* __restrict__ Vh,
    __half* __restrict__ O)
{
    __shared__ __half Qs[64 * FP];
    __shared__ __half KVs[2][2][64 * FP];   // [stage][K=0/V=1]

    const int tid  = threadIdx.x;
    const int wid  = tid >> 5;
    const int lane = tid & 31;
    const int q0   = blockIdx.x * 64;
    const size_t hoff = (size_t)blockIdx.y * HDIM;
    const size_t boff = (size_t)blockIdx.z * SEQ * DMODEL;
    const __half* Qg = Qh + boff + hoff;
    const __half* Kg = Kh + boff + hoff;
    const __half* Vg = Vh + boff + hoff;

    #pragma unroll
    for (int t = 0; t < 4; t++) {
        int idx = tid + t * 128;
        int row = idx >> 3, c8 = idx & 7;
        *(uint4*)&Qs[row * FP + c8 * 8] =
            *(const uint4*)(Qg + (size_t)(q0 + row) * DMODEL + c8 * 8);
    }
    __syncthreads();

    const uint32_t qsb = smem_u32(Qs);
    uint32_t qa[4][4];
    {
        const int ar = wid * 16 + (lane & 15);
        const int ac = (lane >> 4) * 8;
        #pragma unroll
        for (int c = 0; c < 4; c++)
            ldmx4(qa[c], qsb + (uint32_t)(ar * FP + c * 16 + ac) * 2);
    }

    float o[8][4];
    #pragma unroll
    for (int d = 0; d < 8; d++)
        #pragma unroll
        for (int e = 0; e < 4; e++) o[d][e] = 0.f;
    float m0 = -INFINITY, m1 = -INFINITY, l0 = 0.f, l1 = 0.f;

    auto load_kv = [&](int it, int s) {
        const int kb = it * 64;
        #pragma unroll
        for (int t = 0; t < 8; t++) {
            int idx   = tid + t * 128;
            int which = idx >> 9;
            int a     = idx & 511;
            int row   = a >> 3, c8 = a & 7;
            const __half* g =
                (which ? Vg : Kg) + (size_t)(kb + row) * DMODEL + c8 * 8;
            cp16(smem_u32(&KVs[s][which][row * FP + c8 * 8]), g);
        }
        CP_COMMIT();
    };

    load_kv(0, 0);

    const int krow = (lane & 7) + ((lane >> 4) << 3);
    const int kcol = ((lane >> 3) & 1) * 8;
    const int vrow = (lane & 7) + (((lane >> 3) & 1) << 3);
    const int vcol = (lane >> 4) << 3;

    for (int it = 0; it < SEQ / 64; it++) {
        const int s = it & 1;
        if (it + 1 < SEQ / 64) { load_kv(it + 1, s ^ 1); CP_WAIT1(); }
        else                   { CP_WAIT0(); }
        __syncthreads();

        float sc[8][4];
        #pragma unroll
        for (int j = 0; j < 8; j++)
            #pragma unroll
            for (int e = 0; e < 4; e++) sc[j][e] = 0.f;

        const uint32_t kbase = smem_u32(&KVs[s][0][0]);
        #pragma unroll
        for (int c = 0; c < 4; c++) {
            #pragma unroll
            for (int j2 = 0; j2 < 4; j2++) {
                uint32_t r[4];
                ldmx4(r, kbase + (uint32_t)((16 * j2 + krow) * FP + c * 16 + kcol) * 2);
                mma16816(sc[2 * j2],     qa[c], r);
                mma16816(sc[2 * j2 + 1], qa[c], r + 2);
            }
        }

        float rx0 = -INFINITY, rx1 = -INFINITY;
        #pragma unroll
        for (int j = 0; j < 8; j++) {
            rx0 = fmaxf(rx0, fmaxf(sc[j][0], sc[j][1]));
            rx1 = fmaxf(rx1, fmaxf(sc[j][2], sc[j][3]));
        }
        #pragma unroll
        for (int off = 1; off < 4; off <<= 1) {
            rx0 = fmaxf(rx0, __shfl_xor_sync(0xffffffffu, rx0, off));
            rx1 = fmaxf(rx1, __shfl_xor_sync(0xffffffffu, rx1, off));
        }
        const float mn0 = fmaxf(m0, rx0), mn1 = fmaxf(m1, rx1);
        const float al0 = expf(m0 - mn0), al1 = expf(m1 - mn1);
        float rs0 = 0.f, rs1 = 0.f;
        #pragma unroll
        for (int j = 0; j < 8; j++) {
            sc[j][0] = expf(sc[j][0] - mn0);
            sc[j][1] = expf(sc[j][1] - mn0);
            sc[j][2] = expf(sc[j][2] - mn1);
            sc[j][3] = expf(sc[j][3] - mn1);
            rs0 += sc[j][0] + sc[j][1];
            rs1 += sc[j][2] + sc[j][3];
        }
        #pragma unroll
        for (int off = 1; off < 4; off <<= 1) {
            rs0 += __shfl_xor_sync(0xffffffffu, rs0, off);
            rs1 += __shfl_xor_sync(0xffffffffu, rs1, off);
        }
        l0 = l0 * al0 + rs0; m0 = mn0;
        l1 = l1 * al1 + rs1; m1 = mn1;
        #pragma unroll
        for (int d = 0; d < 8; d++) {
            o[d][0] *= al0; o[d][1] *= al0;
            o[d][2] *= al1; o[d][3] *= al1;
        }

        uint32_t pa[4][4];
        #pragma unroll
        for (int kc = 0; kc < 4; kc++) {
            pa[kc][0] = packh2(sc[2 * kc][0],     sc[2 * kc][1]);
            pa[kc][1] = packh2(sc[2 * kc][2],     sc[2 * kc][3]);
            pa[kc][2] = packh2(sc[2 * kc + 1][0], sc[2 * kc + 1][1]);
            pa[kc][3] = packh2(sc[2 * kc + 1][2], sc[2 * kc + 1][3]);
        }

        const uint32_t vbase = smem_u32(&KVs[s][1][0]);
        #pragma unroll
        for (int kc = 0; kc < 4; kc++) {
            #pragma unroll
            for (int d2 = 0; d2 < 4; d2++) {
                uint32_t r[4];
                ldmx4t(r, vbase + (uint32_t)((kc * 16 + vrow) * FP + d2 * 16 + vcol) * 2);
                mma16816(o[2 * d2],     pa[kc], r);
                mma16816(o[2 * d2 + 1], pa[kc], r + 2);
            }
        }
        __syncthreads();
    }

    const float inv0 = 1.0f / l0, inv1 = 1.0f / l1;
    const int row0 = q0 + wid * 16 + (lane >> 2);
    const int coff = (lane & 3) * 2;
    __half* Ob = O + boff + hoff;
    #pragma unroll
    for (int d = 0; d < 8; d++) {
        *(uint32_t*)(Ob + (size_t)row0 * DMODEL + d * 8 + coff) =
            packh2(o[d][0] * inv0, o[d][1] * inv0);
        *(uint32_t*)(Ob + (size_t)(row0 + 8) * DMODEL + d * 8 + coff) =
            packh2(o[d][2] * inv1, o[d][3] * inv1);
    }
}

// ====================================================================
// kernel_launch
// ====================================================================
extern "C" void kernel_launch(void* const* d_in, const int* in_sizes, int n_in,
                              void* d_out, int out_size)
{
    const float* x        = (const float*)d_in[0];
    const float* Wq       = (const float*)d_in[1];
    const float* bq       = (const float*)d_in[2];
    const float* Wk       = (const float*)d_in[3];
    const float* bk       = (const float*)d_in[4];
    const float* Wv       = (const float*)d_in[5];
    const float* bv       = (const float*)d_in[6];
    const float* Wo       = (const float*)d_in[7];
    const float* bo       = (const float*)d_in[8];
    const float* qn_scale = (const float*)d_in[9];
    const float* qn_bias  = (const float*)d_in[10];
    const float* kn_scale = (const float*)d_in[11];
    const float* kn_bias  = (const float*)d_in[12];
    const float* W1       = (const float*)d_in[13];
    const float* b1       = (const float*)d_in[14];
    const float* W2       = (const float*)d_in[15];
    const float* b2       = (const float*)d_in[16];
    const float* n1_scale = (const float*)d_in[17];
    const float* n2_scale = (const float*)d_in[18];
    float* out = (float*)d_out;

    __half *h, *qh, *kh, *vh, *at, *h2, *f;
    __half *pWq, *pWk, *pWv, *pWo, *pW1, *pW2;
    float *x2;
    cudaGetSymbolAddress((void**)&h,   g_h);
    cudaGetSymbolAddress((void**)&qh,  g_qh);  cudaGetSymbolAddress((void**)&kh,  g_kh);
    cudaGetSymbolAddress((void**)&vh,  g_vh);
    cudaGetSymbolAddress((void**)&at,  g_at);
    cudaGetSymbolAddress((void**)&x2,  g_x2);
    cudaGetSymbolAddress((void**)&h2,  g_h2);
    cudaGetSymbolAddress((void**)&f,   g_f);
    cudaGetSymbolAddress((void**)&pWq, g_Wq);  cudaGetSymbolAddress((void**)&pWk, g_Wk);
    cudaGetSymbolAddress((void**)&pWv, g_Wv);  cudaGetSymbolAddress((void**)&pWo, g_Wo);
    cudaGetSymbolAddress((void**)&pW1, g_W1);  cudaGetSymbolAddress((void**)&pW2, g_W2);

    cudaFuncSetAttribute(mma_gemm, cudaFuncAttributeMaxDynamicSharedMemorySize, GSMEM);

    const dim3 tb(32, 8);
    const dim3 gD(DMODEL / BN, TOK / BM);     // 4 x 64
    const dim3 gF(FDIM   / BN, TOK / BM);     // 16 x 64

    // launches 6 and 7 are both mma_gemm so ncu (-s 5 -c 1) captures a GEMM
    wconv_t<<<dim3(DMODEL/32, DMODEL/32), tb>>>(Wq, pWq, DMODEL, DMODEL);   // 1
    wconv_t<<<dim3(DMODEL/32, DMODEL/32), tb>>>(Wk, pWk, DMODEL, DMODEL);   // 2
    wconv_t<<<dim3(DMODEL/32, DMODEL/32), tb>>>(Wv, pWv, DMODEL, DMODEL);   // 3
    rmsnorm_h<<<TOK, 256>>>(x, n1_scale, h);                                // 4
    wconv_t<<<dim3(DMODEL/32, DMODEL/32), tb>>>(Wo, pWo, DMODEL, DMODEL);   // 5
    // q = LN(h@Wq + bq) * 0.125  (fused head-LN epilogue)
    mma_gemm<<<gD, 256, GSMEM>>>(h, pWq, bq, nullptr, qn_scale, qn_bias,    // 6
                                 nullptr, qh, TOK, DMODEL, DMODEL, EPI_QLN);
    // k = LN(h@Wk + bk)
    mma_gemm<<<gD, 256, GSMEM>>>(h, pWk, bk, nullptr, kn_scale, kn_bias,    // 7
                                 nullptr, kh, TOK, DMODEL, DMODEL, EPI_KLN);
    wconv_t<<<dim3(FDIM/32,   DMODEL/32), tb>>>(W1, pW1, DMODEL, FDIM);     // 8
    wconv_t<<<dim3(DMODEL/32, FDIM/32),   tb>>>(W2, pW2, FDIM,   DMODEL);   // 9
    // v = h@Wv + bv  (fp16 out)
    mma_gemm<<<gD, 256, GSMEM>>>(h, pWv, bv, nullptr, nullptr, nullptr,
                                 nullptr, vh, TOK, DMODEL, DMODEL, EPI_F16);

    flash_mma<<<dim3(SEQ / 64, NHEAD, BATCH), 128>>>(qh, kh, vh, at);

    // x2 = x + attn @ Wo + bo
    mma_gemm<<<gD, 256, GSMEM>>>(at, pWo, bo, x, nullptr, nullptr,
                                 x2, nullptr, TOK, DMODEL, DMODEL, EPI_RES);

    rmsnorm_h<<<TOK, 256>>>(x2, n2_scale, h2);

    // ffn = gelu(h2 @ W1 + b1)  (fp16 out)
    mma_gemm<<<gF, 256, GSMEM>>>(h2, pW1, b1, nullptr, nullptr, nullptr,
                                 nullptr, f, TOK, FDIM, DMODEL, EPI_GELU);

    // out = x2 + ffn @ W2 + b2
    mma_gemm<<<gD, 256, GSMEM>>>(f, pW2, b2, x2, nullptr, nullptr,
                                 out, nullptr, TOK, DMODEL, FDIM, EPI_RES);
}